// round 9
// baseline (speedup 1.0000x reference)
#include <cuda_runtime.h>
#include <cstdint>
#include <math.h>

#define T_SEQ 2048
#define NH 16
#define HD 64
#define CEMB 1024
#define KVW 512

// ---------------- scratch (device globals) ----------------------------------
static __device__ float g_qraw[T_SEQ * CEMB];
static __device__ float g_kraw[T_SEQ * CEMB];
static __device__ float g_vraw[T_SEQ * CEMB];
static __device__ float g_qn[NH * T_SEQ * HD];
static __device__ float g_kvp[NH * T_SEQ * KVW];        // paired layout [h][g][c][w']
static __device__ uint32_t g_qbh[NH * T_SEQ * 32];      // q bf16-hi packed (permuted words)
static __device__ uint32_t g_qbl[NH * T_SEQ * 32];
static __device__ uint32_t g_kbh[NH * T_SEQ * 32];
static __device__ uint32_t g_kbl[NH * T_SEQ * 32];
static __device__ float g_y[T_SEQ * CEMB];

// ---------------- helpers ----------------------------------------------------
static __device__ __forceinline__ uint32_t smem_u32(const void* p) {
    uint32_t a;
    asm("{ .reg .u64 t; cvta.to.shared.u64 t, %1; cvt.u32.u64 %0, t; }" : "=r"(a) : "l"(p));
    return a;
}
static __device__ __forceinline__ float tf32r(float x) {
    float y; asm("cvt.rna.tf32.f32 %0, %1;" : "=f"(y) : "f"(x)); return y;
}
static __device__ __forceinline__ void mma_tf32(
    float* acc, uint32_t a0, uint32_t a1, uint32_t a2, uint32_t a3,
    uint32_t b0, uint32_t b1)
{
    asm volatile(
        "mma.sync.aligned.m16n8k8.row.col.f32.tf32.tf32.f32 "
        "{%0,%1,%2,%3},{%4,%5,%6,%7},{%8,%9},{%0,%1,%2,%3};"
        : "+f"(acc[0]), "+f"(acc[1]), "+f"(acc[2]), "+f"(acc[3])
        : "r"(a0), "r"(a1), "r"(a2), "r"(a3), "r"(b0), "r"(b1));
}
static __device__ __forceinline__ void mma_bf16(
    float* acc, uint32_t a0, uint32_t a1, uint32_t a2, uint32_t a3,
    uint32_t b0, uint32_t b1)
{
    asm volatile(
        "mma.sync.aligned.m16n8k16.row.col.f32.bf16.bf16.f32 "
        "{%0,%1,%2,%3},{%4,%5,%6,%7},{%8,%9},{%0,%1,%2,%3};"
        : "+f"(acc[0]), "+f"(acc[1]), "+f"(acc[2]), "+f"(acc[3])
        : "r"(a0), "r"(a1), "r"(a2), "r"(a3), "r"(b0), "r"(b1));
}
static __device__ __forceinline__ uint2 pack_split(float f0, float f1) {
    uint32_t h;
    asm("cvt.rn.bf16x2.f32 %0, %1, %2;" : "=r"(h) : "f"(f1), "f"(f0));
    float h0 = __uint_as_float(h << 16);
    float h1 = __uint_as_float(h & 0xffff0000u);
    uint32_t l;
    float r0 = f0 - h0, r1 = f1 - h1;
    asm("cvt.rn.bf16x2.f32 %0, %1, %2;" : "=r"(l) : "f"(r1), "f"(r0));
    return make_uint2(h, l);
}
#define CP16(dst_u32, src_ptr) \
    asm volatile("cp.async.cg.shared.global [%0], [%1], 16;" \
                 :: "r"(dst_u32), "l"(src_ptr) : "memory")
#define CP_COMMIT() asm volatile("cp.async.commit_group;" ::: "memory")

static __device__ __forceinline__ int permw(int d) {
    return (d & ~7) + ((d & 3) * 2 + ((d & 7) >> 2));
}

// ================= bf16 3x-split GEMM (NT), 128x64 tiles =====================
#define BSTR 12
#define GA_HI 0
#define GB_HI (128 * BSTR)
#define GA_LO (GB_HI + 64 * BSTR)
#define GB_LO (GA_LO + 128 * BSTR)
#define GSTAGE (GB_LO + 64 * BSTR)      // 3840 words per stage

static __device__ __forceinline__ void bf16_nt_body(
    const float* __restrict__ A, const float* __restrict__ B, float* __restrict__ C,
    int K, int lda, int ldb, int ldc, int m0, int n0)
{
    extern __shared__ uint32_t smu[];
    int nch = K >> 4;

    int tid = threadIdx.x;
    int lane = tid & 31, wid = tid >> 5;
    int gid = lane >> 2, tig = lane & 3;
    int warp_m = wid & 3, warp_n = wid >> 2;
    int arow = tid >> 1, akc = (tid & 1) * 8;
    int brow = tid >> 2, bkc = (tid & 3) * 4;

    float acc[2][4][4];
#pragma unroll
    for (int i = 0; i < 2; i++)
#pragma unroll
        for (int j = 0; j < 4; j++)
#pragma unroll
            for (int q = 0; q < 4; q++) acc[i][j][q] = 0.f;

    float4 ra0, ra1, rb0;
    auto LOADG = [&](int k0) {
        const float* ap = A + (long)(m0 + arow) * lda + k0 + akc;
        ra0 = *(const float4*)ap;
        ra1 = *(const float4*)(ap + 4);
        rb0 = *(const float4*)(B + (long)(n0 + brow) * ldb + k0 + bkc);
    };
    auto STORES = [&](int sb) {
        int ao = arow * BSTR + (akc >> 1);
        uint2 p0 = pack_split(ra0.x, ra0.y), p1 = pack_split(ra0.z, ra0.w);
        uint2 p2 = pack_split(ra1.x, ra1.y), p3 = pack_split(ra1.z, ra1.w);
        *(uint4*)(smu + sb + GA_HI + ao) = make_uint4(p0.x, p1.x, p2.x, p3.x);
        *(uint4*)(smu + sb + GA_LO + ao) = make_uint4(p0.y, p1.y, p2.y, p3.y);
        uint2 q0 = pack_split(rb0.x, rb0.y), q1 = pack_split(rb0.z, rb0.w);
        int bo = brow * BSTR + (bkc >> 1);
        *(uint2*)(smu + sb + GB_HI + bo) = make_uint2(q0.x, q1.x);
        *(uint2*)(smu + sb + GB_LO + bo) = make_uint2(q0.y, q1.y);
    };

    LOADG(0);
    STORES(0);
    __syncthreads();

    for (int ch = 0; ch < nch; ch++) {
        if (ch + 1 < nch) LOADG((ch + 1) << 4);
        int sb = (ch & 1) * GSTAGE;
#pragma unroll
        for (int p = 0; p < 3; p++) {
            const uint32_t* Abase = smu + sb + (p == 2 ? GA_LO : GA_HI);
            const uint32_t* Bbase = smu + sb + (p == 1 ? GB_LO : GB_HI);
            uint32_t af[2][4];
#pragma unroll
            for (int mt = 0; mt < 2; mt++) {
                int r = (warp_m * 32 + mt * 16 + gid) * BSTR + tig;
                af[mt][0] = Abase[r];
                af[mt][1] = Abase[r + 8 * BSTR];
                af[mt][2] = Abase[r + 4];
                af[mt][3] = Abase[r + 8 * BSTR + 4];
            }
            uint32_t bfr[4][2];
#pragma unroll
            for (int nt = 0; nt < 4; nt++) {
                int c = (warp_n * 32 + nt * 8 + gid) * BSTR + tig;
                bfr[nt][0] = Bbase[c];
                bfr[nt][1] = Bbase[c + 4];
            }
#pragma unroll
            for (int mt = 0; mt < 2; mt++)
#pragma unroll
                for (int nt = 0; nt < 4; nt++)
                    mma_bf16(acc[mt][nt], af[mt][0], af[mt][1], af[mt][2],
                             af[mt][3], bfr[nt][0], bfr[nt][1]);
        }
        if (ch + 1 < nch) {
            __syncthreads();
            STORES(((ch + 1) & 1) * GSTAGE);
            __syncthreads();
        }
    }

#pragma unroll
    for (int mt = 0; mt < 2; mt++) {
        int r0 = m0 + warp_m * 32 + mt * 16 + gid;
#pragma unroll
        for (int nt = 0; nt < 4; nt++) {
            int c = n0 + warp_n * 32 + nt * 8 + tig * 2;
            *(float2*)(C + (long)r0 * ldc + c) =
                make_float2(acc[mt][nt][0], acc[mt][nt][1]);
            *(float2*)(C + (long)(r0 + 8) * ldc + c) =
                make_float2(acc[mt][nt][2], acc[mt][nt][3]);
        }
    }
}

__global__ void __launch_bounds__(256, 2) qkv_gemm(
    const float* __restrict__ x,
    const float* __restrict__ Wq, const float* __restrict__ Wk,
    const float* __restrict__ Wv,
    float* q, float* k, float* v)
{
    const float* B = blockIdx.z == 0 ? Wq : blockIdx.z == 1 ? Wk : Wv;
    float* C = blockIdx.z == 0 ? q : blockIdx.z == 1 ? k : v;
    bf16_nt_body(x, B, C, CEMB, CEMB, CEMB, CEMB,
                 blockIdx.y * 128, blockIdx.x * 64);
}

__global__ void __launch_bounds__(256, 2) wo_gemm(
    const float* __restrict__ y, const float* __restrict__ Wo, float* out)
{
    bf16_nt_body(y, Wo, out, CEMB, CEMB, CEMB, CEMB,
                 blockIdx.y * 128, blockIdx.x * 64);
}

// ---------------- prep (unchanged) --------------------------------------------
__global__ __launch_bounds__(512) void prep_kernel(
    const float* __restrict__ qraw, const float* __restrict__ kraw,
    const float* __restrict__ vraw,
    const float* __restrict__ cosp, const float* __restrict__ sinp,
    float* __restrict__ qn, float* __restrict__ kvp,
    uint32_t* __restrict__ qbh, uint32_t* __restrict__ qbl,
    uint32_t* __restrict__ kbh, uint32_t* __restrict__ kbl)
{
    int h = blockIdx.x, g = blockIdx.y;
    int tid = threadIdx.x;
    int w = tid >> 6, d = tid & 63;
    int t = g * 8 + w;

    __shared__ float r1[8][64], r2[8][64], skc[8][64], sv[8][64];
    __shared__ float sq[8][64], sk[8][64];
    __shared__ float kvstage[8][512];

    long base = (long)t * CEMB + h * HD;
    int j = d & 31;
    float c = cosp[t * 32 + j], s = sinp[t * 32 + j];

    float x1q = qraw[base + j], x2q = qraw[base + j + 32];
    float qv = (d < 32) ? (x1q * c + x2q * s) : (x2q * c - x1q * s);
    float x1k = kraw[base + j], x2k = kraw[base + j + 32];
    float kvv = (d < 32) ? (x1k * c + x2k * s) : (x2k * c - x1k * s);

    r1[w][d] = qv * qv;
    r2[w][d] = kvv * kvv;
    __syncthreads();
#pragma unroll
    for (int off = 32; off > 0; off >>= 1) {
        if (d < off) { r1[w][d] += r1[w][d + off]; r2[w][d] += r2[w][d + off]; }
        __syncthreads();
    }
    float rq = rsqrtf(r1[w][0] * (1.f / 64.f) + 1e-6f);
    float rk = rsqrtf(r2[w][0] * (1.f / 64.f) + 1e-6f);
    float qno = qv * rq, kno = kvv * rk;

    qn[((long)h * T_SEQ + t) * HD + d] = qno;
    sq[w][d] = qno;
    sk[w][d] = kno;

    float o = kno * kno;
    o += __shfl_xor_sync(0xffffffffu, o, 1);
    o += __shfl_xor_sync(0xffffffffu, o, 2);
    o += __shfl_xor_sync(0xffffffffu, o, 4);
    float ko = kno / fmaxf(sqrtf(o), 1e-12f);
    skc[w][d] = ((d & 7) == 0) ? ko : -ko;
    sv[w][d] = vraw[base + d];
    __syncthreads();

    {
        float kc = skc[w][d];
        int mb = d & ~7;
#pragma unroll
        for (int i = 0; i < 8; i++)
            kvstage[w][d * 8 + i] = tf32r(kc * sv[w][mb + i]);
    }
    {
        long pbase = ((long)h * T_SEQ + t) * 32;
        if (d < 32) {
            uint2 p = pack_split(sq[w][2 * d], sq[w][2 * d + 1]);
            qbh[pbase + permw(d)] = p.x;
            qbl[pbase + permw(d)] = p.y;
        } else {
            int d2 = d - 32;
            uint2 p = pack_split(sk[w][2 * d2], sk[w][2 * d2 + 1]);
            kbh[pbase + permw(d2)] = p.x;
            kbl[pbase + permw(d2)] = p.y;
        }
    }
    __syncthreads();

    float* outb = kvp + ((long)(h * 256 + g) * 512) * 8;
#pragma unroll
    for (int it = 0; it < 2; it++) {
        int idx = tid + it * 512;
        int cc = idx >> 1, half = idx & 1;
        float4 v;
        v.x = kvstage[((half * 4 + 0) >> 1) + ((half * 4 + 0) & 1) * 4][cc];
        v.y = kvstage[((half * 4 + 1) >> 1) + ((half * 4 + 1) & 1) * 4][cc];
        v.z = kvstage[((half * 4 + 2) >> 1) + ((half * 4 + 2) & 1) * 4][cc];
        v.w = kvstage[((half * 4 + 3) >> 1) + ((half * 4 + 3) & 1) * 4][cc];
        *(float4*)(outb + cc * 8 + half * 4) = v;
    }
}

// ---------------- octonion math ----------------------------------------------
__device__ __forceinline__ void qmul4(const float* q1, const float* q2, float* r)
{
    r[0] = q1[0]*q2[0] - q1[1]*q2[1] - q1[2]*q2[2] - q1[3]*q2[3];
    r[1] = q1[0]*q2[1] + q1[1]*q2[0] + q1[2]*q2[3] - q1[3]*q2[2];
    r[2] = q1[0]*q2[2] - q1[1]*q2[3] + q1[2]*q2[0] + q1[3]*q2[1];
    r[3] = q1[0]*q2[3] + q1[1]*q2[2] - q1[2]*q2[1] + q1[3]*q2[0];
}
__device__ __forceinline__ void omul8(const float* o1, const float* o2, float* r)
{
    const float* a = o1; const float* b = o1 + 4;
    const float* c = o2; const float* d = o2 + 4;
    float dc[4] = { d[0], -d[1], -d[2], -d[3] };
    float cc[4] = { c[0], -c[1], -c[2], -c[3] };
    float t1[4], t2[4];
    qmul4(a, c, t1); qmul4(dc, b, t2);
    r[0] = t1[0] - t2[0]; r[1] = t1[1] - t2[1];
    r[2] = t1[2] - t2[2]; r[3] = t1[3] - t2[3];
    qmul4(d, a, t1); qmul4(b, cc, t2);
    r[4] = t1[0] + t2[0]; r[5] = t1[1] + t2[1];
    r[6] = t1[2] + t2[2]; r[7] = t1[3] + t2[3];
}

// ===== fused attention: split KV cols across 2 CTAs, 2 CTAs/SM ===============
#define TK 32
// word offsets in dynamic smem
#define OFF_KV 0
#define KV_STG 8192             // 4 kgroups * 256c * 8
#define OFF_KH 16384            // 2 stages x 32x40
#define KH_STG 1280
#define OFF_KL 18944
#define OFF_P  21504            // 64 x 40
#define OFF_S  24064            // 2x64 + 64
#define FA_SMEM ((OFF_S + 192) * 4)   // 97024 B -> 2 CTAs/SM
// Q staging overlays KV stage 1 during the prologue (Q lives in regs after)
#define OFF_QH_OVL (OFF_KV + KV_STG)
#define OFF_QL_OVL (OFF_QH_OVL + 2560)

__global__ void __launch_bounds__(256, 2) fused_attn(
    const float* __restrict__ qn,
    const uint32_t* __restrict__ qbh, const uint32_t* __restrict__ qbl,
    const uint32_t* __restrict__ kbh, const uint32_t* __restrict__ kbl,
    const float* __restrict__ kvp, float* __restrict__ y)
{
    extern __shared__ __align__(16) float fsm[];
    uint32_t* usm = (uint32_t*)fsm;
    uint32_t sbase = smem_u32(fsm);

    int qt = 31 - blockIdx.x;
    int h = blockIdx.y;
    int half = blockIdx.z;              // which 256 KV columns
    int c0 = half * 256;
    int r0 = qt * 64;
    int njt = 2 * qt + 2;

    int tid = threadIdx.x, lane = tid & 31, wid = tid >> 5;
    int gid = lane >> 2, tig = lane & 3;
    int wms = wid & 3, wns = wid >> 2;   // scores: rows wms*16, keys wns*16

    const float*    kvph = kvp + (long)h * T_SEQ * KVW + (long)c0 * 8;
    const uint32_t* khh = kbh + (long)h * T_SEQ * 32;
    const uint32_t* khl = kbl + (long)h * T_SEQ * 32;

    auto issue_tile = [&](int jt, int s) {
        const float* srcb = kvph + (long)jt * 16384;
#pragma unroll
        for (int i = 0; i < 8; i++) {
            int idx = tid + i * 256;            // 0..2047 16B chunks
            int gg = idx >> 9, ci = idx & 511;
            CP16(sbase + (OFF_KV + s * KV_STG + gg * 2048 + ci * 4) * 4,
                 srcb + (long)gg * 4096 + ci * 4);
        }
#pragma unroll
        for (int i = 0; i < 2; i++) {
            int idx = tid + i * 256;
            int arr = idx >> 8, rr = (idx >> 3) & 31, ch = (idx & 7) * 4;
            const uint32_t* sb2 = (arr ? khl : khh) + (long)(jt * TK + rr) * 32 + ch;
            CP16(sbase + ((arr ? OFF_KL : OFF_KH) + s * KH_STG + rr * 40 + ch) * 4, sb2);
        }
    };

    // prologue: Q into KV-stage-1 overlay, then tile 0 into stage 0
    {
        const uint32_t* qhh = qbh + ((long)h * T_SEQ + r0) * 32;
        const uint32_t* qhl = qbl + ((long)h * T_SEQ + r0) * 32;
#pragma unroll
        for (int i = 0; i < 4; i++) {
            int idx = tid + i * 256;
            int arr = idx >> 9, rr = (idx >> 3) & 63, ch = (idx & 7) * 4;
            const uint32_t* src = (arr ? qhl : qhh) + (long)rr * 32 + ch;
            CP16(sbase + ((arr ? OFF_QL_OVL : OFF_QH_OVL) + rr * 40 + ch) * 4, src);
        }
        CP_COMMIT();
        issue_tile(0, 0);
        CP_COMMIT();
        asm volatile("cp.async.wait_group 1;" ::: "memory");   // Q arrived
        __syncthreads();
    }

    int rowa = wms * 16 + gid;
    // preload Q frags into registers, then free the overlay
    uint32_t qh[4][4], ql[4][4];
#pragma unroll
    for (int ks = 0; ks < 4; ks++) {
        int b = rowa * 40 + ks * 8 + 2 * tig;
        uint2 a = *(const uint2*)(usm + OFF_QH_OVL + b);
        uint2 bb = *(const uint2*)(usm + OFF_QH_OVL + b + 8 * 40);
        qh[ks][0] = a.x; qh[ks][1] = bb.x; qh[ks][2] = a.y; qh[ks][3] = bb.y;
        uint2 c = *(const uint2*)(usm + OFF_QL_OVL + b);
        uint2 d = *(const uint2*)(usm + OFF_QL_OVL + b + 8 * 40);
        ql[ks][0] = c.x; ql[ks][1] = d.x; ql[ks][2] = c.y; ql[ks][3] = d.y;
    }
    __syncthreads();    // all Q reads done before tile 1 overwrites the overlay

    float zacc[4][4][4];
#pragma unroll
    for (int i = 0; i < 4; i++)
#pragma unroll
        for (int j = 0; j < 4; j++)
#pragma unroll
            for (int q = 0; q < 4; q++) zacc[i][j][q] = 0.f;
    float s_acc0 = 0.f, s_acc1 = 0.f;

    int phys0 = ((2 * tig) & 3) * 2 + (tig >> 1);
    int phys1 = ((2 * tig + 1) & 3) * 2 + (tig >> 1);

    for (int jt = 0; jt < njt; jt++) {
        int s = jt & 1;
        if (jt + 1 < njt) {
            issue_tile(jt + 1, s ^ 1);
            CP_COMMIT();
            asm volatile("cp.async.wait_group 1;" ::: "memory");
        } else {
            asm volatile("cp.async.wait_group 0;" ::: "memory");
        }
        __syncthreads();

        // ---- scores: warp tile 16 rows x 16 keys (duplicated across halves) --
#pragma unroll
        for (int nt = 0; nt < 2; nt++) {
            float sc3[3][4];
#pragma unroll
            for (int p = 0; p < 3; p++)
#pragma unroll
                for (int q = 0; q < 4; q++) sc3[p][q] = 0.f;
            int krow = (wns * 16 + nt * 8 + gid) * 40 + 2 * tig;
#pragma unroll
            for (int ks = 0; ks < 4; ks++) {
#pragma unroll
                for (int p = 0; p < 3; p++) {
                    const uint32_t* Aq = (p == 2) ? ql[ks] : qh[ks];
                    const uint32_t* Bb = usm + (p == 1 ? OFF_KL : OFF_KH) +
                                         s * KH_STG;
                    uint2 kb = *(const uint2*)(Bb + krow + ks * 8);
                    mma_bf16(sc3[p], Aq[0], Aq[1], Aq[2], Aq[3], kb.x, kb.y);
                }
            }
            float s0 = sc3[0][0] + sc3[1][0] + sc3[2][0];
            float s1 = sc3[0][1] + sc3[1][1] + sc3[2][1];
            float s2 = sc3[0][2] + sc3[1][2] + sc3[2][2];
            float s3 = sc3[0][3] + sc3[1][3] + sc3[2][3];

            int colg = jt * TK + wns * 16 + nt * 8 + tig * 2;
            float p00 = __expf(s0 * 0.125f);
            float p01 = __expf(s1 * 0.125f);
            float p10 = __expf(s2 * 0.125f);
            float p11 = __expf(s3 * 0.125f);
            if (jt >= njt - 2) {
                if (colg     > r0 + rowa)     p00 = 0.f;
                if (colg + 1 > r0 + rowa)     p01 = 0.f;
                if (colg     > r0 + rowa + 8) p10 = 0.f;
                if (colg + 1 > r0 + rowa + 8) p11 = 0.f;
            }
            p00 = tf32r(p00); p01 = tf32r(p01);
            p10 = tf32r(p10); p11 = tf32r(p11);
            float* Pr = fsm + OFF_P + rowa * 40 + wns * 16 + nt * 8;
            Pr[phys0] = p00; Pr[phys1] = p01;
            Pr[8 * 40 + phys0] = p10; Pr[8 * 40 + phys1] = p11;
            s_acc0 += p00 + p01;
            s_acc1 += p10 + p11;
        }
        __syncthreads();

        // ---- Z += P @ KV : warp tile 64 rows x 32 cols (KV read once) ----
        {
            const float* KVs = fsm + OFF_KV + s * KV_STG;
#pragma unroll
            for (int ks = 0; ks < 4; ks++) {
                uint2 pa[4][2];
#pragma unroll
                for (int mt = 0; mt < 4; mt++) {
                    const float* Pr = fsm + OFF_P +
                        (mt * 16 + gid) * 40 + ks * 8 + 2 * tig;
                    pa[mt][0] = *(const uint2*)Pr;
                    pa[mt][1] = *(const uint2*)(Pr + 8 * 40);
                }
#pragma unroll
                for (int nt = 0; nt < 4; nt++) {
                    int cl = wid * 32 + nt * 8 + gid;
                    uint2 bb = *(const uint2*)(KVs + ks * 2048 + cl * 8 + 2 * tig);
#pragma unroll
                    for (int mt = 0; mt < 4; mt++)
                        mma_tf32(zacc[mt][nt], pa[mt][0].x, pa[mt][1].x,
                                 pa[mt][0].y, pa[mt][1].y, bb.x, bb.y);
                }
            }
        }
        __syncthreads();
    }

    // ---- S reduce ----
    s_acc0 += __shfl_xor_sync(~0u, s_acc0, 1);
    s_acc0 += __shfl_xor_sync(~0u, s_acc0, 2);
    s_acc1 += __shfl_xor_sync(~0u, s_acc1, 1);
    s_acc1 += __shfl_xor_sync(~0u, s_acc1, 2);
    if (tig == 0) {
        fsm[OFF_S + wns * 64 + rowa] = s_acc0;
        fsm[OFF_S + wns * 64 + rowa + 8] = s_acc1;
    }
    // ---- Z regs -> smem (overlay on dead KV/KH stages), stride 260 ----
#pragma unroll
    for (int mt = 0; mt < 4; mt++) {
        int row = mt * 16 + gid;
#pragma unroll
        for (int nt = 0; nt < 4; nt++) {
            int cl = wid * 32 + nt * 8 + tig * 2;
            float* zp = fsm + row * 260 + cl + (wid >> 1);
            zp[0] = zacc[mt][nt][0];
            zp[1] = zacc[mt][nt][1];
            zp[8 * 260] = zacc[mt][nt][2];
            zp[8 * 260 + 1] = zacc[mt][nt][3];
        }
    }
    __syncthreads();
    if (tid < 64)
        fsm[OFF_S + 128 + tid] = 1.f / (fsm[OFF_S + tid] + fsm[OFF_S + 64 + tid]);
    __syncthreads();

    // ---- octonion epilogue: 1 (row, m) unit per thread ----
    {
        int row = tid >> 2, m_loc = tid & 3;
        int m = half * 4 + m_loc;
        float invS = fsm[OFF_S + 128 + row];
        const float* q = qn + ((long)h * T_SEQ + r0 + row) * HD + m * 8;
        const float* z = fsm + row * 260 + m_loc * 65;

        float q8[8];
        float4 qa = *(const float4*)q, qb = *(const float4*)(q + 4);
        q8[0]=qa.x; q8[1]=qa.y; q8[2]=qa.z; q8[3]=qa.w;
        q8[4]=qb.x; q8[5]=qb.y; q8[6]=qb.z; q8[7]=qb.w;
        float acc[8] = {0,0,0,0,0,0,0,0};
#pragma unroll
        for (int p = 0; p < 8; p++) {
            float e[8] = {0,0,0,0,0,0,0,0};
            e[p] = 1.f;
            float uo[8], z8[8], wv[8];
            omul8(q8, e, uo);
#pragma unroll
            for (int i = 0; i < 8; i++) z8[i] = z[p * 8 + i];
            omul8(uo, z8, wv);
#pragma unroll
            for (int k = 0; k < 8; k++) acc[k] += wv[k];
        }
        float* yo = y + (long)(r0 + row) * CEMB + h * HD + m * 8;
        *(float4*)yo = make_float4(acc[0]*invS, acc[1]*invS, acc[2]*invS, acc[3]*invS);
        *(float4*)(yo + 4) = make_float4(acc[4]*invS, acc[5]*invS, acc[6]*invS, acc[7]*invS);
    }
}

// ---------------- launch -----------------------------------------------------
extern "C" void kernel_launch(void* const* d_in, const int* in_sizes, int n_in,
                              void* d_out, int out_size)
{
    const float* x    = (const float*)d_in[0];
    const float* cosp = (const float*)d_in[1];
    const float* sinp = (const float*)d_in[2];
    const float* Wq   = (const float*)d_in[3];
    const float* Wk   = (const float*)d_in[4];
    const float* Wv   = (const float*)d_in[5];
    const float* Wo   = (const float*)d_in[6];
    float* out = (float*)d_out;

    float *qraw, *kraw, *vraw, *qn, *kvp, *y;
    uint32_t *qbh, *qbl, *kbh, *kbl;
    cudaGetSymbolAddress((void**)&qraw, g_qraw);
    cudaGetSymbolAddress((void**)&kraw, g_kraw);
    cudaGetSymbolAddress((void**)&vraw, g_vraw);
    cudaGetSymbolAddress((void**)&qn,   g_qn);
    cudaGetSymbolAddress((void**)&kvp,  g_kvp);
    cudaGetSymbolAddress((void**)&qbh,  g_qbh);
    cudaGetSymbolAddress((void**)&qbl,  g_qbl);
    cudaGetSymbolAddress((void**)&kbh,  g_kbh);
    cudaGetSymbolAddress((void**)&kbl,  g_kbl);
    cudaGetSymbolAddress((void**)&y,    g_y);

    const int smem_gemm = 2 * GSTAGE * 4;   // 30720 B
    cudaFuncSetAttribute(qkv_gemm, cudaFuncAttributeMaxDynamicSharedMemorySize, smem_gemm);
    cudaFuncSetAttribute(wo_gemm,  cudaFuncAttributeMaxDynamicSharedMemorySize, smem_gemm);
    cudaFuncSetAttribute(fused_attn, cudaFuncAttributeMaxDynamicSharedMemorySize, FA_SMEM);

    // 1) merged QKV projections (3xBF16 split, NT, 128x64 tiles)
    qkv_gemm<<<dim3(CEMB / 64, T_SEQ / 128, 3), 256, smem_gemm>>>(
        x, Wq, Wk, Wv, qraw, kraw, vraw);

    // 2) rotary + rms + octet-norm + paired tf32 KV + permuted bf16 packing
    prep_kernel<<<dim3(NH, T_SEQ / 8), 512>>>(qraw, kraw, vraw, cosp, sinp,
                                              qn, kvp, qbh, qbl, kbh, kbl);

    // 3) fused attention, KV columns split across 2 CTAs -> 2 CTAs/SM
    fused_attn<<<dim3(32, NH, 2), 256, FA_SMEM>>>(qn, qbh, qbl, kbh, kbl, kvp, y);

    // 4) out = y @ Wo^T (3xBF16 split, 128x64 tiles)
    wo_gemm<<<dim3(CEMB / 64, T_SEQ / 128), 256, smem_gemm>>>(y, Wo, out);
}

// round 10
// speedup vs baseline: 1.0150x; 1.0150x over previous
#include <cuda_runtime.h>
#include <cstdint>
#include <math.h>

#define T_SEQ 2048
#define NH 16
#define HD 64
#define CEMB 1024
#define KVW 512

// ---------------- scratch (device globals) ----------------------------------
static __device__ float g_qraw[T_SEQ * CEMB];
static __device__ float g_kraw[T_SEQ * CEMB];
static __device__ float g_vraw[T_SEQ * CEMB];
static __device__ float g_qn[NH * T_SEQ * HD];
static __device__ float g_kvp[NH * T_SEQ * KVW];        // paired layout [h][g][c][w']
static __device__ uint32_t g_qbh[NH * T_SEQ * 32];      // q bf16-hi packed (permuted words)
static __device__ uint32_t g_qbl[NH * T_SEQ * 32];
static __device__ uint32_t g_kbh[NH * T_SEQ * 32];
static __device__ uint32_t g_kbl[NH * T_SEQ * 32];
static __device__ float g_y[T_SEQ * CEMB];

// ---------------- helpers ----------------------------------------------------
static __device__ __forceinline__ uint32_t smem_u32(const void* p) {
    uint32_t a;
    asm("{ .reg .u64 t; cvta.to.shared.u64 t, %1; cvt.u32.u64 %0, t; }" : "=r"(a) : "l"(p));
    return a;
}
static __device__ __forceinline__ float tf32r(float x) {
    float y; asm("cvt.rna.tf32.f32 %0, %1;" : "=f"(y) : "f"(x)); return y;
}
static __device__ __forceinline__ void mma_tf32(
    float* acc, uint32_t a0, uint32_t a1, uint32_t a2, uint32_t a3,
    uint32_t b0, uint32_t b1)
{
    asm volatile(
        "mma.sync.aligned.m16n8k8.row.col.f32.tf32.tf32.f32 "
        "{%0,%1,%2,%3},{%4,%5,%6,%7},{%8,%9},{%0,%1,%2,%3};"
        : "+f"(acc[0]), "+f"(acc[1]), "+f"(acc[2]), "+f"(acc[3])
        : "r"(a0), "r"(a1), "r"(a2), "r"(a3), "r"(b0), "r"(b1));
}
static __device__ __forceinline__ void mma_bf16(
    float* acc, uint32_t a0, uint32_t a1, uint32_t a2, uint32_t a3,
    uint32_t b0, uint32_t b1)
{
    asm volatile(
        "mma.sync.aligned.m16n8k16.row.col.f32.bf16.bf16.f32 "
        "{%0,%1,%2,%3},{%4,%5,%6,%7},{%8,%9},{%0,%1,%2,%3};"
        : "+f"(acc[0]), "+f"(acc[1]), "+f"(acc[2]), "+f"(acc[3])
        : "r"(a0), "r"(a1), "r"(a2), "r"(a3), "r"(b0), "r"(b1));
}
static __device__ __forceinline__ uint2 pack_split(float f0, float f1) {
    uint32_t h;
    asm("cvt.rn.bf16x2.f32 %0, %1, %2;" : "=r"(h) : "f"(f1), "f"(f0));
    float h0 = __uint_as_float(h << 16);
    float h1 = __uint_as_float(h & 0xffff0000u);
    uint32_t l;
    float r0 = f0 - h0, r1 = f1 - h1;
    asm("cvt.rn.bf16x2.f32 %0, %1, %2;" : "=r"(l) : "f"(r1), "f"(r0));
    return make_uint2(h, l);
}
#define CP16(dst_u32, src_ptr) \
    asm volatile("cp.async.cg.shared.global [%0], [%1], 16;" \
                 :: "r"(dst_u32), "l"(src_ptr) : "memory")
#define CP_COMMIT() asm volatile("cp.async.commit_group;" ::: "memory")

static __device__ __forceinline__ int permw(int d) {
    return (d & ~7) + ((d & 3) * 2 + ((d & 7) >> 2));
}

// ================= bf16 3x-split GEMM (NT), 128x64 tiles =====================
#define BSTR 12
#define GA_HI 0
#define GB_HI (128 * BSTR)
#define GA_LO (GB_HI + 64 * BSTR)
#define GB_LO (GA_LO + 128 * BSTR)
#define GSTAGE (GB_LO + 64 * BSTR)      // 3840 words per stage

static __device__ __forceinline__ void bf16_nt_body(
    const float* __restrict__ A, const float* __restrict__ B, float* __restrict__ C,
    int K, int lda, int ldb, int ldc, int m0, int n0)
{
    extern __shared__ uint32_t smu[];
    int nch = K >> 4;

    int tid = threadIdx.x;
    int lane = tid & 31, wid = tid >> 5;
    int gid = lane >> 2, tig = lane & 3;
    int warp_m = wid & 3, warp_n = wid >> 2;
    int arow = tid >> 1, akc = (tid & 1) * 8;
    int brow = tid >> 2, bkc = (tid & 3) * 4;

    float acc[2][4][4];
#pragma unroll
    for (int i = 0; i < 2; i++)
#pragma unroll
        for (int j = 0; j < 4; j++)
#pragma unroll
            for (int q = 0; q < 4; q++) acc[i][j][q] = 0.f;

    float4 ra0, ra1, rb0;
    auto LOADG = [&](int k0) {
        const float* ap = A + (long)(m0 + arow) * lda + k0 + akc;
        ra0 = *(const float4*)ap;
        ra1 = *(const float4*)(ap + 4);
        rb0 = *(const float4*)(B + (long)(n0 + brow) * ldb + k0 + bkc);
    };
    auto STORES = [&](int sb) {
        int ao = arow * BSTR + (akc >> 1);
        uint2 p0 = pack_split(ra0.x, ra0.y), p1 = pack_split(ra0.z, ra0.w);
        uint2 p2 = pack_split(ra1.x, ra1.y), p3 = pack_split(ra1.z, ra1.w);
        *(uint4*)(smu + sb + GA_HI + ao) = make_uint4(p0.x, p1.x, p2.x, p3.x);
        *(uint4*)(smu + sb + GA_LO + ao) = make_uint4(p0.y, p1.y, p2.y, p3.y);
        uint2 q0 = pack_split(rb0.x, rb0.y), q1 = pack_split(rb0.z, rb0.w);
        int bo = brow * BSTR + (bkc >> 1);
        *(uint2*)(smu + sb + GB_HI + bo) = make_uint2(q0.x, q1.x);
        *(uint2*)(smu + sb + GB_LO + bo) = make_uint2(q0.y, q1.y);
    };

    LOADG(0);
    STORES(0);
    __syncthreads();

    for (int ch = 0; ch < nch; ch++) {
        if (ch + 1 < nch) LOADG((ch + 1) << 4);
        int sb = (ch & 1) * GSTAGE;
#pragma unroll
        for (int p = 0; p < 3; p++) {
            const uint32_t* Abase = smu + sb + (p == 2 ? GA_LO : GA_HI);
            const uint32_t* Bbase = smu + sb + (p == 1 ? GB_LO : GB_HI);
            uint32_t af[2][4];
#pragma unroll
            for (int mt = 0; mt < 2; mt++) {
                int r = (warp_m * 32 + mt * 16 + gid) * BSTR + tig;
                af[mt][0] = Abase[r];
                af[mt][1] = Abase[r + 8 * BSTR];
                af[mt][2] = Abase[r + 4];
                af[mt][3] = Abase[r + 8 * BSTR + 4];
            }
            uint32_t bfr[4][2];
#pragma unroll
            for (int nt = 0; nt < 4; nt++) {
                int c = (warp_n * 32 + nt * 8 + gid) * BSTR + tig;
                bfr[nt][0] = Bbase[c];
                bfr[nt][1] = Bbase[c + 4];
            }
#pragma unroll
            for (int mt = 0; mt < 2; mt++)
#pragma unroll
                for (int nt = 0; nt < 4; nt++)
                    mma_bf16(acc[mt][nt], af[mt][0], af[mt][1], af[mt][2],
                             af[mt][3], bfr[nt][0], bfr[nt][1]);
        }
        if (ch + 1 < nch) {
            __syncthreads();
            STORES(((ch + 1) & 1) * GSTAGE);
            __syncthreads();
        }
    }

#pragma unroll
    for (int mt = 0; mt < 2; mt++) {
        int r0 = m0 + warp_m * 32 + mt * 16 + gid;
#pragma unroll
        for (int nt = 0; nt < 4; nt++) {
            int c = n0 + warp_n * 32 + nt * 8 + tig * 2;
            *(float2*)(C + (long)r0 * ldc + c) =
                make_float2(acc[mt][nt][0], acc[mt][nt][1]);
            *(float2*)(C + (long)(r0 + 8) * ldc + c) =
                make_float2(acc[mt][nt][2], acc[mt][nt][3]);
        }
    }
}

__global__ void __launch_bounds__(256, 2) qkv_gemm(
    const float* __restrict__ x,
    const float* __restrict__ Wq, const float* __restrict__ Wk,
    const float* __restrict__ Wv,
    float* q, float* k, float* v)
{
    const float* B = blockIdx.z == 0 ? Wq : blockIdx.z == 1 ? Wk : Wv;
    float* C = blockIdx.z == 0 ? q : blockIdx.z == 1 ? k : v;
    bf16_nt_body(x, B, C, CEMB, CEMB, CEMB, CEMB,
                 blockIdx.y * 128, blockIdx.x * 64);
}

__global__ void __launch_bounds__(256, 2) wo_gemm(
    const float* __restrict__ y, const float* __restrict__ Wo, float* out)
{
    bf16_nt_body(y, Wo, out, CEMB, CEMB, CEMB, CEMB,
                 blockIdx.y * 128, blockIdx.x * 64);
}

// ---------------- prep (unchanged) --------------------------------------------
__global__ __launch_bounds__(512) void prep_kernel(
    const float* __restrict__ qraw, const float* __restrict__ kraw,
    const float* __restrict__ vraw,
    const float* __restrict__ cosp, const float* __restrict__ sinp,
    float* __restrict__ qn, float* __restrict__ kvp,
    uint32_t* __restrict__ qbh, uint32_t* __restrict__ qbl,
    uint32_t* __restrict__ kbh, uint32_t* __restrict__ kbl)
{
    int h = blockIdx.x, g = blockIdx.y;
    int tid = threadIdx.x;
    int w = tid >> 6, d = tid & 63;
    int t = g * 8 + w;

    __shared__ float r1[8][64], r2[8][64], skc[8][64], sv[8][64];
    __shared__ float sq[8][64], sk[8][64];
    __shared__ float kvstage[8][512];

    long base = (long)t * CEMB + h * HD;
    int j = d & 31;
    float c = cosp[t * 32 + j], s = sinp[t * 32 + j];

    float x1q = qraw[base + j], x2q = qraw[base + j + 32];
    float qv = (d < 32) ? (x1q * c + x2q * s) : (x2q * c - x1q * s);
    float x1k = kraw[base + j], x2k = kraw[base + j + 32];
    float kvv = (d < 32) ? (x1k * c + x2k * s) : (x2k * c - x1k * s);

    r1[w][d] = qv * qv;
    r2[w][d] = kvv * kvv;
    __syncthreads();
#pragma unroll
    for (int off = 32; off > 0; off >>= 1) {
        if (d < off) { r1[w][d] += r1[w][d + off]; r2[w][d] += r2[w][d + off]; }
        __syncthreads();
    }
    float rq = rsqrtf(r1[w][0] * (1.f / 64.f) + 1e-6f);
    float rk = rsqrtf(r2[w][0] * (1.f / 64.f) + 1e-6f);
    float qno = qv * rq, kno = kvv * rk;

    qn[((long)h * T_SEQ + t) * HD + d] = qno;
    sq[w][d] = qno;
    sk[w][d] = kno;

    float o = kno * kno;
    o += __shfl_xor_sync(0xffffffffu, o, 1);
    o += __shfl_xor_sync(0xffffffffu, o, 2);
    o += __shfl_xor_sync(0xffffffffu, o, 4);
    float ko = kno / fmaxf(sqrtf(o), 1e-12f);
    skc[w][d] = ((d & 7) == 0) ? ko : -ko;
    sv[w][d] = vraw[base + d];
    __syncthreads();

    {
        float kc = skc[w][d];
        int mb = d & ~7;
#pragma unroll
        for (int i = 0; i < 8; i++)
            kvstage[w][d * 8 + i] = tf32r(kc * sv[w][mb + i]);
    }
    {
        long pbase = ((long)h * T_SEQ + t) * 32;
        if (d < 32) {
            uint2 p = pack_split(sq[w][2 * d], sq[w][2 * d + 1]);
            qbh[pbase + permw(d)] = p.x;
            qbl[pbase + permw(d)] = p.y;
        } else {
            int d2 = d - 32;
            uint2 p = pack_split(sk[w][2 * d2], sk[w][2 * d2 + 1]);
            kbh[pbase + permw(d2)] = p.x;
            kbl[pbase + permw(d2)] = p.y;
        }
    }
    __syncthreads();

    float* outb = kvp + ((long)(h * 256 + g) * 512) * 8;
#pragma unroll
    for (int it = 0; it < 2; it++) {
        int idx = tid + it * 512;
        int cc = idx >> 1, half = idx & 1;
        float4 v;
        v.x = kvstage[((half * 4 + 0) >> 1) + ((half * 4 + 0) & 1) * 4][cc];
        v.y = kvstage[((half * 4 + 1) >> 1) + ((half * 4 + 1) & 1) * 4][cc];
        v.z = kvstage[((half * 4 + 2) >> 1) + ((half * 4 + 2) & 1) * 4][cc];
        v.w = kvstage[((half * 4 + 3) >> 1) + ((half * 4 + 3) & 1) * 4][cc];
        *(float4*)(outb + cc * 8 + half * 4) = v;
    }
}

// ---------------- octonion math ----------------------------------------------
__device__ __forceinline__ void qmul4(const float* q1, const float* q2, float* r)
{
    r[0] = q1[0]*q2[0] - q1[1]*q2[1] - q1[2]*q2[2] - q1[3]*q2[3];
    r[1] = q1[0]*q2[1] + q1[1]*q2[0] + q1[2]*q2[3] - q1[3]*q2[2];
    r[2] = q1[0]*q2[2] - q1[1]*q2[3] + q1[2]*q2[0] + q1[3]*q2[1];
    r[3] = q1[0]*q2[3] + q1[1]*q2[2] - q1[2]*q2[1] + q1[3]*q2[0];
}
__device__ __forceinline__ void omul8(const float* o1, const float* o2, float* r)
{
    const float* a = o1; const float* b = o1 + 4;
    const float* c = o2; const float* d = o2 + 4;
    float dc[4] = { d[0], -d[1], -d[2], -d[3] };
    float cc[4] = { c[0], -c[1], -c[2], -c[3] };
    float t1[4], t2[4];
    qmul4(a, c, t1); qmul4(dc, b, t2);
    r[0] = t1[0] - t2[0]; r[1] = t1[1] - t2[1];
    r[2] = t1[2] - t2[2]; r[3] = t1[3] - t2[3];
    qmul4(d, a, t1); qmul4(b, cc, t2);
    r[4] = t1[0] + t2[0]; r[5] = t1[1] + t2[1];
    r[6] = t1[2] + t2[2]; r[7] = t1[3] + t2[3];
}

// ===== fused attention: 512 thr (4 warps/SMSP), full KV width, KV read once ==
#define TK 32
// word offsets in dynamic smem (R8 layout)
#define OFF_KV 0
#define KV_STG 16384            // 4 kgroups * 512c * 8
#define OFF_KH 32768            // 2 stages x 32x40
#define KH_STG 1280
#define OFF_KL 35328
#define OFF_P  37888            // 64 x 40
#define OFF_QH 40448            // 64 x 40
#define OFF_QL 43008
#define OFF_S  45568            // 4x64 + 64
#define FA_SMEM ((OFF_S + 320) * 4)

__global__ void __launch_bounds__(512, 1) fused_attn(
    const float* __restrict__ qn,
    const uint32_t* __restrict__ qbh, const uint32_t* __restrict__ qbl,
    const uint32_t* __restrict__ kbh, const uint32_t* __restrict__ kbl,
    const float* __restrict__ kvp, float* __restrict__ y)
{
    extern __shared__ __align__(16) float fsm[];
    uint32_t* usm = (uint32_t*)fsm;
    uint32_t sbase = smem_u32(fsm);

    int qt = 31 - blockIdx.x;
    int h = blockIdx.y;
    int r0 = qt * 64;
    int njt = 2 * qt + 2;

    int tid = threadIdx.x, lane = tid & 31, wid = tid >> 5;
    int gid = lane >> 2, tig = lane & 3;
    int wms = wid & 3, wns = wid >> 2;   // scores: rows wms*16, key group wns*8

    const float*    kvph = kvp + (long)h * T_SEQ * KVW;
    const uint32_t* khh = kbh + (long)h * T_SEQ * 32;
    const uint32_t* khl = kbl + (long)h * T_SEQ * 32;

    auto issue_tile = [&](int jt, int s) {
        const float* src = kvph + (long)jt * 16384;
        uint32_t dstw = OFF_KV + s * KV_STG;
#pragma unroll
        for (int i = 0; i < 8; i++) {
            int idx = tid + i * 512;
            CP16(sbase + (dstw + idx * 4) * 4, src + idx * 4);
        }
        {
            int arr = tid >> 8, rr = (tid >> 3) & 31, ch = (tid & 7) * 4;
            const uint32_t* sb2 = (arr ? khl : khh) + (long)(jt * TK + rr) * 32 + ch;
            CP16(sbase + ((arr ? OFF_KL : OFF_KH) + s * KH_STG + rr * 40 + ch) * 4, sb2);
        }
    };

    // prologue: Q tiles then tile 0
    {
        const uint32_t* qhh = qbh + ((long)h * T_SEQ + r0) * 32;
        const uint32_t* qhl = qbl + ((long)h * T_SEQ + r0) * 32;
#pragma unroll
        for (int i = 0; i < 2; i++) {
            int idx = tid + i * 512;
            int arr = idx >> 9, rr = (idx >> 3) & 63, ch = (idx & 7) * 4;
            const uint32_t* src = (arr ? qhl : qhh) + (long)rr * 32 + ch;
            CP16(sbase + ((arr ? OFF_QL : OFF_QH) + rr * 40 + ch) * 4, src);
        }
        issue_tile(0, 0);
        CP_COMMIT();
    }

    float zacc[4][4][4];
#pragma unroll
    for (int i = 0; i < 4; i++)
#pragma unroll
        for (int j = 0; j < 4; j++)
#pragma unroll
            for (int q = 0; q < 4; q++) zacc[i][j][q] = 0.f;
    float s_acc0 = 0.f, s_acc1 = 0.f;

    int rowa = wms * 16 + gid;
    int phys0 = ((2 * tig) & 3) * 2 + (tig >> 1);
    int phys1 = ((2 * tig + 1) & 3) * 2 + (tig >> 1);

    for (int jt = 0; jt < njt; jt++) {
        int s = jt & 1;
        if (jt + 1 < njt) {
            issue_tile(jt + 1, s ^ 1);
            CP_COMMIT();
            asm volatile("cp.async.wait_group 1;" ::: "memory");
        } else {
            asm volatile("cp.async.wait_group 0;" ::: "memory");
        }
        __syncthreads();

        // ---- scores: warp tile 16 rows x 8 keys (3 split chains) ----
        {
            float sc3[3][4];
#pragma unroll
            for (int p = 0; p < 3; p++)
#pragma unroll
                for (int q = 0; q < 4; q++) sc3[p][q] = 0.f;
            int krow = (wns * 8 + gid) * 40 + 2 * tig;
            int arow2 = rowa * 40 + 2 * tig;
#pragma unroll
            for (int ks = 0; ks < 4; ks++) {
#pragma unroll
                for (int p = 0; p < 3; p++) {
                    const uint32_t* Ab = usm + (p == 2 ? OFF_QL : OFF_QH);
                    const uint32_t* Bb = usm + (p == 1 ? OFF_KL : OFF_KH) +
                                         s * KH_STG;
                    uint2 qa = *(const uint2*)(Ab + arow2 + ks * 8);
                    uint2 qb = *(const uint2*)(Ab + arow2 + ks * 8 + 8 * 40);
                    uint2 kb = *(const uint2*)(Bb + krow + ks * 8);
                    mma_bf16(sc3[p], qa.x, qb.x, qa.y, qb.y, kb.x, kb.y);
                }
            }
            float s0 = sc3[0][0] + sc3[1][0] + sc3[2][0];
            float s1 = sc3[0][1] + sc3[1][1] + sc3[2][1];
            float s2 = sc3[0][2] + sc3[1][2] + sc3[2][2];
            float s3 = sc3[0][3] + sc3[1][3] + sc3[2][3];

            int colg = jt * TK + wns * 8 + tig * 2;
            float p00 = __expf(s0 * 0.125f);
            float p01 = __expf(s1 * 0.125f);
            float p10 = __expf(s2 * 0.125f);
            float p11 = __expf(s3 * 0.125f);
            if (jt >= njt - 2) {
                if (colg     > r0 + rowa)     p00 = 0.f;
                if (colg + 1 > r0 + rowa)     p01 = 0.f;
                if (colg     > r0 + rowa + 8) p10 = 0.f;
                if (colg + 1 > r0 + rowa + 8) p11 = 0.f;
            }
            p00 = tf32r(p00); p01 = tf32r(p01);
            p10 = tf32r(p10); p11 = tf32r(p11);
            float* Pr = fsm + OFF_P + rowa * 40 + wns * 8;
            Pr[phys0] = p00; Pr[phys1] = p01;
            Pr[8 * 40 + phys0] = p10; Pr[8 * 40 + phys1] = p11;
            s_acc0 += p00 + p01;
            s_acc1 += p10 + p11;
        }
        __syncthreads();

        // ---- Z += P @ KV : warp tile 64 rows x 32 cols (KV read once) ----
        {
            const float* KVs = fsm + OFF_KV + s * KV_STG;
#pragma unroll
            for (int ks = 0; ks < 4; ks++) {
                uint2 pa[4][2];
#pragma unroll
                for (int mt = 0; mt < 4; mt++) {
                    const float* Pr = fsm + OFF_P +
                        (mt * 16 + gid) * 40 + ks * 8 + 2 * tig;
                    pa[mt][0] = *(const uint2*)Pr;
                    pa[mt][1] = *(const uint2*)(Pr + 8 * 40);
                }
#pragma unroll
                for (int nt = 0; nt < 4; nt++) {
                    int c = wid * 32 + nt * 8 + gid;
                    uint2 bb = *(const uint2*)(KVs + (ks * 512 + c) * 8 + 2 * tig);
#pragma unroll
                    for (int mt = 0; mt < 4; mt++)
                        mma_tf32(zacc[mt][nt], pa[mt][0].x, pa[mt][1].x,
                                 pa[mt][0].y, pa[mt][1].y, bb.x, bb.y);
                }
            }
        }
        __syncthreads();
    }

    // ---- S reduce: quad shuffle then 4 partials ----
    s_acc0 += __shfl_xor_sync(~0u, s_acc0, 1);
    s_acc0 += __shfl_xor_sync(~0u, s_acc0, 2);
    s_acc1 += __shfl_xor_sync(~0u, s_acc1, 1);
    s_acc1 += __shfl_xor_sync(~0u, s_acc1, 2);
    if (tig == 0) {
        fsm[OFF_S + wns * 64 + rowa] = s_acc0;
        fsm[OFF_S + wns * 64 + rowa + 8] = s_acc1;
    }
    // ---- Z regs -> smem (overlay on dead KV/KH stages), stride 520 ----
#pragma unroll
    for (int mt = 0; mt < 4; mt++) {
        int row = mt * 16 + gid;
#pragma unroll
        for (int nt = 0; nt < 4; nt++) {
            float* zp = fsm + row * 520 + wid * 32 + (wid >> 1) + nt * 8 + tig * 2;
            zp[0] = zacc[mt][nt][0];
            zp[1] = zacc[mt][nt][1];
            zp[8 * 520] = zacc[mt][nt][2];
            zp[8 * 520 + 1] = zacc[mt][nt][3];
        }
    }
    __syncthreads();
    if (tid < 64)
        fsm[OFF_S + 256 + tid] = 1.f / (fsm[OFF_S + tid] + fsm[OFF_S + 64 + tid] +
                                        fsm[OFF_S + 128 + tid] + fsm[OFF_S + 192 + tid]);
    __syncthreads();

    // ---- octonion epilogue: one (row, m) unit per thread ----
    {
        int row = tid >> 3, m = tid & 7;
        float invS = fsm[OFF_S + 256 + row];
        const float* q = qn + ((long)h * T_SEQ + r0 + row) * HD + m * 8;
        const float* z = fsm + row * 520 + m * 65;

        float q8[8];
        float4 qa = *(const float4*)q, qb = *(const float4*)(q + 4);
        q8[0]=qa.x; q8[1]=qa.y; q8[2]=qa.z; q8[3]=qa.w;
        q8[4]=qb.x; q8[5]=qb.y; q8[6]=qb.z; q8[7]=qb.w;
        float acc[8] = {0,0,0,0,0,0,0,0};
#pragma unroll
        for (int p = 0; p < 8; p++) {
            float e[8] = {0,0,0,0,0,0,0,0};
            e[p] = 1.f;
            float uo[8], z8[8], wv[8];
            omul8(q8, e, uo);
#pragma unroll
            for (int i = 0; i < 8; i++) z8[i] = z[p * 8 + i];
            omul8(uo, z8, wv);
#pragma unroll
            for (int k = 0; k < 8; k++) acc[k] += wv[k];
        }
        float* yo = y + (long)(r0 + row) * CEMB + h * HD + m * 8;
        *(float4*)yo = make_float4(acc[0]*invS, acc[1]*invS, acc[2]*invS, acc[3]*invS);
        *(float4*)(yo + 4) = make_float4(acc[4]*invS, acc[5]*invS, acc[6]*invS, acc[7]*invS);
    }
}

// ---------------- launch -----------------------------------------------------
extern "C" void kernel_launch(void* const* d_in, const int* in_sizes, int n_in,
                              void* d_out, int out_size)
{
    const float* x    = (const float*)d_in[0];
    const float* cosp = (const float*)d_in[1];
    const float* sinp = (const float*)d_in[2];
    const float* Wq   = (const float*)d_in[3];
    const float* Wk   = (const float*)d_in[4];
    const float* Wv   = (const float*)d_in[5];
    const float* Wo   = (const float*)d_in[6];
    float* out = (float*)d_out;

    float *qraw, *kraw, *vraw, *qn, *kvp, *y;
    uint32_t *qbh, *qbl, *kbh, *kbl;
    cudaGetSymbolAddress((void**)&qraw, g_qraw);
    cudaGetSymbolAddress((void**)&kraw, g_kraw);
    cudaGetSymbolAddress((void**)&vraw, g_vraw);
    cudaGetSymbolAddress((void**)&qn,   g_qn);
    cudaGetSymbolAddress((void**)&kvp,  g_kvp);
    cudaGetSymbolAddress((void**)&qbh,  g_qbh);
    cudaGetSymbolAddress((void**)&qbl,  g_qbl);
    cudaGetSymbolAddress((void**)&kbh,  g_kbh);
    cudaGetSymbolAddress((void**)&kbl,  g_kbl);
    cudaGetSymbolAddress((void**)&y,    g_y);

    const int smem_gemm = 2 * GSTAGE * 4;   // 30720 B
    cudaFuncSetAttribute(qkv_gemm, cudaFuncAttributeMaxDynamicSharedMemorySize, smem_gemm);
    cudaFuncSetAttribute(wo_gemm,  cudaFuncAttributeMaxDynamicSharedMemorySize, smem_gemm);
    cudaFuncSetAttribute(fused_attn, cudaFuncAttributeMaxDynamicSharedMemorySize, FA_SMEM);

    // 1) merged QKV projections (3xBF16 split, NT, 128x64 tiles)
    qkv_gemm<<<dim3(CEMB / 64, T_SEQ / 128, 3), 256, smem_gemm>>>(
        x, Wq, Wk, Wv, qraw, kraw, vraw);

    // 2) rotary + rms + octet-norm + paired tf32 KV + permuted bf16 packing
    prep_kernel<<<dim3(NH, T_SEQ / 8), 512>>>(qraw, kraw, vraw, cosp, sinp,
                                              qn, kvp, qbh, qbl, kbh, kbl);

    // 3) fused attention: 512 threads, full KV width, KV read once
    fused_attn<<<dim3(32, NH), 512, FA_SMEM>>>(qn, qbh, qbl, kbh, kbl, kvp, y);

    // 4) out = y @ Wo^T (3xBF16 split, 128x64 tiles)
    wo_gemm<<<dim3(CEMB / 64, T_SEQ / 128), 256, smem_gemm>>>(y, Wo, out);
}

// round 11
// speedup vs baseline: 1.0784x; 1.0625x over previous
#include <cuda_runtime.h>
#include <cstdint>
#include <math.h>

#define T_SEQ 2048
#define NH 16
#define HD 64
#define CEMB 1024
#define KVW 512

// ---------------- scratch (device globals) ----------------------------------
static __device__ float g_qraw[T_SEQ * CEMB];
static __device__ float g_kraw[T_SEQ * CEMB];
static __device__ float g_vraw[T_SEQ * CEMB];
static __device__ float g_qn[NH * T_SEQ * HD];
static __device__ float g_kvp[NH * T_SEQ * KVW];        // paired layout [h][g][c][w']
static __device__ uint32_t g_qbh[NH * T_SEQ * 32];      // q bf16-hi packed (permuted words)
static __device__ uint32_t g_qbl[NH * T_SEQ * 32];
static __device__ uint32_t g_kbh[NH * T_SEQ * 32];
static __device__ uint32_t g_kbl[NH * T_SEQ * 32];
static __device__ float g_y[T_SEQ * CEMB];

// ---------------- helpers ----------------------------------------------------
static __device__ __forceinline__ uint32_t smem_u32(const void* p) {
    uint32_t a;
    asm("{ .reg .u64 t; cvta.to.shared.u64 t, %1; cvt.u32.u64 %0, t; }" : "=r"(a) : "l"(p));
    return a;
}
static __device__ __forceinline__ float tf32r(float x) {
    float y; asm("cvt.rna.tf32.f32 %0, %1;" : "=f"(y) : "f"(x)); return y;
}
static __device__ __forceinline__ void mma_tf32(
    float* acc, uint32_t a0, uint32_t a1, uint32_t a2, uint32_t a3,
    uint32_t b0, uint32_t b1)
{
    asm volatile(
        "mma.sync.aligned.m16n8k8.row.col.f32.tf32.tf32.f32 "
        "{%0,%1,%2,%3},{%4,%5,%6,%7},{%8,%9},{%0,%1,%2,%3};"
        : "+f"(acc[0]), "+f"(acc[1]), "+f"(acc[2]), "+f"(acc[3])
        : "r"(a0), "r"(a1), "r"(a2), "r"(a3), "r"(b0), "r"(b1));
}
static __device__ __forceinline__ void mma_bf16(
    float* acc, uint32_t a0, uint32_t a1, uint32_t a2, uint32_t a3,
    uint32_t b0, uint32_t b1)
{
    asm volatile(
        "mma.sync.aligned.m16n8k16.row.col.f32.bf16.bf16.f32 "
        "{%0,%1,%2,%3},{%4,%5,%6,%7},{%8,%9},{%0,%1,%2,%3};"
        : "+f"(acc[0]), "+f"(acc[1]), "+f"(acc[2]), "+f"(acc[3])
        : "r"(a0), "r"(a1), "r"(a2), "r"(a3), "r"(b0), "r"(b1));
}
static __device__ __forceinline__ uint2 pack_split(float f0, float f1) {
    uint32_t h;
    asm("cvt.rn.bf16x2.f32 %0, %1, %2;" : "=r"(h) : "f"(f1), "f"(f0));
    float h0 = __uint_as_float(h << 16);
    float h1 = __uint_as_float(h & 0xffff0000u);
    uint32_t l;
    float r0 = f0 - h0, r1 = f1 - h1;
    asm("cvt.rn.bf16x2.f32 %0, %1, %2;" : "=r"(l) : "f"(r1), "f"(r0));
    return make_uint2(h, l);
}
#define CP16(dst_u32, src_ptr) \
    asm volatile("cp.async.cg.shared.global [%0], [%1], 16;" \
                 :: "r"(dst_u32), "l"(src_ptr) : "memory")
#define CP_COMMIT() asm volatile("cp.async.commit_group;" ::: "memory")

static __device__ __forceinline__ int permw(int d) {
    return (d & ~7) + ((d & 3) * 2 + ((d & 7) >> 2));
}

// ================= bf16 3x-split GEMM (NT), 128x64 tiles =====================
#define BSTR 12
#define GA_HI 0
#define GB_HI (128 * BSTR)
#define GA_LO (GB_HI + 64 * BSTR)
#define GB_LO (GA_LO + 128 * BSTR)
#define GSTAGE (GB_LO + 64 * BSTR)      // 3840 words per stage

static __device__ __forceinline__ void bf16_nt_body(
    const float* __restrict__ A, const float* __restrict__ B, float* __restrict__ C,
    int K, int lda, int ldb, int ldc, int m0, int n0)
{
    extern __shared__ uint32_t smu[];
    int nch = K >> 4;

    int tid = threadIdx.x;
    int lane = tid & 31, wid = tid >> 5;
    int gid = lane >> 2, tig = lane & 3;
    int warp_m = wid & 3, warp_n = wid >> 2;
    int arow = tid >> 1, akc = (tid & 1) * 8;
    int brow = tid >> 2, bkc = (tid & 3) * 4;

    float acc[2][4][4];
#pragma unroll
    for (int i = 0; i < 2; i++)
#pragma unroll
        for (int j = 0; j < 4; j++)
#pragma unroll
            for (int q = 0; q < 4; q++) acc[i][j][q] = 0.f;

    float4 ra0, ra1, rb0;
    auto LOADG = [&](int k0) {
        const float* ap = A + (long)(m0 + arow) * lda + k0 + akc;
        ra0 = *(const float4*)ap;
        ra1 = *(const float4*)(ap + 4);
        rb0 = *(const float4*)(B + (long)(n0 + brow) * ldb + k0 + bkc);
    };
    auto STORES = [&](int sb) {
        int ao = arow * BSTR + (akc >> 1);
        uint2 p0 = pack_split(ra0.x, ra0.y), p1 = pack_split(ra0.z, ra0.w);
        uint2 p2 = pack_split(ra1.x, ra1.y), p3 = pack_split(ra1.z, ra1.w);
        *(uint4*)(smu + sb + GA_HI + ao) = make_uint4(p0.x, p1.x, p2.x, p3.x);
        *(uint4*)(smu + sb + GA_LO + ao) = make_uint4(p0.y, p1.y, p2.y, p3.y);
        uint2 q0 = pack_split(rb0.x, rb0.y), q1 = pack_split(rb0.z, rb0.w);
        int bo = brow * BSTR + (bkc >> 1);
        *(uint2*)(smu + sb + GB_HI + bo) = make_uint2(q0.x, q1.x);
        *(uint2*)(smu + sb + GB_LO + bo) = make_uint2(q0.y, q1.y);
    };

    LOADG(0);
    STORES(0);
    __syncthreads();

    for (int ch = 0; ch < nch; ch++) {
        if (ch + 1 < nch) LOADG((ch + 1) << 4);
        int sb = (ch & 1) * GSTAGE;
#pragma unroll
        for (int p = 0; p < 3; p++) {
            const uint32_t* Abase = smu + sb + (p == 2 ? GA_LO : GA_HI);
            const uint32_t* Bbase = smu + sb + (p == 1 ? GB_LO : GB_HI);
            uint32_t af[2][4];
#pragma unroll
            for (int mt = 0; mt < 2; mt++) {
                int r = (warp_m * 32 + mt * 16 + gid) * BSTR + tig;
                af[mt][0] = Abase[r];
                af[mt][1] = Abase[r + 8 * BSTR];
                af[mt][2] = Abase[r + 4];
                af[mt][3] = Abase[r + 8 * BSTR + 4];
            }
            uint32_t bfr[4][2];
#pragma unroll
            for (int nt = 0; nt < 4; nt++) {
                int c = (warp_n * 32 + nt * 8 + gid) * BSTR + tig;
                bfr[nt][0] = Bbase[c];
                bfr[nt][1] = Bbase[c + 4];
            }
#pragma unroll
            for (int mt = 0; mt < 2; mt++)
#pragma unroll
                for (int nt = 0; nt < 4; nt++)
                    mma_bf16(acc[mt][nt], af[mt][0], af[mt][1], af[mt][2],
                             af[mt][3], bfr[nt][0], bfr[nt][1]);
        }
        if (ch + 1 < nch) {
            __syncthreads();
            STORES(((ch + 1) & 1) * GSTAGE);
            __syncthreads();
        }
    }

#pragma unroll
    for (int mt = 0; mt < 2; mt++) {
        int r0 = m0 + warp_m * 32 + mt * 16 + gid;
#pragma unroll
        for (int nt = 0; nt < 4; nt++) {
            int c = n0 + warp_n * 32 + nt * 8 + tig * 2;
            *(float2*)(C + (long)r0 * ldc + c) =
                make_float2(acc[mt][nt][0], acc[mt][nt][1]);
            *(float2*)(C + (long)(r0 + 8) * ldc + c) =
                make_float2(acc[mt][nt][2], acc[mt][nt][3]);
        }
    }
}

__global__ void __launch_bounds__(256, 3) qkv_gemm(
    const float* __restrict__ x,
    const float* __restrict__ Wq, const float* __restrict__ Wk,
    const float* __restrict__ Wv,
    float* q, float* k, float* v)
{
    const float* B = blockIdx.z == 0 ? Wq : blockIdx.z == 1 ? Wk : Wv;
    float* C = blockIdx.z == 0 ? q : blockIdx.z == 1 ? k : v;
    bf16_nt_body(x, B, C, CEMB, CEMB, CEMB, CEMB,
                 blockIdx.y * 128, blockIdx.x * 64);
}

__global__ void __launch_bounds__(256, 3) wo_gemm(
    const float* __restrict__ y, const float* __restrict__ Wo, float* out)
{
    bf16_nt_body(y, Wo, out, CEMB, CEMB, CEMB, CEMB,
                 blockIdx.y * 128, blockIdx.x * 64);
}

// ---------------- prep (unchanged) --------------------------------------------
__global__ __launch_bounds__(512) void prep_kernel(
    const float* __restrict__ qraw, const float* __restrict__ kraw,
    const float* __restrict__ vraw,
    const float* __restrict__ cosp, const float* __restrict__ sinp,
    float* __restrict__ qn, float* __restrict__ kvp,
    uint32_t* __restrict__ qbh, uint32_t* __restrict__ qbl,
    uint32_t* __restrict__ kbh, uint32_t* __restrict__ kbl)
{
    int h = blockIdx.x, g = blockIdx.y;
    int tid = threadIdx.x;
    int w = tid >> 6, d = tid & 63;
    int t = g * 8 + w;

    __shared__ float r1[8][64], r2[8][64], skc[8][64], sv[8][64];
    __shared__ float sq[8][64], sk[8][64];
    __shared__ float kvstage[8][512];

    long base = (long)t * CEMB + h * HD;
    int j = d & 31;
    float c = cosp[t * 32 + j], s = sinp[t * 32 + j];

    float x1q = qraw[base + j], x2q = qraw[base + j + 32];
    float qv = (d < 32) ? (x1q * c + x2q * s) : (x2q * c - x1q * s);
    float x1k = kraw[base + j], x2k = kraw[base + j + 32];
    float kvv = (d < 32) ? (x1k * c + x2k * s) : (x2k * c - x1k * s);

    r1[w][d] = qv * qv;
    r2[w][d] = kvv * kvv;
    __syncthreads();
#pragma unroll
    for (int off = 32; off > 0; off >>= 1) {
        if (d < off) { r1[w][d] += r1[w][d + off]; r2[w][d] += r2[w][d + off]; }
        __syncthreads();
    }
    float rq = rsqrtf(r1[w][0] * (1.f / 64.f) + 1e-6f);
    float rk = rsqrtf(r2[w][0] * (1.f / 64.f) + 1e-6f);
    float qno = qv * rq, kno = kvv * rk;

    qn[((long)h * T_SEQ + t) * HD + d] = qno;
    sq[w][d] = qno;
    sk[w][d] = kno;

    float o = kno * kno;
    o += __shfl_xor_sync(0xffffffffu, o, 1);
    o += __shfl_xor_sync(0xffffffffu, o, 2);
    o += __shfl_xor_sync(0xffffffffu, o, 4);
    float ko = kno / fmaxf(sqrtf(o), 1e-12f);
    skc[w][d] = ((d & 7) == 0) ? ko : -ko;
    sv[w][d] = vraw[base + d];
    __syncthreads();

    {
        float kc = skc[w][d];
        int mb = d & ~7;
#pragma unroll
        for (int i = 0; i < 8; i++)
            kvstage[w][d * 8 + i] = tf32r(kc * sv[w][mb + i]);
    }
    {
        long pbase = ((long)h * T_SEQ + t) * 32;
        if (d < 32) {
            uint2 p = pack_split(sq[w][2 * d], sq[w][2 * d + 1]);
            qbh[pbase + permw(d)] = p.x;
            qbl[pbase + permw(d)] = p.y;
        } else {
            int d2 = d - 32;
            uint2 p = pack_split(sk[w][2 * d2], sk[w][2 * d2 + 1]);
            kbh[pbase + permw(d2)] = p.x;
            kbl[pbase + permw(d2)] = p.y;
        }
    }
    __syncthreads();

    float* outb = kvp + ((long)(h * 256 + g) * 512) * 8;
#pragma unroll
    for (int it = 0; it < 2; it++) {
        int idx = tid + it * 512;
        int cc = idx >> 1, half = idx & 1;
        float4 v;
        v.x = kvstage[((half * 4 + 0) >> 1) + ((half * 4 + 0) & 1) * 4][cc];
        v.y = kvstage[((half * 4 + 1) >> 1) + ((half * 4 + 1) & 1) * 4][cc];
        v.z = kvstage[((half * 4 + 2) >> 1) + ((half * 4 + 2) & 1) * 4][cc];
        v.w = kvstage[((half * 4 + 3) >> 1) + ((half * 4 + 3) & 1) * 4][cc];
        *(float4*)(outb + cc * 8 + half * 4) = v;
    }
}

// ---------------- octonion math ----------------------------------------------
__device__ __forceinline__ void qmul4(const float* q1, const float* q2, float* r)
{
    r[0] = q1[0]*q2[0] - q1[1]*q2[1] - q1[2]*q2[2] - q1[3]*q2[3];
    r[1] = q1[0]*q2[1] + q1[1]*q2[0] + q1[2]*q2[3] - q1[3]*q2[2];
    r[2] = q1[0]*q2[2] - q1[1]*q2[3] + q1[2]*q2[0] + q1[3]*q2[1];
    r[3] = q1[0]*q2[3] + q1[1]*q2[2] - q1[2]*q2[1] + q1[3]*q2[0];
}
__device__ __forceinline__ void omul8(const float* o1, const float* o2, float* r)
{
    const float* a = o1; const float* b = o1 + 4;
    const float* c = o2; const float* d = o2 + 4;
    float dc[4] = { d[0], -d[1], -d[2], -d[3] };
    float cc[4] = { c[0], -c[1], -c[2], -c[3] };
    float t1[4], t2[4];
    qmul4(a, c, t1); qmul4(dc, b, t2);
    r[0] = t1[0] - t2[0]; r[1] = t1[1] - t2[1];
    r[2] = t1[2] - t2[2]; r[3] = t1[3] - t2[3];
    qmul4(d, a, t1); qmul4(b, cc, t2);
    r[4] = t1[0] + t2[0]; r[5] = t1[1] + t2[1];
    r[6] = t1[2] + t2[2]; r[7] = t1[3] + t2[3];
}

// ===== fused attention: pipelined scores(jt+1) || Z(jt), ONE barrier/iter ====
#define TK 16
// word offsets in dynamic smem
#define OFF_KV 0
#define KV_STG 8192             // 16 keys * 512c * 4B = 32KB, 4 stages (mod 4)
#define OFF_KH 32768            // 4 stages x 16x40
#define KH_STG 640
#define OFF_KL 35328
#define OFF_P  37888            // 2 stages x 64x40
#define P_STG  2560
#define OFF_QH 43008            // 64 x 40
#define OFF_QL 45568
#define OFF_S  48128            // 2x64 + 64
#define FA_SMEM ((OFF_S + 192) * 4)   // 193280 B

__global__ void __launch_bounds__(512, 1) fused_attn(
    const float* __restrict__ qn,
    const uint32_t* __restrict__ qbh, const uint32_t* __restrict__ qbl,
    const uint32_t* __restrict__ kbh, const uint32_t* __restrict__ kbl,
    const float* __restrict__ kvp, float* __restrict__ y)
{
    extern __shared__ __align__(16) float fsm[];
    uint32_t* usm = (uint32_t*)fsm;
    uint32_t sbase = smem_u32(fsm);

    int qt = 31 - blockIdx.x;
    int h = blockIdx.y;
    int r0 = qt * 64;
    int njt = 4 * (qt + 1);      // 16-key tiles

    int tid = threadIdx.x, lane = tid & 31, wid = tid >> 5;
    int gid = lane >> 2, tig = lane & 3;
    // score warps: wid 0..7: rg = wid&3 (16-row group), kg = wid>>2 (8-key group)
    int rg = wid & 3, kg = wid >> 2;
    int rowa = rg * 16 + gid;

    const float*    kvph = kvp + (long)h * T_SEQ * KVW;
    const uint32_t* khh = kbh + (long)h * T_SEQ * 32;
    const uint32_t* khl = kbl + (long)h * T_SEQ * 32;

    auto issue_tile = [&](int t) {
        const float* src = kvph + (long)t * 8192;
        uint32_t dstw = OFF_KV + (t & 3) * KV_STG;
#pragma unroll
        for (int i = 0; i < 4; i++) {
            int idx = tid + i * 512;
            CP16(sbase + (dstw + idx * 4) * 4, src + idx * 4);
        }
        if (tid < 256) {
            int arr = tid >> 7, rr = (tid >> 3) & 15, ch = (tid & 7) * 4;
            const uint32_t* sb2 = (arr ? khl : khh) + (long)(t * TK + rr) * 32 + ch;
            CP16(sbase + ((arr ? OFF_KL : OFF_KH) + (t & 3) * KH_STG + rr * 40 + ch) * 4, sb2);
        }
    };

    float s_acc0 = 0.f, s_acc1 = 0.f;
    int phys0 = ((2 * tig) & 3) * 2 + (tig >> 1);
    int phys1 = ((2 * tig + 1) & 3) * 2 + (tig >> 1);

    // scores(j) into P[j&1] (warps 0..7 only)
    auto do_scores = [&](int j) {
        float sc3[3][4];
#pragma unroll
        for (int p = 0; p < 3; p++)
#pragma unroll
            for (int q = 0; q < 4; q++) sc3[p][q] = 0.f;
        int krow = (kg * 8 + gid) * 40 + 2 * tig;
        int arow2 = rowa * 40 + 2 * tig;
        const uint32_t* KHb = usm + OFF_KH + (j & 3) * KH_STG;
        const uint32_t* KLb = usm + OFF_KL + (j & 3) * KH_STG;
#pragma unroll
        for (int ks = 0; ks < 4; ks++) {
#pragma unroll
            for (int p = 0; p < 3; p++) {
                const uint32_t* Ab = usm + (p == 2 ? OFF_QL : OFF_QH);
                const uint32_t* Bb = (p == 1) ? KLb : KHb;
                uint2 qa = *(const uint2*)(Ab + arow2 + ks * 8);
                uint2 qb = *(const uint2*)(Ab + arow2 + ks * 8 + 8 * 40);
                uint2 kb = *(const uint2*)(Bb + krow + ks * 8);
                mma_bf16(sc3[p], qa.x, qb.x, qa.y, qb.y, kb.x, kb.y);
            }
        }
        float s0 = sc3[0][0] + sc3[1][0] + sc3[2][0];
        float s1 = sc3[0][1] + sc3[1][1] + sc3[2][1];
        float s2 = sc3[0][2] + sc3[1][2] + sc3[2][2];
        float s3 = sc3[0][3] + sc3[1][3] + sc3[2][3];

        int colg = j * TK + kg * 8 + tig * 2;
        float p00 = __expf(s0 * 0.125f);
        float p01 = __expf(s1 * 0.125f);
        float p10 = __expf(s2 * 0.125f);
        float p11 = __expf(s3 * 0.125f);
        if (j >= njt - 4) {
            if (colg     > r0 + rowa)     p00 = 0.f;
            if (colg + 1 > r0 + rowa)     p01 = 0.f;
            if (colg     > r0 + rowa + 8) p10 = 0.f;
            if (colg + 1 > r0 + rowa + 8) p11 = 0.f;
        }
        p00 = tf32r(p00); p01 = tf32r(p01);
        p10 = tf32r(p10); p11 = tf32r(p11);
        float* Pr = fsm + OFF_P + (j & 1) * P_STG + rowa * 40 + kg * 8;
        Pr[phys0] = p00; Pr[phys1] = p01;
        Pr[8 * 40 + phys0] = p10; Pr[8 * 40 + phys1] = p11;
        s_acc0 += p00 + p01;
        s_acc1 += p10 + p11;
    };

    // prologue: Q tiles, tile 0, tile 1; scores(0)
    {
        const uint32_t* qhh = qbh + ((long)h * T_SEQ + r0) * 32;
        const uint32_t* qhl = qbl + ((long)h * T_SEQ + r0) * 32;
#pragma unroll
        for (int i = 0; i < 2; i++) {
            int idx = tid + i * 512;
            int arr = idx >> 9, rr = (idx >> 3) & 63, ch = (idx & 7) * 4;
            const uint32_t* src = (arr ? qhl : qhh) + (long)rr * 32 + ch;
            CP16(sbase + ((arr ? OFF_QL : OFF_QH) + rr * 40 + ch) * 4, src);
        }
        issue_tile(0);
        CP_COMMIT();                 // group: Q + tile0
        issue_tile(1);
        CP_COMMIT();                 // group: tile1
        asm volatile("cp.async.wait_group 1;" ::: "memory");
        __syncthreads();
        if (wid < 8) do_scores(0);
    }

    float zacc[4][4][4];
#pragma unroll
    for (int i = 0; i < 4; i++)
#pragma unroll
        for (int j = 0; j < 4; j++)
#pragma unroll
            for (int q = 0; q < 4; q++) zacc[i][j][q] = 0.f;

    for (int jt = 0; jt < njt; jt++) {
        if (jt + 2 < njt) {
            issue_tile(jt + 2);
            CP_COMMIT();
            asm volatile("cp.async.wait_group 1;" ::: "memory");
        } else {
            asm volatile("cp.async.wait_group 0;" ::: "memory");
        }
        __syncthreads();   // ONE barrier: P[jt] & tile jt+1 ready; prev Z done

        // scores(jt+1) by warps 0..7 — independent of Z(jt)
        if (wid < 8 && jt + 1 < njt) do_scores(jt + 1);

        // Z(jt) by all warps: warp tile 64 rows x 32 cols
        {
            const float* KVs = fsm + OFF_KV + (jt & 3) * KV_STG;
            const float* Pb = fsm + OFF_P + (jt & 1) * P_STG;
#pragma unroll
            for (int ks = 0; ks < 2; ks++) {
                uint2 pa[4][2];
#pragma unroll
                for (int mt = 0; mt < 4; mt++) {
                    const float* Pr = Pb + (mt * 16 + gid) * 40 + ks * 8 + 2 * tig;
                    pa[mt][0] = *(const uint2*)Pr;
                    pa[mt][1] = *(const uint2*)(Pr + 8 * 40);
                }
#pragma unroll
                for (int nt = 0; nt < 4; nt++) {
                    int c = wid * 32 + nt * 8 + gid;
                    uint2 bb = *(const uint2*)(KVs + (ks * 512 + c) * 8 + 2 * tig);
#pragma unroll
                    for (int mt = 0; mt < 4; mt++)
                        mma_tf32(zacc[mt][nt], pa[mt][0].x, pa[mt][1].x,
                                 pa[mt][0].y, pa[mt][1].y, bb.x, bb.y);
                }
            }
        }
    }
    __syncthreads();

    // ---- S reduce (score warps only) ----
    s_acc0 += __shfl_xor_sync(~0u, s_acc0, 1);
    s_acc0 += __shfl_xor_sync(~0u, s_acc0, 2);
    s_acc1 += __shfl_xor_sync(~0u, s_acc1, 1);
    s_acc1 += __shfl_xor_sync(~0u, s_acc1, 2);
    if (wid < 8 && tig == 0) {
        fsm[OFF_S + kg * 64 + rowa] = s_acc0;
        fsm[OFF_S + kg * 64 + rowa + 8] = s_acc1;
    }
    // ---- Z regs -> smem overlay (KV stages dead), stride 520 ----
#pragma unroll
    for (int mt = 0; mt < 4; mt++) {
        int row = mt * 16 + gid;
#pragma unroll
        for (int nt = 0; nt < 4; nt++) {
            float* zp = fsm + row * 520 + wid * 32 + (wid >> 1) + nt * 8 + tig * 2;
            zp[0] = zacc[mt][nt][0];
            zp[1] = zacc[mt][nt][1];
            zp[8 * 520] = zacc[mt][nt][2];
            zp[8 * 520 + 1] = zacc[mt][nt][3];
        }
    }
    __syncthreads();
    if (tid < 64)
        fsm[OFF_S + 128 + tid] = 1.f / (fsm[OFF_S + tid] + fsm[OFF_S + 64 + tid]);
    __syncthreads();

    // ---- octonion epilogue: one (row, m) unit per thread ----
    {
        int row = tid >> 3, m = tid & 7;
        float invS = fsm[OFF_S + 128 + row];
        const float* q = qn + ((long)h * T_SEQ + r0 + row) * HD + m * 8;
        const float* z = fsm + row * 520 + m * 65;

        float q8[8];
        float4 qa = *(const float4*)q, qb = *(const float4*)(q + 4);
        q8[0]=qa.x; q8[1]=qa.y; q8[2]=qa.z; q8[3]=qa.w;
        q8[4]=qb.x; q8[5]=qb.y; q8[6]=qb.z; q8[7]=qb.w;
        float acc[8] = {0,0,0,0,0,0,0,0};
#pragma unroll
        for (int p = 0; p < 8; p++) {
            float e[8] = {0,0,0,0,0,0,0,0};
            e[p] = 1.f;
            float uo[8], z8[8], wv[8];
            omul8(q8, e, uo);
#pragma unroll
            for (int i = 0; i < 8; i++) z8[i] = z[p * 8 + i];
            omul8(uo, z8, wv);
#pragma unroll
            for (int k = 0; k < 8; k++) acc[k] += wv[k];
        }
        float* yo = y + (long)(r0 + row) * CEMB + h * HD + m * 8;
        *(float4*)yo = make_float4(acc[0]*invS, acc[1]*invS, acc[2]*invS, acc[3]*invS);
        *(float4*)(yo + 4) = make_float4(acc[4]*invS, acc[5]*invS, acc[6]*invS, acc[7]*invS);
    }
}

// ---------------- launch -----------------------------------------------------
extern "C" void kernel_launch(void* const* d_in, const int* in_sizes, int n_in,
                              void* d_out, int out_size)
{
    const float* x    = (const float*)d_in[0];
    const float* cosp = (const float*)d_in[1];
    const float* sinp = (const float*)d_in[2];
    const float* Wq   = (const float*)d_in[3];
    const float* Wk   = (const float*)d_in[4];
    const float* Wv   = (const float*)d_in[5];
    const float* Wo   = (const float*)d_in[6];
    float* out = (float*)d_out;

    float *qraw, *kraw, *vraw, *qn, *kvp, *y;
    uint32_t *qbh, *qbl, *kbh, *kbl;
    cudaGetSymbolAddress((void**)&qraw, g_qraw);
    cudaGetSymbolAddress((void**)&kraw, g_kraw);
    cudaGetSymbolAddress((void**)&vraw, g_vraw);
    cudaGetSymbolAddress((void**)&qn,   g_qn);
    cudaGetSymbolAddress((void**)&kvp,  g_kvp);
    cudaGetSymbolAddress((void**)&qbh,  g_qbh);
    cudaGetSymbolAddress((void**)&qbl,  g_qbl);
    cudaGetSymbolAddress((void**)&kbh,  g_kbh);
    cudaGetSymbolAddress((void**)&kbl,  g_kbl);
    cudaGetSymbolAddress((void**)&y,    g_y);

    const int smem_gemm = 2 * GSTAGE * 4;   // 30720 B
    cudaFuncSetAttribute(qkv_gemm, cudaFuncAttributeMaxDynamicSharedMemorySize, smem_gemm);
    cudaFuncSetAttribute(wo_gemm,  cudaFuncAttributeMaxDynamicSharedMemorySize, smem_gemm);
    cudaFuncSetAttribute(fused_attn, cudaFuncAttributeMaxDynamicSharedMemorySize, FA_SMEM);

    // 1) merged QKV projections (3xBF16 split, NT, 128x64 tiles)
    qkv_gemm<<<dim3(CEMB / 64, T_SEQ / 128, 3), 256, smem_gemm>>>(
        x, Wq, Wk, Wv, qraw, kraw, vraw);

    // 2) rotary + rms + octet-norm + paired tf32 KV + permuted bf16 packing
    prep_kernel<<<dim3(NH, T_SEQ / 8), 512>>>(qraw, kraw, vraw, cosp, sinp,
                                              qn, kvp, qbh, qbl, kbh, kbl);

    // 3) fused attention: pipelined scores || Z, one barrier per 16-key tile
    fused_attn<<<dim3(32, NH), 512, FA_SMEM>>>(qn, qbh, qbl, kbh, kbl, kvp, y);

    // 4) out = y @ Wo^T (3xBF16 split, 128x64 tiles)
    wo_gemm<<<dim3(CEMB / 64, T_SEQ / 128), 256, smem_gemm>>>(y, Wo, out);
}

// round 12
// speedup vs baseline: 1.2907x; 1.1969x over previous
#include <cuda_runtime.h>
#include <cuda_fp16.h>
#include <cstdint>
#include <math.h>

#define T_SEQ 2048
#define NH 16
#define HD 64
#define CEMB 1024
#define KVW 512

// ---------------- scratch (device globals) ----------------------------------
static __device__ float g_qraw[T_SEQ * CEMB];
static __device__ float g_kraw[T_SEQ * CEMB];
static __device__ float g_vraw[T_SEQ * CEMB];
static __device__ float g_qn[NH * T_SEQ * HD];
static __device__ uint32_t g_kvp16[NH * T_SEQ * KVW / 2]; // fp16x2 paired [h][G][c][w']
static __device__ uint32_t g_qbh[NH * T_SEQ * 32];
static __device__ uint32_t g_qbl[NH * T_SEQ * 32];
static __device__ uint32_t g_kbh[NH * T_SEQ * 32];
static __device__ uint32_t g_kbl[NH * T_SEQ * 32];
static __device__ float g_y[T_SEQ * CEMB];

// ---------------- helpers ----------------------------------------------------
static __device__ __forceinline__ uint32_t smem_u32(const void* p) {
    uint32_t a;
    asm("{ .reg .u64 t; cvta.to.shared.u64 t, %1; cvt.u32.u64 %0, t; }" : "=r"(a) : "l"(p));
    return a;
}
static __device__ __forceinline__ void mma_f16(
    float* acc, uint32_t a0, uint32_t a1, uint32_t a2, uint32_t a3,
    uint32_t b0, uint32_t b1)
{
    asm volatile(
        "mma.sync.aligned.m16n8k16.row.col.f32.f16.f16.f32 "
        "{%0,%1,%2,%3},{%4,%5,%6,%7},{%8,%9},{%0,%1,%2,%3};"
        : "+f"(acc[0]), "+f"(acc[1]), "+f"(acc[2]), "+f"(acc[3])
        : "r"(a0), "r"(a1), "r"(a2), "r"(a3), "r"(b0), "r"(b1));
}
static __device__ __forceinline__ void mma_bf16(
    float* acc, uint32_t a0, uint32_t a1, uint32_t a2, uint32_t a3,
    uint32_t b0, uint32_t b1)
{
    asm volatile(
        "mma.sync.aligned.m16n8k16.row.col.f32.bf16.bf16.f32 "
        "{%0,%1,%2,%3},{%4,%5,%6,%7},{%8,%9},{%0,%1,%2,%3};"
        : "+f"(acc[0]), "+f"(acc[1]), "+f"(acc[2]), "+f"(acc[3])
        : "r"(a0), "r"(a1), "r"(a2), "r"(a3), "r"(b0), "r"(b1));
}
static __device__ __forceinline__ uint2 pack_split(float f0, float f1) {
    uint32_t h;
    asm("cvt.rn.bf16x2.f32 %0, %1, %2;" : "=r"(h) : "f"(f1), "f"(f0));
    float h0 = __uint_as_float(h << 16);
    float h1 = __uint_as_float(h & 0xffff0000u);
    uint32_t l;
    float r0 = f0 - h0, r1 = f1 - h1;
    asm("cvt.rn.bf16x2.f32 %0, %1, %2;" : "=r"(l) : "f"(r1), "f"(r0));
    return make_uint2(h, l);
}
static __device__ __forceinline__ uint32_t packf16(float lo, float hi) {
    uint32_t w;
    asm("cvt.rn.f16x2.f32 %0, %1, %2;" : "=r"(w) : "f"(hi), "f"(lo));
    return w;
}
#define CP16(dst_u32, src_ptr) \
    asm volatile("cp.async.cg.shared.global [%0], [%1], 16;" \
                 :: "r"(dst_u32), "l"(src_ptr) : "memory")
#define CP_COMMIT() asm volatile("cp.async.commit_group;" ::: "memory")

static __device__ __forceinline__ int permw(int d) {
    return (d & ~7) + ((d & 3) * 2 + ((d & 7) >> 2));
}

// ================= bf16 3x-split GEMM (NT), 128x64 tiles (unchanged) =========
#define BSTR 12
#define GA_HI 0
#define GB_HI (128 * BSTR)
#define GA_LO (GB_HI + 64 * BSTR)
#define GB_LO (GA_LO + 128 * BSTR)
#define GSTAGE (GB_LO + 64 * BSTR)

static __device__ __forceinline__ void bf16_nt_body(
    const float* __restrict__ A, const float* __restrict__ B, float* __restrict__ C,
    int K, int lda, int ldb, int ldc, int m0, int n0)
{
    extern __shared__ uint32_t smu[];
    int nch = K >> 4;

    int tid = threadIdx.x;
    int lane = tid & 31, wid = tid >> 5;
    int gid = lane >> 2, tig = lane & 3;
    int warp_m = wid & 3, warp_n = wid >> 2;
    int arow = tid >> 1, akc = (tid & 1) * 8;
    int brow = tid >> 2, bkc = (tid & 3) * 4;

    float acc[2][4][4];
#pragma unroll
    for (int i = 0; i < 2; i++)
#pragma unroll
        for (int j = 0; j < 4; j++)
#pragma unroll
            for (int q = 0; q < 4; q++) acc[i][j][q] = 0.f;

    float4 ra0, ra1, rb0;
    auto LOADG = [&](int k0) {
        const float* ap = A + (long)(m0 + arow) * lda + k0 + akc;
        ra0 = *(const float4*)ap;
        ra1 = *(const float4*)(ap + 4);
        rb0 = *(const float4*)(B + (long)(n0 + brow) * ldb + k0 + bkc);
    };
    auto STORES = [&](int sb) {
        int ao = arow * BSTR + (akc >> 1);
        uint2 p0 = pack_split(ra0.x, ra0.y), p1 = pack_split(ra0.z, ra0.w);
        uint2 p2 = pack_split(ra1.x, ra1.y), p3 = pack_split(ra1.z, ra1.w);
        *(uint4*)(smu + sb + GA_HI + ao) = make_uint4(p0.x, p1.x, p2.x, p3.x);
        *(uint4*)(smu + sb + GA_LO + ao) = make_uint4(p0.y, p1.y, p2.y, p3.y);
        uint2 q0 = pack_split(rb0.x, rb0.y), q1 = pack_split(rb0.z, rb0.w);
        int bo = brow * BSTR + (bkc >> 1);
        *(uint2*)(smu + sb + GB_HI + bo) = make_uint2(q0.x, q1.x);
        *(uint2*)(smu + sb + GB_LO + bo) = make_uint2(q0.y, q1.y);
    };

    LOADG(0);
    STORES(0);
    __syncthreads();

    for (int ch = 0; ch < nch; ch++) {
        if (ch + 1 < nch) LOADG((ch + 1) << 4);
        int sb = (ch & 1) * GSTAGE;
#pragma unroll
        for (int p = 0; p < 3; p++) {
            const uint32_t* Abase = smu + sb + (p == 2 ? GA_LO : GA_HI);
            const uint32_t* Bbase = smu + sb + (p == 1 ? GB_LO : GB_HI);
            uint32_t af[2][4];
#pragma unroll
            for (int mt = 0; mt < 2; mt++) {
                int r = (warp_m * 32 + mt * 16 + gid) * BSTR + tig;
                af[mt][0] = Abase[r];
                af[mt][1] = Abase[r + 8 * BSTR];
                af[mt][2] = Abase[r + 4];
                af[mt][3] = Abase[r + 8 * BSTR + 4];
            }
            uint32_t bfr[4][2];
#pragma unroll
            for (int nt = 0; nt < 4; nt++) {
                int c = (warp_n * 32 + nt * 8 + gid) * BSTR + tig;
                bfr[nt][0] = Bbase[c];
                bfr[nt][1] = Bbase[c + 4];
            }
#pragma unroll
            for (int mt = 0; mt < 2; mt++)
#pragma unroll
                for (int nt = 0; nt < 4; nt++)
                    mma_bf16(acc[mt][nt], af[mt][0], af[mt][1], af[mt][2],
                             af[mt][3], bfr[nt][0], bfr[nt][1]);
        }
        if (ch + 1 < nch) {
            __syncthreads();
            STORES(((ch + 1) & 1) * GSTAGE);
            __syncthreads();
        }
    }

#pragma unroll
    for (int mt = 0; mt < 2; mt++) {
        int r0 = m0 + warp_m * 32 + mt * 16 + gid;
#pragma unroll
        for (int nt = 0; nt < 4; nt++) {
            int c = n0 + warp_n * 32 + nt * 8 + tig * 2;
            *(float2*)(C + (long)r0 * ldc + c) =
                make_float2(acc[mt][nt][0], acc[mt][nt][1]);
            *(float2*)(C + (long)(r0 + 8) * ldc + c) =
                make_float2(acc[mt][nt][2], acc[mt][nt][3]);
        }
    }
}

__global__ void __launch_bounds__(256, 3) qkv_gemm(
    const float* __restrict__ x,
    const float* __restrict__ Wq, const float* __restrict__ Wk,
    const float* __restrict__ Wv,
    float* q, float* k, float* v)
{
    const float* B = blockIdx.z == 0 ? Wq : blockIdx.z == 1 ? Wk : Wv;
    float* C = blockIdx.z == 0 ? q : blockIdx.z == 1 ? k : v;
    bf16_nt_body(x, B, C, CEMB, CEMB, CEMB, CEMB,
                 blockIdx.y * 128, blockIdx.x * 64);
}

__global__ void __launch_bounds__(256, 3) wo_gemm(
    const float* __restrict__ y, const float* __restrict__ Wo, float* out)
{
    bf16_nt_body(y, Wo, out, CEMB, CEMB, CEMB, CEMB,
                 blockIdx.y * 128, blockIdx.x * 64);
}

// ---------------- prep: fp16 paired KV + permuted bf16 q/k packing -----------
__global__ __launch_bounds__(512) void prep_kernel(
    const float* __restrict__ qraw, const float* __restrict__ kraw,
    const float* __restrict__ vraw,
    const float* __restrict__ cosp, const float* __restrict__ sinp,
    float* __restrict__ qn, uint32_t* __restrict__ kvp16,
    uint32_t* __restrict__ qbh, uint32_t* __restrict__ qbl,
    uint32_t* __restrict__ kbh, uint32_t* __restrict__ kbl)
{
    int h = blockIdx.x, g = blockIdx.y;
    int tid = threadIdx.x;
    int w = tid >> 6, d = tid & 63;
    int t = g * 8 + w;

    __shared__ float r1[8][64], r2[8][64], skc[8][64], sv[8][64];
    __shared__ float sq[8][64], sk[8][64];
    __shared__ float kvstage[8][512];

    long base = (long)t * CEMB + h * HD;
    int j = d & 31;
    float c = cosp[t * 32 + j], s = sinp[t * 32 + j];

    float x1q = qraw[base + j], x2q = qraw[base + j + 32];
    float qv = (d < 32) ? (x1q * c + x2q * s) : (x2q * c - x1q * s);
    float x1k = kraw[base + j], x2k = kraw[base + j + 32];
    float kvv = (d < 32) ? (x1k * c + x2k * s) : (x2k * c - x1k * s);

    r1[w][d] = qv * qv;
    r2[w][d] = kvv * kvv;
    __syncthreads();
#pragma unroll
    for (int off = 32; off > 0; off >>= 1) {
        if (d < off) { r1[w][d] += r1[w][d + off]; r2[w][d] += r2[w][d + off]; }
        __syncthreads();
    }
    float rq = rsqrtf(r1[w][0] * (1.f / 64.f) + 1e-6f);
    float rk = rsqrtf(r2[w][0] * (1.f / 64.f) + 1e-6f);
    float qno = qv * rq, kno = kvv * rk;

    qn[((long)h * T_SEQ + t) * HD + d] = qno;
    sq[w][d] = qno;
    sk[w][d] = kno;

    float o = kno * kno;
    o += __shfl_xor_sync(0xffffffffu, o, 1);
    o += __shfl_xor_sync(0xffffffffu, o, 2);
    o += __shfl_xor_sync(0xffffffffu, o, 4);
    float ko = kno / fmaxf(sqrtf(o), 1e-12f);
    skc[w][d] = ((d & 7) == 0) ? ko : -ko;
    sv[w][d] = vraw[base + d];
    __syncthreads();

    {
        float kc = skc[w][d];
        int mb = d & ~7;
#pragma unroll
        for (int i = 0; i < 8; i++)
            kvstage[w][d * 8 + i] = kc * sv[w][mb + i];
    }
    {
        long pbase = ((long)h * T_SEQ + t) * 32;
        if (d < 32) {
            uint2 p = pack_split(sq[w][2 * d], sq[w][2 * d + 1]);
            qbh[pbase + permw(d)] = p.x;
            qbl[pbase + permw(d)] = p.y;
        } else {
            int d2 = d - 32;
            uint2 p = pack_split(sk[w][2 * d2], sk[w][2 * d2 + 1]);
            kbh[pbase + permw(d2)] = p.x;
            kbl[pbase + permw(d2)] = p.y;
        }
    }
    __syncthreads();

    // fp16 paired write: group G = g>>1 (16 keys), this block owns pairs
    // p = (g&1)*4 + pl (pl=0..3, keys local 2pl,2pl+1); phys word = pl*2 + (g&1)
    uint32_t* outb = kvp16 + ((long)(h * 128 + (g >> 1)) * 512) * 8 + (g & 1);
#pragma unroll
    for (int it = 0; it < 4; it++) {
        int idx = tid + it * 512;
        int cc = idx >> 2, pl = idx & 3;
        outb[cc * 8 + pl * 2] = packf16(kvstage[2 * pl][cc], kvstage[2 * pl + 1][cc]);
    }
}

// ---------------- octonion math ----------------------------------------------
__device__ __forceinline__ void qmul4(const float* q1, const float* q2, float* r)
{
    r[0] = q1[0]*q2[0] - q1[1]*q2[1] - q1[2]*q2[2] - q1[3]*q2[3];
    r[1] = q1[0]*q2[1] + q1[1]*q2[0] + q1[2]*q2[3] - q1[3]*q2[2];
    r[2] = q1[0]*q2[2] - q1[1]*q2[3] + q1[2]*q2[0] + q1[3]*q2[1];
    r[3] = q1[0]*q2[3] + q1[1]*q2[2] - q1[2]*q2[1] + q1[3]*q2[0];
}
__device__ __forceinline__ void omul8(const float* o1, const float* o2, float* r)
{
    const float* a = o1; const float* b = o1 + 4;
    const float* c = o2; const float* d = o2 + 4;
    float dc[4] = { d[0], -d[1], -d[2], -d[3] };
    float cc[4] = { c[0], -c[1], -c[2], -c[3] };
    float t1[4], t2[4];
    qmul4(a, c, t1); qmul4(dc, b, t2);
    r[0] = t1[0] - t2[0]; r[1] = t1[1] - t2[1];
    r[2] = t1[2] - t2[2]; r[3] = t1[3] - t2[3];
    qmul4(d, a, t1); qmul4(b, cc, t2);
    r[4] = t1[0] + t2[0]; r[5] = t1[1] + t2[1];
    r[6] = t1[2] + t2[2]; r[7] = t1[3] + t2[3];
}

// ===== fused attention: pipelined, fp16 k16 Z GEMM ===========================
#define TK 16
#define OFF_KV 0
#define KV_STG 4096             // 512c * 8 fp16x2 words = 16KB, 4 stages
#define OFF_KH 16384
#define KH_STG 640
#define OFF_KL 18944
#define OFF_P  21504            // 2 stages x 64x40 (fp16x2 words)
#define P_STG  2560
#define OFF_QH 26624
#define OFF_QL 29184
#define OFF_S  33280            // after epilogue Z overlay (64*520 = 33280)
#define FA_SMEM ((OFF_S + 192) * 4)

__global__ void __launch_bounds__(512, 1) fused_attn(
    const float* __restrict__ qn,
    const uint32_t* __restrict__ qbh, const uint32_t* __restrict__ qbl,
    const uint32_t* __restrict__ kbh, const uint32_t* __restrict__ kbl,
    const uint32_t* __restrict__ kvp16, float* __restrict__ y)
{
    extern __shared__ __align__(16) float fsm[];
    uint32_t* usm = (uint32_t*)fsm;
    uint32_t sbase = smem_u32(fsm);

    int qt = 31 - blockIdx.x;
    int h = blockIdx.y;
    int r0 = qt * 64;
    int njt = 4 * (qt + 1);

    int tid = threadIdx.x, lane = tid & 31, wid = tid >> 5;
    int gid = lane >> 2, tig = lane & 3;
    int rg = wid & 3, kg = wid >> 2;
    int rowa = rg * 16 + gid;

    const uint32_t* kvph = kvp16 + (long)h * 128 * 4096;
    const uint32_t* khh = kbh + (long)h * T_SEQ * 32;
    const uint32_t* khl = kbl + (long)h * T_SEQ * 32;

    auto issue_tile = [&](int t) {
        const uint32_t* src = kvph + (long)t * 4096;
        uint32_t dstw = OFF_KV + (t & 3) * KV_STG;
#pragma unroll
        for (int i = 0; i < 2; i++) {
            int idx = tid + i * 512;
            CP16(sbase + (dstw + idx * 4) * 4, src + idx * 4);
        }
        if (tid < 256) {
            int arr = tid >> 7, rr = (tid >> 3) & 15, ch = (tid & 7) * 4;
            const uint32_t* sb2 = (arr ? khl : khh) + (long)(t * TK + rr) * 32 + ch;
            CP16(sbase + ((arr ? OFF_KL : OFF_KH) + (t & 3) * KH_STG + rr * 40 + ch) * 4, sb2);
        }
    };

    float s_acc0 = 0.f, s_acc1 = 0.f;

    // scores(j) into P[j&1] as fp16x2 pairs (warps 0..7 only)
    auto do_scores = [&](int j) {
        float sc3[3][4];
#pragma unroll
        for (int p = 0; p < 3; p++)
#pragma unroll
            for (int q = 0; q < 4; q++) sc3[p][q] = 0.f;
        int krow = (kg * 8 + gid) * 40 + 2 * tig;
        int arow2 = rowa * 40 + 2 * tig;
        const uint32_t* KHb = usm + OFF_KH + (j & 3) * KH_STG;
        const uint32_t* KLb = usm + OFF_KL + (j & 3) * KH_STG;
#pragma unroll
        for (int ks = 0; ks < 4; ks++) {
#pragma unroll
            for (int p = 0; p < 3; p++) {
                const uint32_t* Ab = usm + (p == 2 ? OFF_QL : OFF_QH);
                const uint32_t* Bb = (p == 1) ? KLb : KHb;
                uint2 qa = *(const uint2*)(Ab + arow2 + ks * 8);
                uint2 qb = *(const uint2*)(Ab + arow2 + ks * 8 + 8 * 40);
                uint2 kb = *(const uint2*)(Bb + krow + ks * 8);
                mma_bf16(sc3[p], qa.x, qb.x, qa.y, qb.y, kb.x, kb.y);
            }
        }
        float s0 = sc3[0][0] + sc3[1][0] + sc3[2][0];
        float s1 = sc3[0][1] + sc3[1][1] + sc3[2][1];
        float s2 = sc3[0][2] + sc3[1][2] + sc3[2][2];
        float s3 = sc3[0][3] + sc3[1][3] + sc3[2][3];

        int colg = j * TK + kg * 8 + tig * 2;
        float p00 = __expf(s0 * 0.125f);
        float p01 = __expf(s1 * 0.125f);
        float p10 = __expf(s2 * 0.125f);
        float p11 = __expf(s3 * 0.125f);
        if (j >= njt - 4) {
            if (colg     > r0 + rowa)     p00 = 0.f;
            if (colg + 1 > r0 + rowa)     p01 = 0.f;
            if (colg     > r0 + rowa + 8) p10 = 0.f;
            if (colg + 1 > r0 + rowa + 8) p11 = 0.f;
        }
        uint32_t w0 = packf16(p00, p01);
        uint32_t w1 = packf16(p10, p11);
        uint32_t* Pr = usm + OFF_P + (j & 1) * P_STG + rowa * 40 + tig * 2 + kg;
        Pr[0] = w0;
        Pr[8 * 40] = w1;
        float2 f0 = __half22float2(*(__half2*)&w0);
        float2 f1 = __half22float2(*(__half2*)&w1);
        s_acc0 += f0.x + f0.y;
        s_acc1 += f1.x + f1.y;
    };

    // prologue
    {
        const uint32_t* qhh = qbh + ((long)h * T_SEQ + r0) * 32;
        const uint32_t* qhl = qbl + ((long)h * T_SEQ + r0) * 32;
#pragma unroll
        for (int i = 0; i < 2; i++) {
            int idx = tid + i * 512;
            int arr = idx >> 9, rr = (idx >> 3) & 63, ch = (idx & 7) * 4;
            const uint32_t* src = (arr ? qhl : qhh) + (long)rr * 32 + ch;
            CP16(sbase + ((arr ? OFF_QL : OFF_QH) + rr * 40 + ch) * 4, src);
        }
        issue_tile(0);
        CP_COMMIT();
        issue_tile(1);
        CP_COMMIT();
        asm volatile("cp.async.wait_group 1;" ::: "memory");
        __syncthreads();
        if (wid < 8) do_scores(0);
    }

    float zacc[4][4][4];
#pragma unroll
    for (int i = 0; i < 4; i++)
#pragma unroll
        for (int j = 0; j < 4; j++)
#pragma unroll
            for (int q = 0; q < 4; q++) zacc[i][j][q] = 0.f;

    for (int jt = 0; jt < njt; jt++) {
        if (jt + 2 < njt) {
            issue_tile(jt + 2);
            CP_COMMIT();
            asm volatile("cp.async.wait_group 1;" ::: "memory");
        } else {
            asm volatile("cp.async.wait_group 0;" ::: "memory");
        }
        __syncthreads();

        if (wid < 8 && jt + 1 < njt) do_scores(jt + 1);

        // Z(jt) += P @ KV  (fp16 m16n8k16, one K-step covers the 16-key tile)
        {
            const uint32_t* KVs = usm + OFF_KV + (jt & 3) * KV_STG;
            const uint32_t* Pb = usm + OFF_P + (jt & 1) * P_STG;
            uint2 pa[4][2];
#pragma unroll
            for (int mt = 0; mt < 4; mt++) {
                const uint32_t* Pr = Pb + (mt * 16 + gid) * 40 + 2 * tig;
                pa[mt][0] = *(const uint2*)Pr;
                pa[mt][1] = *(const uint2*)(Pr + 8 * 40);
            }
#pragma unroll
            for (int nt = 0; nt < 4; nt++) {
                int c = wid * 32 + nt * 8 + gid;
                uint2 bb = *(const uint2*)(KVs + c * 8 + 2 * tig);
#pragma unroll
                for (int mt = 0; mt < 4; mt++)
                    mma_f16(zacc[mt][nt], pa[mt][0].x, pa[mt][1].x,
                            pa[mt][0].y, pa[mt][1].y, bb.x, bb.y);
            }
        }
    }
    __syncthreads();

    // ---- S reduce ----
    s_acc0 += __shfl_xor_sync(~0u, s_acc0, 1);
    s_acc0 += __shfl_xor_sync(~0u, s_acc0, 2);
    s_acc1 += __shfl_xor_sync(~0u, s_acc1, 1);
    s_acc1 += __shfl_xor_sync(~0u, s_acc1, 2);
    if (wid < 8 && tig == 0) {
        fsm[OFF_S + kg * 64 + rowa] = s_acc0;
        fsm[OFF_S + kg * 64 + rowa + 8] = s_acc1;
    }
    // ---- Z regs -> smem overlay (whole pipeline region dead), stride 520 ----
#pragma unroll
    for (int mt = 0; mt < 4; mt++) {
        int row = mt * 16 + gid;
#pragma unroll
        for (int nt = 0; nt < 4; nt++) {
            float* zp = fsm + row * 520 + wid * 32 + (wid >> 1) + nt * 8 + tig * 2;
            zp[0] = zacc[mt][nt][0];
            zp[1] = zacc[mt][nt][1];
            zp[8 * 520] = zacc[mt][nt][2];
            zp[8 * 520 + 1] = zacc[mt][nt][3];
        }
    }
    __syncthreads();
    if (tid < 64)
        fsm[OFF_S + 128 + tid] = 1.f / (fsm[OFF_S + tid] + fsm[OFF_S + 64 + tid]);
    __syncthreads();

    // ---- octonion epilogue: one (row, m) unit per thread ----
    {
        int row = tid >> 3, m = tid & 7;
        float invS = fsm[OFF_S + 128 + row];
        const float* q = qn + ((long)h * T_SEQ + r0 + row) * HD + m * 8;
        const float* z = fsm + row * 520 + m * 65;

        float q8[8];
        float4 qa = *(const float4*)q, qb = *(const float4*)(q + 4);
        q8[0]=qa.x; q8[1]=qa.y; q8[2]=qa.z; q8[3]=qa.w;
        q8[4]=qb.x; q8[5]=qb.y; q8[6]=qb.z; q8[7]=qb.w;
        float acc[8] = {0,0,0,0,0,0,0,0};
#pragma unroll
        for (int p = 0; p < 8; p++) {
            float e[8] = {0,0,0,0,0,0,0,0};
            e[p] = 1.f;
            float uo[8], z8[8], wv[8];
            omul8(q8, e, uo);
#pragma unroll
            for (int i = 0; i < 8; i++) z8[i] = z[p * 8 + i];
            omul8(uo, z8, wv);
#pragma unroll
            for (int k = 0; k < 8; k++) acc[k] += wv[k];
        }
        float* yo = y + (long)(r0 + row) * CEMB + h * HD + m * 8;
        *(float4*)yo = make_float4(acc[0]*invS, acc[1]*invS, acc[2]*invS, acc[3]*invS);
        *(float4*)(yo + 4) = make_float4(acc[4]*invS, acc[5]*invS, acc[6]*invS, acc[7]*invS);
    }
}

// ---------------- launch -----------------------------------------------------
extern "C" void kernel_launch(void* const* d_in, const int* in_sizes, int n_in,
                              void* d_out, int out_size)
{
    const float* x    = (const float*)d_in[0];
    const float* cosp = (const float*)d_in[1];
    const float* sinp = (const float*)d_in[2];
    const float* Wq   = (const float*)d_in[3];
    const float* Wk   = (const float*)d_in[4];
    const float* Wv   = (const float*)d_in[5];
    const float* Wo   = (const float*)d_in[6];
    float* out = (float*)d_out;

    float *qraw, *kraw, *vraw, *qn, *y;
    uint32_t *kvp16, *qbh, *qbl, *kbh, *kbl;
    cudaGetSymbolAddress((void**)&qraw,  g_qraw);
    cudaGetSymbolAddress((void**)&kraw,  g_kraw);
    cudaGetSymbolAddress((void**)&vraw,  g_vraw);
    cudaGetSymbolAddress((void**)&qn,    g_qn);
    cudaGetSymbolAddress((void**)&kvp16, g_kvp16);
    cudaGetSymbolAddress((void**)&qbh,   g_qbh);
    cudaGetSymbolAddress((void**)&qbl,   g_qbl);
    cudaGetSymbolAddress((void**)&kbh,   g_kbh);
    cudaGetSymbolAddress((void**)&kbl,   g_kbl);
    cudaGetSymbolAddress((void**)&y,     g_y);

    const int smem_gemm = 2 * GSTAGE * 4;
    cudaFuncSetAttribute(qkv_gemm, cudaFuncAttributeMaxDynamicSharedMemorySize, smem_gemm);
    cudaFuncSetAttribute(wo_gemm,  cudaFuncAttributeMaxDynamicSharedMemorySize, smem_gemm);
    cudaFuncSetAttribute(fused_attn, cudaFuncAttributeMaxDynamicSharedMemorySize, FA_SMEM);

    qkv_gemm<<<dim3(CEMB / 64, T_SEQ / 128, 3), 256, smem_gemm>>>(
        x, Wq, Wk, Wv, qraw, kraw, vraw);

    prep_kernel<<<dim3(NH, T_SEQ / 8), 512>>>(qraw, kraw, vraw, cosp, sinp,
                                              qn, kvp16, qbh, qbl, kbh, kbl);

    fused_attn<<<dim3(32, NH), 512, FA_SMEM>>>(qn, qbh, qbl, kbh, kbl, kvp16, y);

    wo_gemm<<<dim3(CEMB / 64, T_SEQ / 128), 256, smem_gemm>>>(y, Wo, out);
}

// round 13
// speedup vs baseline: 1.5104x; 1.1702x over previous
#include <cuda_runtime.h>
#include <cuda_fp16.h>
#include <cstdint>
#include <math.h>

#define T_SEQ 2048
#define NH 16
#define HD 64
#define CEMB 1024
#define KVW 512

// ---------------- scratch (device globals) ----------------------------------
static __device__ float g_qraw[T_SEQ * CEMB];
static __device__ float g_kraw[T_SEQ * CEMB];
static __device__ float g_vraw[T_SEQ * CEMB];
static __device__ float g_qn[NH * T_SEQ * HD];
static __device__ uint32_t g_kvp16[NH * T_SEQ * KVW / 2]; // fp16x2 paired
static __device__ uint32_t g_qf[NH * T_SEQ * 32];         // q fp16x2 (permuted words)
static __device__ uint32_t g_kf[NH * T_SEQ * 32];         // k fp16x2 (permuted words)
static __device__ float g_y[T_SEQ * CEMB];

// ---------------- helpers ----------------------------------------------------
static __device__ __forceinline__ uint32_t smem_u32(const void* p) {
    uint32_t a;
    asm("{ .reg .u64 t; cvta.to.shared.u64 t, %1; cvt.u32.u64 %0, t; }" : "=r"(a) : "l"(p));
    return a;
}
static __device__ __forceinline__ void mma_f16(
    float* acc, uint32_t a0, uint32_t a1, uint32_t a2, uint32_t a3,
    uint32_t b0, uint32_t b1)
{
    asm volatile(
        "mma.sync.aligned.m16n8k16.row.col.f32.f16.f16.f32 "
        "{%0,%1,%2,%3},{%4,%5,%6,%7},{%8,%9},{%0,%1,%2,%3};"
        : "+f"(acc[0]), "+f"(acc[1]), "+f"(acc[2]), "+f"(acc[3])
        : "r"(a0), "r"(a1), "r"(a2), "r"(a3), "r"(b0), "r"(b1));
}
static __device__ __forceinline__ uint32_t packf16(float lo, float hi) {
    uint32_t w;
    asm("cvt.rn.f16x2.f32 %0, %1, %2;" : "=r"(w) : "f"(hi), "f"(lo));
    return w;
}
// fp16 hi + residual-lo pair
static __device__ __forceinline__ uint2 pack_split_f16(float f0, float f1) {
    uint32_t h = packf16(f0, f1);
    float2 hf = __half22float2(*(__half2*)&h);
    uint32_t l = packf16(f0 - hf.x, f1 - hf.y);
    return make_uint2(h, l);
}
#define CP16(dst_u32, src_ptr) \
    asm volatile("cp.async.cg.shared.global [%0], [%1], 16;" \
                 :: "r"(dst_u32), "l"(src_ptr) : "memory")
#define CP_COMMIT() asm volatile("cp.async.commit_group;" ::: "memory")

static __device__ __forceinline__ int permw(int d) {
    return (d & ~7) + ((d & 3) * 2 + ((d & 7) >> 2));
}

// ================= fp16 2-pass GEMM (NT), 128x64 tiles =======================
// C = A@B^T with A split hi+lo (fp16), B hi only: error ~ B rounding (1e-4 rel)
#define BSTR 12
#define GA_HI 0
#define GA_LO (128 * BSTR)
#define GB_HI (256 * BSTR)
#define GSTAGE (320 * BSTR)     // 3840 words per stage

static __device__ __forceinline__ void f16_nt_body(
    const float* __restrict__ A, const float* __restrict__ B, float* __restrict__ C,
    int K, int lda, int ldb, int ldc, int m0, int n0)
{
    extern __shared__ uint32_t smu[];
    int nch = K >> 4;

    int tid = threadIdx.x;
    int lane = tid & 31, wid = tid >> 5;
    int gid = lane >> 2, tig = lane & 3;
    int warp_m = wid & 3, warp_n = wid >> 2;
    int arow = tid >> 1, akc = (tid & 1) * 8;
    int brow = tid >> 2, bkc = (tid & 3) * 4;

    float acc[2][4][4];
#pragma unroll
    for (int i = 0; i < 2; i++)
#pragma unroll
        for (int j = 0; j < 4; j++)
#pragma unroll
            for (int q = 0; q < 4; q++) acc[i][j][q] = 0.f;

    float4 ra0, ra1, rb0;
    auto LOADG = [&](int k0) {
        const float* ap = A + (long)(m0 + arow) * lda + k0 + akc;
        ra0 = *(const float4*)ap;
        ra1 = *(const float4*)(ap + 4);
        rb0 = *(const float4*)(B + (long)(n0 + brow) * ldb + k0 + bkc);
    };
    auto STORES = [&](int sb) {
        int ao = arow * BSTR + (akc >> 1);
        uint2 p0 = pack_split_f16(ra0.x, ra0.y), p1 = pack_split_f16(ra0.z, ra0.w);
        uint2 p2 = pack_split_f16(ra1.x, ra1.y), p3 = pack_split_f16(ra1.z, ra1.w);
        *(uint4*)(smu + sb + GA_HI + ao) = make_uint4(p0.x, p1.x, p2.x, p3.x);
        *(uint4*)(smu + sb + GA_LO + ao) = make_uint4(p0.y, p1.y, p2.y, p3.y);
        int bo = brow * BSTR + (bkc >> 1);
        *(uint2*)(smu + sb + GB_HI + bo) =
            make_uint2(packf16(rb0.x, rb0.y), packf16(rb0.z, rb0.w));
    };

    LOADG(0);
    STORES(0);
    __syncthreads();

    for (int ch = 0; ch < nch; ch++) {
        if (ch + 1 < nch) LOADG((ch + 1) << 4);
        int sb = (ch & 1) * GSTAGE;
#pragma unroll
        for (int p = 0; p < 2; p++) {
            const uint32_t* Abase = smu + sb + (p == 1 ? GA_LO : GA_HI);
            const uint32_t* Bbase = smu + sb + GB_HI;
            uint32_t af[2][4];
#pragma unroll
            for (int mt = 0; mt < 2; mt++) {
                int r = (warp_m * 32 + mt * 16 + gid) * BSTR + tig;
                af[mt][0] = Abase[r];
                af[mt][1] = Abase[r + 8 * BSTR];
                af[mt][2] = Abase[r + 4];
                af[mt][3] = Abase[r + 8 * BSTR + 4];
            }
            uint32_t bfr[4][2];
#pragma unroll
            for (int nt = 0; nt < 4; nt++) {
                int c = (warp_n * 32 + nt * 8 + gid) * BSTR + tig;
                bfr[nt][0] = Bbase[c];
                bfr[nt][1] = Bbase[c + 4];
            }
#pragma unroll
            for (int mt = 0; mt < 2; mt++)
#pragma unroll
                for (int nt = 0; nt < 4; nt++)
                    mma_f16(acc[mt][nt], af[mt][0], af[mt][1], af[mt][2],
                            af[mt][3], bfr[nt][0], bfr[nt][1]);
        }
        if (ch + 1 < nch) {
            __syncthreads();
            STORES(((ch + 1) & 1) * GSTAGE);
            __syncthreads();
        }
    }

#pragma unroll
    for (int mt = 0; mt < 2; mt++) {
        int r0 = m0 + warp_m * 32 + mt * 16 + gid;
#pragma unroll
        for (int nt = 0; nt < 4; nt++) {
            int c = n0 + warp_n * 32 + nt * 8 + tig * 2;
            *(float2*)(C + (long)r0 * ldc + c) =
                make_float2(acc[mt][nt][0], acc[mt][nt][1]);
            *(float2*)(C + (long)(r0 + 8) * ldc + c) =
                make_float2(acc[mt][nt][2], acc[mt][nt][3]);
        }
    }
}

__global__ void __launch_bounds__(256, 3) qkv_gemm(
    const float* __restrict__ x,
    const float* __restrict__ Wq, const float* __restrict__ Wk,
    const float* __restrict__ Wv,
    float* q, float* k, float* v)
{
    const float* B = blockIdx.z == 0 ? Wq : blockIdx.z == 1 ? Wk : Wv;
    float* C = blockIdx.z == 0 ? q : blockIdx.z == 1 ? k : v;
    f16_nt_body(x, B, C, CEMB, CEMB, CEMB, CEMB,
                blockIdx.y * 128, blockIdx.x * 64);
}

__global__ void __launch_bounds__(256, 3) wo_gemm(
    const float* __restrict__ y, const float* __restrict__ Wo, float* out)
{
    f16_nt_body(y, Wo, out, CEMB, CEMB, CEMB, CEMB,
                blockIdx.y * 128, blockIdx.x * 64);
}

// ---------------- prep: fp16 paired KV + fp16 q/k packing --------------------
__global__ __launch_bounds__(512) void prep_kernel(
    const float* __restrict__ qraw, const float* __restrict__ kraw,
    const float* __restrict__ vraw,
    const float* __restrict__ cosp, const float* __restrict__ sinp,
    float* __restrict__ qn, uint32_t* __restrict__ kvp16,
    uint32_t* __restrict__ qf, uint32_t* __restrict__ kf)
{
    int h = blockIdx.x, g = blockIdx.y;
    int tid = threadIdx.x;
    int w = tid >> 6, d = tid & 63;
    int t = g * 8 + w;

    __shared__ float r1[8][64], r2[8][64], skc[8][64], sv[8][64];
    __shared__ float sq[8][64], sk[8][64];
    __shared__ float kvstage[8][512];

    long base = (long)t * CEMB + h * HD;
    int j = d & 31;
    float c = cosp[t * 32 + j], s = sinp[t * 32 + j];

    float x1q = qraw[base + j], x2q = qraw[base + j + 32];
    float qv = (d < 32) ? (x1q * c + x2q * s) : (x2q * c - x1q * s);
    float x1k = kraw[base + j], x2k = kraw[base + j + 32];
    float kvv = (d < 32) ? (x1k * c + x2k * s) : (x2k * c - x1k * s);

    r1[w][d] = qv * qv;
    r2[w][d] = kvv * kvv;
    __syncthreads();
#pragma unroll
    for (int off = 32; off > 0; off >>= 1) {
        if (d < off) { r1[w][d] += r1[w][d + off]; r2[w][d] += r2[w][d + off]; }
        __syncthreads();
    }
    float rq = rsqrtf(r1[w][0] * (1.f / 64.f) + 1e-6f);
    float rk = rsqrtf(r2[w][0] * (1.f / 64.f) + 1e-6f);
    float qno = qv * rq, kno = kvv * rk;

    qn[((long)h * T_SEQ + t) * HD + d] = qno;
    sq[w][d] = qno;
    sk[w][d] = kno;

    float o = kno * kno;
    o += __shfl_xor_sync(0xffffffffu, o, 1);
    o += __shfl_xor_sync(0xffffffffu, o, 2);
    o += __shfl_xor_sync(0xffffffffu, o, 4);
    float ko = kno / fmaxf(sqrtf(o), 1e-12f);
    skc[w][d] = ((d & 7) == 0) ? ko : -ko;
    sv[w][d] = vraw[base + d];
    __syncthreads();

    {
        float kc = skc[w][d];
        int mb = d & ~7;
#pragma unroll
        for (int i = 0; i < 8; i++)
            kvstage[w][d * 8 + i] = kc * sv[w][mb + i];
    }
    {
        long pbase = ((long)h * T_SEQ + t) * 32;
        if (d < 32) {
            qf[pbase + permw(d)] = packf16(sq[w][2 * d], sq[w][2 * d + 1]);
        } else {
            int d2 = d - 32;
            kf[pbase + permw(d2)] = packf16(sk[w][2 * d2], sk[w][2 * d2 + 1]);
        }
    }
    __syncthreads();

    uint32_t* outb = kvp16 + ((long)(h * 128 + (g >> 1)) * 512) * 8 + (g & 1);
#pragma unroll
    for (int it = 0; it < 4; it++) {
        int idx = tid + it * 512;
        int cc = idx >> 2, pl = idx & 3;
        outb[cc * 8 + pl * 2] = packf16(kvstage[2 * pl][cc], kvstage[2 * pl + 1][cc]);
    }
}

// ---------------- octonion math ----------------------------------------------
__device__ __forceinline__ void qmul4(const float* q1, const float* q2, float* r)
{
    r[0] = q1[0]*q2[0] - q1[1]*q2[1] - q1[2]*q2[2] - q1[3]*q2[3];
    r[1] = q1[0]*q2[1] + q1[1]*q2[0] + q1[2]*q2[3] - q1[3]*q2[2];
    r[2] = q1[0]*q2[2] - q1[1]*q2[3] + q1[2]*q2[0] + q1[3]*q2[1];
    r[3] = q1[0]*q2[3] + q1[1]*q2[2] - q1[2]*q2[1] + q1[3]*q2[0];
}
__device__ __forceinline__ void omul8(const float* o1, const float* o2, float* r)
{
    const float* a = o1; const float* b = o1 + 4;
    const float* c = o2; const float* d = o2 + 4;
    float dc[4] = { d[0], -d[1], -d[2], -d[3] };
    float cc[4] = { c[0], -c[1], -c[2], -c[3] };
    float t1[4], t2[4];
    qmul4(a, c, t1); qmul4(dc, b, t2);
    r[0] = t1[0] - t2[0]; r[1] = t1[1] - t2[1];
    r[2] = t1[2] - t2[2]; r[3] = t1[3] - t2[3];
    qmul4(d, a, t1); qmul4(b, cc, t2);
    r[4] = t1[0] + t2[0]; r[5] = t1[1] + t2[1];
    r[6] = t1[2] + t2[2]; r[7] = t1[3] + t2[3];
}

// ===== fused attention: pipelined, fp16 scores (1-pass) + fp16 Z =============
#define TK 16
#define OFF_KV 0
#define KV_STG 4096             // 4 stages
#define OFF_KH 16384            // 4 stages x 16x40
#define KH_STG 640
#define OFF_P  18944            // 2 stages x 64x40
#define P_STG  2560
#define OFF_QF 24064            // 64 x 40
#define OFF_S  33280            // after epilogue Z overlay (64*520)
#define FA_SMEM ((OFF_S + 192) * 4)

__global__ void __launch_bounds__(512, 1) fused_attn(
    const float* __restrict__ qn,
    const uint32_t* __restrict__ qf, const uint32_t* __restrict__ kf,
    const uint32_t* __restrict__ kvp16, float* __restrict__ y)
{
    extern __shared__ __align__(16) float fsm[];
    uint32_t* usm = (uint32_t*)fsm;
    uint32_t sbase = smem_u32(fsm);

    int qt = 31 - blockIdx.x;
    int h = blockIdx.y;
    int r0 = qt * 64;
    int njt = 4 * (qt + 1);

    int tid = threadIdx.x, lane = tid & 31, wid = tid >> 5;
    int gid = lane >> 2, tig = lane & 3;
    int rg = wid & 3, kg = wid >> 2;
    int rowa = rg * 16 + gid;

    const uint32_t* kvph = kvp16 + (long)h * 128 * 4096;
    const uint32_t* kfh = kf + (long)h * T_SEQ * 32;

    auto issue_tile = [&](int t) {
        const uint32_t* src = kvph + (long)t * 4096;
        uint32_t dstw = OFF_KV + (t & 3) * KV_STG;
#pragma unroll
        for (int i = 0; i < 2; i++) {
            int idx = tid + i * 512;
            CP16(sbase + (dstw + idx * 4) * 4, src + idx * 4);
        }
        if (tid < 128) {
            int rr = tid >> 3, ch = (tid & 7) * 4;
            const uint32_t* sb2 = kfh + (long)(t * TK + rr) * 32 + ch;
            CP16(sbase + (OFF_KH + (t & 3) * KH_STG + rr * 40 + ch) * 4, sb2);
        }
    };

    float s_acc0 = 0.f, s_acc1 = 0.f;

    // scores(j) into P[j&1] as fp16x2 pairs (warps 0..7), 1-pass fp16
    auto do_scores = [&](int j) {
        float sc2[2][4];
#pragma unroll
        for (int p = 0; p < 2; p++)
#pragma unroll
            for (int q = 0; q < 4; q++) sc2[p][q] = 0.f;
        int krow = (kg * 8 + gid) * 40 + 2 * tig;
        int arow2 = rowa * 40 + 2 * tig;
        const uint32_t* KHb = usm + OFF_KH + (j & 3) * KH_STG;
#pragma unroll
        for (int ks = 0; ks < 4; ks++) {
            const uint32_t* Ab = usm + OFF_QF;
            uint2 qa = *(const uint2*)(Ab + arow2 + ks * 8);
            uint2 qb = *(const uint2*)(Ab + arow2 + ks * 8 + 8 * 40);
            uint2 kb = *(const uint2*)(KHb + krow + ks * 8);
            mma_f16(sc2[ks & 1], qa.x, qb.x, qa.y, qb.y, kb.x, kb.y);
        }
        float s0 = sc2[0][0] + sc2[1][0];
        float s1 = sc2[0][1] + sc2[1][1];
        float s2 = sc2[0][2] + sc2[1][2];
        float s3 = sc2[0][3] + sc2[1][3];

        int colg = j * TK + kg * 8 + tig * 2;
        float p00 = __expf(s0 * 0.125f);
        float p01 = __expf(s1 * 0.125f);
        float p10 = __expf(s2 * 0.125f);
        float p11 = __expf(s3 * 0.125f);
        if (j >= njt - 4) {
            if (colg     > r0 + rowa)     p00 = 0.f;
            if (colg + 1 > r0 + rowa)     p01 = 0.f;
            if (colg     > r0 + rowa + 8) p10 = 0.f;
            if (colg + 1 > r0 + rowa + 8) p11 = 0.f;
        }
        uint32_t w0 = packf16(p00, p01);
        uint32_t w1 = packf16(p10, p11);
        uint32_t* Pr = usm + OFF_P + (j & 1) * P_STG + rowa * 40 + tig * 2 + kg;
        Pr[0] = w0;
        Pr[8 * 40] = w1;
        float2 f0 = __half22float2(*(__half2*)&w0);
        float2 f1 = __half22float2(*(__half2*)&w1);
        s_acc0 += f0.x + f0.y;
        s_acc1 += f1.x + f1.y;
    };

    // prologue
    {
        const uint32_t* qhh = qf + ((long)h * T_SEQ + r0) * 32;
        {
            int rr = tid >> 3, ch = (tid & 7) * 4;
            CP16(sbase + (OFF_QF + rr * 40 + ch) * 4, qhh + (long)rr * 32 + ch);
        }
        issue_tile(0);
        CP_COMMIT();
        issue_tile(1);
        CP_COMMIT();
        asm volatile("cp.async.wait_group 1;" ::: "memory");
        __syncthreads();
        if (wid < 8) do_scores(0);
    }

    float zacc[4][4][4];
#pragma unroll
    for (int i = 0; i < 4; i++)
#pragma unroll
        for (int j = 0; j < 4; j++)
#pragma unroll
            for (int q = 0; q < 4; q++) zacc[i][j][q] = 0.f;

    for (int jt = 0; jt < njt; jt++) {
        if (jt + 2 < njt) {
            issue_tile(jt + 2);
            CP_COMMIT();
            asm volatile("cp.async.wait_group 1;" ::: "memory");
        } else {
            asm volatile("cp.async.wait_group 0;" ::: "memory");
        }
        __syncthreads();

        if (wid < 8 && jt + 1 < njt) do_scores(jt + 1);

        // Z(jt) += P @ KV  (fp16 m16n8k16)
        {
            const uint32_t* KVs = usm + OFF_KV + (jt & 3) * KV_STG;
            const uint32_t* Pb = usm + OFF_P + (jt & 1) * P_STG;
            uint2 pa[4][2];
#pragma unroll
            for (int mt = 0; mt < 4; mt++) {
                const uint32_t* Pr = Pb + (mt * 16 + gid) * 40 + 2 * tig;
                pa[mt][0] = *(const uint2*)Pr;
                pa[mt][1] = *(const uint2*)(Pr + 8 * 40);
            }
#pragma unroll
            for (int nt = 0; nt < 4; nt++) {
                int c = wid * 32 + nt * 8 + gid;
                uint2 bb = *(const uint2*)(KVs + c * 8 + 2 * tig);
#pragma unroll
                for (int mt = 0; mt < 4; mt++)
                    mma_f16(zacc[mt][nt], pa[mt][0].x, pa[mt][1].x,
                            pa[mt][0].y, pa[mt][1].y, bb.x, bb.y);
            }
        }
    }
    __syncthreads();

    // ---- S reduce ----
    s_acc0 += __shfl_xor_sync(~0u, s_acc0, 1);
    s_acc0 += __shfl_xor_sync(~0u, s_acc0, 2);
    s_acc1 += __shfl_xor_sync(~0u, s_acc1, 1);
    s_acc1 += __shfl_xor_sync(~0u, s_acc1, 2);
    if (wid < 8 && tig == 0) {
        fsm[OFF_S + kg * 64 + rowa] = s_acc0;
        fsm[OFF_S + kg * 64 + rowa + 8] = s_acc1;
    }
    // ---- Z regs -> smem overlay, stride 520 ----
#pragma unroll
    for (int mt = 0; mt < 4; mt++) {
        int row = mt * 16 + gid;
#pragma unroll
        for (int nt = 0; nt < 4; nt++) {
            float* zp = fsm + row * 520 + wid * 32 + (wid >> 1) + nt * 8 + tig * 2;
            zp[0] = zacc[mt][nt][0];
            zp[1] = zacc[mt][nt][1];
            zp[8 * 520] = zacc[mt][nt][2];
            zp[8 * 520 + 1] = zacc[mt][nt][3];
        }
    }
    __syncthreads();
    if (tid < 64)
        fsm[OFF_S + 128 + tid] = 1.f / (fsm[OFF_S + tid] + fsm[OFF_S + 64 + tid]);
    __syncthreads();

    // ---- octonion epilogue ----
    {
        int row = tid >> 3, m = tid & 7;
        float invS = fsm[OFF_S + 128 + row];
        const float* q = qn + ((long)h * T_SEQ + r0 + row) * HD + m * 8;
        const float* z = fsm + row * 520 + m * 65;

        float q8[8];
        float4 qa = *(const float4*)q, qb = *(const float4*)(q + 4);
        q8[0]=qa.x; q8[1]=qa.y; q8[2]=qa.z; q8[3]=qa.w;
        q8[4]=qb.x; q8[5]=qb.y; q8[6]=qb.z; q8[7]=qb.w;
        float acc[8] = {0,0,0,0,0,0,0,0};
#pragma unroll
        for (int p = 0; p < 8; p++) {
            float e[8] = {0,0,0,0,0,0,0,0};
            e[p] = 1.f;
            float uo[8], z8[8], wv[8];
            omul8(q8, e, uo);
#pragma unroll
            for (int i = 0; i < 8; i++) z8[i] = z[p * 8 + i];
            omul8(uo, z8, wv);
#pragma unroll
            for (int k = 0; k < 8; k++) acc[k] += wv[k];
        }
        float* yo = y + (long)(r0 + row) * CEMB + h * HD + m * 8;
        *(float4*)yo = make_float4(acc[0]*invS, acc[1]*invS, acc[2]*invS, acc[3]*invS);
        *(float4*)(yo + 4) = make_float4(acc[4]*invS, acc[5]*invS, acc[6]*invS, acc[7]*invS);
    }
}

// ---------------- launch -----------------------------------------------------
extern "C" void kernel_launch(void* const* d_in, const int* in_sizes, int n_in,
                              void* d_out, int out_size)
{
    const float* x    = (const float*)d_in[0];
    const float* cosp = (const float*)d_in[1];
    const float* sinp = (const float*)d_in[2];
    const float* Wq   = (const float*)d_in[3];
    const float* Wk   = (const float*)d_in[4];
    const float* Wv   = (const float*)d_in[5];
    const float* Wo   = (const float*)d_in[6];
    float* out = (float*)d_out;

    float *qraw, *kraw, *vraw, *qn, *y;
    uint32_t *kvp16, *qf, *kf;
    cudaGetSymbolAddress((void**)&qraw,  g_qraw);
    cudaGetSymbolAddress((void**)&kraw,  g_kraw);
    cudaGetSymbolAddress((void**)&vraw,  g_vraw);
    cudaGetSymbolAddress((void**)&qn,    g_qn);
    cudaGetSymbolAddress((void**)&kvp16, g_kvp16);
    cudaGetSymbolAddress((void**)&qf,    g_qf);
    cudaGetSymbolAddress((void**)&kf,    g_kf);
    cudaGetSymbolAddress((void**)&y,     g_y);

    const int smem_gemm = 2 * GSTAGE * 4;   // 30720 B
    cudaFuncSetAttribute(qkv_gemm, cudaFuncAttributeMaxDynamicSharedMemorySize, smem_gemm);
    cudaFuncSetAttribute(wo_gemm,  cudaFuncAttributeMaxDynamicSharedMemorySize, smem_gemm);
    cudaFuncSetAttribute(fused_attn, cudaFuncAttributeMaxDynamicSharedMemorySize, FA_SMEM);

    qkv_gemm<<<dim3(CEMB / 64, T_SEQ / 128, 3), 256, smem_gemm>>>(
        x, Wq, Wk, Wv, qraw, kraw, vraw);

    prep_kernel<<<dim3(NH, T_SEQ / 8), 512>>>(qraw, kraw, vraw, cosp, sinp,
                                              qn, kvp16, qf, kf);

    fused_attn<<<dim3(32, NH), 512, FA_SMEM>>>(qn, qf, kf, kvp16, y);

    wo_gemm<<<dim3(CEMB / 64, T_SEQ / 128), 256, smem_gemm>>>(y, Wo, out);
}

// round 15
// speedup vs baseline: 1.5189x; 1.0056x over previous
#include <cuda_runtime.h>
#include <cuda_fp16.h>
#include <cstdint>
#include <math.h>

#define T_SEQ 2048
#define NH 16
#define HD 64
#define CEMB 1024
#define KVW 512

// ---------------- scratch (device globals) ----------------------------------
static __device__ float g_qraw[T_SEQ * CEMB];
static __device__ float g_kraw[T_SEQ * CEMB];
static __device__ float g_vraw[T_SEQ * CEMB];
static __device__ float g_qn[NH * T_SEQ * HD];
static __device__ uint32_t g_kvp16[NH * T_SEQ * KVW / 2]; // fp16x2 paired
static __device__ uint32_t g_qf[NH * T_SEQ * 32];         // q fp16x2 (permuted words)
static __device__ uint32_t g_kf[NH * T_SEQ * 32];         // k fp16x2 (permuted words)
static __device__ float g_y[T_SEQ * CEMB];

// ---------------- helpers ----------------------------------------------------
static __device__ __forceinline__ uint32_t smem_u32(const void* p) {
    uint32_t a;
    asm("{ .reg .u64 t; cvta.to.shared.u64 t, %1; cvt.u32.u64 %0, t; }" : "=r"(a) : "l"(p));
    return a;
}
static __device__ __forceinline__ void mma_f16(
    float* acc, uint32_t a0, uint32_t a1, uint32_t a2, uint32_t a3,
    uint32_t b0, uint32_t b1)
{
    asm volatile(
        "mma.sync.aligned.m16n8k16.row.col.f32.f16.f16.f32 "
        "{%0,%1,%2,%3},{%4,%5,%6,%7},{%8,%9},{%0,%1,%2,%3};"
        : "+f"(acc[0]), "+f"(acc[1]), "+f"(acc[2]), "+f"(acc[3])
        : "r"(a0), "r"(a1), "r"(a2), "r"(a3), "r"(b0), "r"(b1));
}
static __device__ __forceinline__ uint32_t packf16(float lo, float hi) {
    uint32_t w;
    asm("cvt.rn.f16x2.f32 %0, %1, %2;" : "=r"(w) : "f"(hi), "f"(lo));
    return w;
}
static __device__ __forceinline__ uint2 pack_split_f16(float f0, float f1) {
    uint32_t h = packf16(f0, f1);
    float2 hf = __half22float2(*(__half2*)&h);
    uint32_t l = packf16(f0 - hf.x, f1 - hf.y);
    return make_uint2(h, l);
}
#define CP16(dst_u32, src_ptr) \
    asm volatile("cp.async.cg.shared.global [%0], [%1], 16;" \
                 :: "r"(dst_u32), "l"(src_ptr) : "memory")
#define CP_COMMIT() asm volatile("cp.async.commit_group;" ::: "memory")

static __device__ __forceinline__ int permw(int d) {
    return (d & ~7) + ((d & 3) * 2 + ((d & 7) >> 2));
}

// ================= fp16 2-pass GEMM (NT), 128x64 tiles (unchanged) ===========
#define BSTR 12
#define GA_HI 0
#define GA_LO (128 * BSTR)
#define GB_HI (256 * BSTR)
#define GSTAGE (320 * BSTR)

static __device__ __forceinline__ void f16_nt_body(
    const float* __restrict__ A, const float* __restrict__ B, float* __restrict__ C,
    int K, int lda, int ldb, int ldc, int m0, int n0)
{
    extern __shared__ uint32_t smu[];
    int nch = K >> 4;

    int tid = threadIdx.x;
    int lane = tid & 31, wid = tid >> 5;
    int gid = lane >> 2, tig = lane & 3;
    int warp_m = wid & 3, warp_n = wid >> 2;
    int arow = tid >> 1, akc = (tid & 1) * 8;
    int brow = tid >> 2, bkc = (tid & 3) * 4;

    float acc[2][4][4];
#pragma unroll
    for (int i = 0; i < 2; i++)
#pragma unroll
        for (int j = 0; j < 4; j++)
#pragma unroll
            for (int q = 0; q < 4; q++) acc[i][j][q] = 0.f;

    float4 ra0, ra1, rb0;
    auto LOADG = [&](int k0) {
        const float* ap = A + (long)(m0 + arow) * lda + k0 + akc;
        ra0 = *(const float4*)ap;
        ra1 = *(const float4*)(ap + 4);
        rb0 = *(const float4*)(B + (long)(n0 + brow) * ldb + k0 + bkc);
    };
    auto STORES = [&](int sb) {
        int ao = arow * BSTR + (akc >> 1);
        uint2 p0 = pack_split_f16(ra0.x, ra0.y), p1 = pack_split_f16(ra0.z, ra0.w);
        uint2 p2 = pack_split_f16(ra1.x, ra1.y), p3 = pack_split_f16(ra1.z, ra1.w);
        *(uint4*)(smu + sb + GA_HI + ao) = make_uint4(p0.x, p1.x, p2.x, p3.x);
        *(uint4*)(smu + sb + GA_LO + ao) = make_uint4(p0.y, p1.y, p2.y, p3.y);
        int bo = brow * BSTR + (bkc >> 1);
        *(uint2*)(smu + sb + GB_HI + bo) =
            make_uint2(packf16(rb0.x, rb0.y), packf16(rb0.z, rb0.w));
    };

    LOADG(0);
    STORES(0);
    __syncthreads();

    for (int ch = 0; ch < nch; ch++) {
        if (ch + 1 < nch) LOADG((ch + 1) << 4);
        int sb = (ch & 1) * GSTAGE;
#pragma unroll
        for (int p = 0; p < 2; p++) {
            const uint32_t* Abase = smu + sb + (p == 1 ? GA_LO : GA_HI);
            const uint32_t* Bbase = smu + sb + GB_HI;
            uint32_t af[2][4];
#pragma unroll
            for (int mt = 0; mt < 2; mt++) {
                int r = (warp_m * 32 + mt * 16 + gid) * BSTR + tig;
                af[mt][0] = Abase[r];
                af[mt][1] = Abase[r + 8 * BSTR];
                af[mt][2] = Abase[r + 4];
                af[mt][3] = Abase[r + 8 * BSTR + 4];
            }
            uint32_t bfr[4][2];
#pragma unroll
            for (int nt = 0; nt < 4; nt++) {
                int c = (warp_n * 32 + nt * 8 + gid) * BSTR + tig;
                bfr[nt][0] = Bbase[c];
                bfr[nt][1] = Bbase[c + 4];
            }
#pragma unroll
            for (int mt = 0; mt < 2; mt++)
#pragma unroll
                for (int nt = 0; nt < 4; nt++)
                    mma_f16(acc[mt][nt], af[mt][0], af[mt][1], af[mt][2],
                            af[mt][3], bfr[nt][0], bfr[nt][1]);
        }
        if (ch + 1 < nch) {
            __syncthreads();
            STORES(((ch + 1) & 1) * GSTAGE);
            __syncthreads();
        }
    }

#pragma unroll
    for (int mt = 0; mt < 2; mt++) {
        int r0 = m0 + warp_m * 32 + mt * 16 + gid;
#pragma unroll
        for (int nt = 0; nt < 4; nt++) {
            int c = n0 + warp_n * 32 + nt * 8 + tig * 2;
            *(float2*)(C + (long)r0 * ldc + c) =
                make_float2(acc[mt][nt][0], acc[mt][nt][1]);
            *(float2*)(C + (long)(r0 + 8) * ldc + c) =
                make_float2(acc[mt][nt][2], acc[mt][nt][3]);
        }
    }
}

__global__ void __launch_bounds__(256, 3) qkv_gemm(
    const float* __restrict__ x,
    const float* __restrict__ Wq, const float* __restrict__ Wk,
    const float* __restrict__ Wv,
    float* q, float* k, float* v)
{
    const float* B = blockIdx.z == 0 ? Wq : blockIdx.z == 1 ? Wk : Wv;
    float* C = blockIdx.z == 0 ? q : blockIdx.z == 1 ? k : v;
    f16_nt_body(x, B, C, CEMB, CEMB, CEMB, CEMB,
                blockIdx.y * 128, blockIdx.x * 64);
}

__global__ void __launch_bounds__(256, 3) wo_gemm(
    const float* __restrict__ y, const float* __restrict__ Wo, float* out)
{
    f16_nt_body(y, Wo, out, CEMB, CEMB, CEMB, CEMB,
                blockIdx.y * 128, blockIdx.x * 64);
}

// ---------------- prep (unchanged) ---------------------------------------------
__global__ __launch_bounds__(512) void prep_kernel(
    const float* __restrict__ qraw, const float* __restrict__ kraw,
    const float* __restrict__ vraw,
    const float* __restrict__ cosp, const float* __restrict__ sinp,
    float* __restrict__ qn, uint32_t* __restrict__ kvp16,
    uint32_t* __restrict__ qf, uint32_t* __restrict__ kf)
{
    int h = blockIdx.x, g = blockIdx.y;
    int tid = threadIdx.x;
    int w = tid >> 6, d = tid & 63;
    int t = g * 8 + w;

    __shared__ float r1[8][64], r2[8][64], skc[8][64], sv[8][64];
    __shared__ float sq[8][64], sk[8][64];
    __shared__ float kvstage[8][512];

    long base = (long)t * CEMB + h * HD;
    int j = d & 31;
    float c = cosp[t * 32 + j], s = sinp[t * 32 + j];

    float x1q = qraw[base + j], x2q = qraw[base + j + 32];
    float qv = (d < 32) ? (x1q * c + x2q * s) : (x2q * c - x1q * s);
    float x1k = kraw[base + j], x2k = kraw[base + j + 32];
    float kvv = (d < 32) ? (x1k * c + x2k * s) : (x2k * c - x1k * s);

    r1[w][d] = qv * qv;
    r2[w][d] = kvv * kvv;
    __syncthreads();
#pragma unroll
    for (int off = 32; off > 0; off >>= 1) {
        if (d < off) { r1[w][d] += r1[w][d + off]; r2[w][d] += r2[w][d + off]; }
        __syncthreads();
    }
    float rq = rsqrtf(r1[w][0] * (1.f / 64.f) + 1e-6f);
    float rk = rsqrtf(r2[w][0] * (1.f / 64.f) + 1e-6f);
    float qno = qv * rq, kno = kvv * rk;

    qn[((long)h * T_SEQ + t) * HD + d] = qno;
    sq[w][d] = qno;
    sk[w][d] = kno;

    float o = kno * kno;
    o += __shfl_xor_sync(0xffffffffu, o, 1);
    o += __shfl_xor_sync(0xffffffffu, o, 2);
    o += __shfl_xor_sync(0xffffffffu, o, 4);
    float ko = kno / fmaxf(sqrtf(o), 1e-12f);
    skc[w][d] = ((d & 7) == 0) ? ko : -ko;
    sv[w][d] = vraw[base + d];
    __syncthreads();

    {
        float kc = skc[w][d];
        int mb = d & ~7;
#pragma unroll
        for (int i = 0; i < 8; i++)
            kvstage[w][d * 8 + i] = kc * sv[w][mb + i];
    }
    {
        long pbase = ((long)h * T_SEQ + t) * 32;
        if (d < 32) {
            qf[pbase + permw(d)] = packf16(sq[w][2 * d], sq[w][2 * d + 1]);
        } else {
            int d2 = d - 32;
            kf[pbase + permw(d2)] = packf16(sk[w][2 * d2], sk[w][2 * d2 + 1]);
        }
    }
    __syncthreads();

    uint32_t* outb = kvp16 + ((long)(h * 128 + (g >> 1)) * 512) * 8 + (g & 1);
#pragma unroll
    for (int it = 0; it < 4; it++) {
        int idx = tid + it * 512;
        int cc = idx >> 2, pl = idx & 3;
        outb[cc * 8 + pl * 2] = packf16(kvstage[2 * pl][cc], kvstage[2 * pl + 1][cc]);
    }
}

// ---------------- octonion math ----------------------------------------------
__device__ __forceinline__ void qmul4(const float* q1, const float* q2, float* r)
{
    r[0] = q1[0]*q2[0] - q1[1]*q2[1] - q1[2]*q2[2] - q1[3]*q2[3];
    r[1] = q1[0]*q2[1] + q1[1]*q2[0] + q1[2]*q2[3] - q1[3]*q2[2];
    r[2] = q1[0]*q2[2] - q1[1]*q2[3] + q1[2]*q2[0] + q1[3]*q2[1];
    r[3] = q1[0]*q2[3] + q1[1]*q2[2] - q1[2]*q2[1] + q1[3]*q2[0];
}
__device__ __forceinline__ void omul8(const float* o1, const float* o2, float* r)
{
    const float* a = o1; const float* b = o1 + 4;
    const float* c = o2; const float* d = o2 + 4;
    float dc[4] = { d[0], -d[1], -d[2], -d[3] };
    float cc[4] = { c[0], -c[1], -c[2], -c[3] };
    float t1[4], t2[4];
    qmul4(a, c, t1); qmul4(dc, b, t2);
    r[0] = t1[0] - t2[0]; r[1] = t1[1] - t2[1];
    r[2] = t1[2] - t2[2]; r[3] = t1[3] - t2[3];
    qmul4(d, a, t1); qmul4(b, cc, t2);
    r[4] = t1[0] + t2[0]; r[5] = t1[1] + t2[1];
    r[6] = t1[2] + t2[2]; r[7] = t1[3] + t2[3];
}

// ===== fused attention: TK=32, 4-stage KV ring (race-free), Q in regs ========
#define TK 32
#define OFF_KV 0
#define KV_STG 8192             // 32 keys * 512c fp16 = 32KB, 4 stages (mod 4)
#define OFF_KH 32768            // 4 stages x 32x40
#define KH_STG 1280
#define OFF_P  37888            // 2 stages x 64x20
#define P_STG  1280
#define OFF_QF 40448            // 64 x 40
#define OFF_S  43008
#define FA_SMEM ((OFF_S + 192) * 4)   // 172800 B

__global__ void __launch_bounds__(512, 1) fused_attn(
    const float* __restrict__ qn,
    const uint32_t* __restrict__ qf, const uint32_t* __restrict__ kf,
    const uint32_t* __restrict__ kvp16, float* __restrict__ y)
{
    extern __shared__ __align__(16) float fsm[];
    uint32_t* usm = (uint32_t*)fsm;
    uint32_t sbase = smem_u32(fsm);

    int qt = 31 - blockIdx.x;
    int h = blockIdx.y;
    int r0 = qt * 64;
    int njt = 2 * (qt + 1);      // 32-key tiles

    int tid = threadIdx.x, lane = tid & 31, wid = tid >> 5;
    int gid = lane >> 2, tig = lane & 3;
    int rg = wid & 3, kw = wid >> 2;    // score warps 0..7: rows rg*16, keys kw*16
    int rowa = rg * 16 + gid;

    const uint32_t* kvph = kvp16 + (long)h * 128 * 4096;
    const uint32_t* kfh = kf + (long)h * T_SEQ * 32;

    auto issue_tile = [&](int t) {
        const uint32_t* src = kvph + (long)t * 8192;
        uint32_t dstw = OFF_KV + (t & 3) * KV_STG;
#pragma unroll
        for (int i = 0; i < 4; i++) {
            int idx = tid + i * 512;
            CP16(sbase + (dstw + idx * 4) * 4, src + idx * 4);
        }
        if (tid < 256) {
            int rr = tid >> 3, ch = (tid & 7) * 4;
            const uint32_t* sb2 = kfh + (long)(t * TK + rr) * 32 + ch;
            CP16(sbase + (OFF_KH + (t & 3) * KH_STG + rr * 40 + ch) * 4, sb2);
        }
    };

    float s_acc0 = 0.f, s_acc1 = 0.f;
    uint32_t qreg[4][4];

    // scores(j) into P[j&1] (warps 0..7), 16 rows x 16 keys per warp
    auto do_scores = [&](int j) {
        const uint32_t* KHb = usm + OFF_KH + (j & 3) * KH_STG;
#pragma unroll
        for (int nt = 0; nt < 2; nt++) {
            float sc2[2][4];
#pragma unroll
            for (int p = 0; p < 2; p++)
#pragma unroll
                for (int q = 0; q < 4; q++) sc2[p][q] = 0.f;
            int krow = (kw * 16 + nt * 8 + gid) * 40 + 2 * tig;
#pragma unroll
            for (int ks = 0; ks < 4; ks++) {
                uint2 kb = *(const uint2*)(KHb + krow + ks * 8);
                mma_f16(sc2[ks & 1], qreg[ks][0], qreg[ks][1],
                        qreg[ks][2], qreg[ks][3], kb.x, kb.y);
            }
            float s0 = sc2[0][0] + sc2[1][0];
            float s1 = sc2[0][1] + sc2[1][1];
            float s2 = sc2[0][2] + sc2[1][2];
            float s3 = sc2[0][3] + sc2[1][3];

            int colg = j * TK + kw * 16 + nt * 8 + tig * 2;
            float p00 = __expf(s0 * 0.125f);
            float p01 = __expf(s1 * 0.125f);
            float p10 = __expf(s2 * 0.125f);
            float p11 = __expf(s3 * 0.125f);
            if (j >= njt - 2) {
                if (colg     > r0 + rowa)     p00 = 0.f;
                if (colg + 1 > r0 + rowa)     p01 = 0.f;
                if (colg     > r0 + rowa + 8) p10 = 0.f;
                if (colg + 1 > r0 + rowa + 8) p11 = 0.f;
            }
            uint32_t w0 = packf16(p00, p01);
            uint32_t w1 = packf16(p10, p11);
            uint32_t* Pr = usm + OFF_P + (j & 1) * P_STG + rowa * 20 +
                           kw * 8 + tig * 2 + nt;
            Pr[0] = w0;
            Pr[8 * 20] = w1;
            float2 f0 = __half22float2(*(__half2*)&w0);
            float2 f1 = __half22float2(*(__half2*)&w1);
            s_acc0 += f0.x + f0.y;
            s_acc1 += f1.x + f1.y;
        }
    };

    // prologue: Q + tile0 (group A), tile1 (group B); Q regs; scores(0)
    {
        const uint32_t* qhh = qf + ((long)h * T_SEQ + r0) * 32;
        {
            int rr = tid >> 3, ch = (tid & 7) * 4;
            CP16(sbase + (OFF_QF + rr * 40 + ch) * 4, qhh + (long)rr * 32 + ch);
        }
        issue_tile(0);
        CP_COMMIT();
        issue_tile(1);
        CP_COMMIT();
        asm volatile("cp.async.wait_group 1;" ::: "memory");
        __syncthreads();
        if (wid < 8) {
            int arow2 = rowa * 40 + 2 * tig;
#pragma unroll
            for (int ks = 0; ks < 4; ks++) {
                uint2 a = *(const uint2*)(usm + OFF_QF + arow2 + ks * 8);
                uint2 b = *(const uint2*)(usm + OFF_QF + arow2 + ks * 8 + 8 * 40);
                qreg[ks][0] = a.x; qreg[ks][1] = b.x;
                qreg[ks][2] = a.y; qreg[ks][3] = b.y;
            }
            do_scores(0);
        }
    }

    float zacc[4][4][4];
#pragma unroll
    for (int i = 0; i < 4; i++)
#pragma unroll
        for (int j = 0; j < 4; j++)
#pragma unroll
            for (int q = 0; q < 4; q++) zacc[i][j][q] = 0.f;

    for (int jt = 0; jt < njt; jt++) {
        if (jt + 2 < njt) {
            issue_tile(jt + 2);
            CP_COMMIT();
            asm volatile("cp.async.wait_group 1;" ::: "memory");
        } else {
            asm volatile("cp.async.wait_group 0;" ::: "memory");
        }
        __syncthreads();   // P[jt] & tile jt+1 ready; prev Z done

        if (wid < 8 && jt + 1 < njt) do_scores(jt + 1);

        // Z(jt) += P @ KV : 2 fp16 k16 steps over the 32-key tile
        {
            const uint32_t* KVs = usm + OFF_KV + (jt & 3) * KV_STG;
            const uint32_t* Pb = usm + OFF_P + (jt & 1) * P_STG;
#pragma unroll
            for (int ks = 0; ks < 2; ks++) {
                uint2 pa[4][2];
#pragma unroll
                for (int mt = 0; mt < 4; mt++) {
                    const uint32_t* Pr = Pb + (mt * 16 + gid) * 20 + ks * 8 + 2 * tig;
                    pa[mt][0] = *(const uint2*)Pr;
                    pa[mt][1] = *(const uint2*)(Pr + 8 * 20);
                }
#pragma unroll
                for (int nt = 0; nt < 4; nt++) {
                    int c = wid * 32 + nt * 8 + gid;
                    uint2 bb = *(const uint2*)(KVs + ks * 4096 + c * 8 + 2 * tig);
#pragma unroll
                    for (int mt = 0; mt < 4; mt++)
                        mma_f16(zacc[mt][nt], pa[mt][0].x, pa[mt][1].x,
                                pa[mt][0].y, pa[mt][1].y, bb.x, bb.y);
                }
            }
        }
    }
    __syncthreads();

    // ---- S reduce ----
    s_acc0 += __shfl_xor_sync(~0u, s_acc0, 1);
    s_acc0 += __shfl_xor_sync(~0u, s_acc0, 2);
    s_acc1 += __shfl_xor_sync(~0u, s_acc1, 1);
    s_acc1 += __shfl_xor_sync(~0u, s_acc1, 2);
    if (wid < 8 && tig == 0) {
        fsm[OFF_S + kw * 64 + rowa] = s_acc0;
        fsm[OFF_S + kw * 64 + rowa + 8] = s_acc1;
    }
    // ---- Z regs -> smem overlay (KV stages dead), stride 520 ----
#pragma unroll
    for (int mt = 0; mt < 4; mt++) {
        int row = mt * 16 + gid;
#pragma unroll
        for (int nt = 0; nt < 4; nt++) {
            float* zp = fsm + row * 520 + wid * 32 + (wid >> 1) + nt * 8 + tig * 2;
            zp[0] = zacc[mt][nt][0];
            zp[1] = zacc[mt][nt][1];
            zp[8 * 520] = zacc[mt][nt][2];
            zp[8 * 520 + 1] = zacc[mt][nt][3];
        }
    }
    __syncthreads();
    if (tid < 64)
        fsm[OFF_S + 128 + tid] = 1.f / (fsm[OFF_S + tid] + fsm[OFF_S + 64 + tid]);
    __syncthreads();

    // ---- octonion epilogue ----
    {
        int row = tid >> 3, m = tid & 7;
        float invS = fsm[OFF_S + 128 + row];
        const float* q = qn + ((long)h * T_SEQ + r0 + row) * HD + m * 8;
        const float* z = fsm + row * 520 + m * 65;

        float q8[8];
        float4 qa = *(const float4*)q, qb = *(const float4*)(q + 4);
        q8[0]=qa.x; q8[1]=qa.y; q8[2]=qa.z; q8[3]=qa.w;
        q8[4]=qb.x; q8[5]=qb.y; q8[6]=qb.z; q8[7]=qb.w;
        float acc[8] = {0,0,0,0,0,0,0,0};
#pragma unroll
        for (int p = 0; p < 8; p++) {
            float e[8] = {0,0,0,0,0,0,0,0};
            e[p] = 1.f;
            float uo[8], z8[8], wv[8];
            omul8(q8, e, uo);
#pragma unroll
            for (int i = 0; i < 8; i++) z8[i] = z[p * 8 + i];
            omul8(uo, z8, wv);
#pragma unroll
            for (int k = 0; k < 8; k++) acc[k] += wv[k];
        }
        float* yo = y + (long)(r0 + row) * CEMB + h * HD + m * 8;
        *(float4*)yo = make_float4(acc[0]*invS, acc[1]*invS, acc[2]*invS, acc[3]*invS);
        *(float4*)(yo + 4) = make_float4(acc[4]*invS, acc[5]*invS, acc[6]*invS, acc[7]*invS);
    }
}

// ---------------- launch -----------------------------------------------------
extern "C" void kernel_launch(void* const* d_in, const int* in_sizes, int n_in,
                              void* d_out, int out_size)
{
    const float* x    = (const float*)d_in[0];
    const float* cosp = (const float*)d_in[1];
    const float* sinp = (const float*)d_in[2];
    const float* Wq   = (const float*)d_in[3];
    const float* Wk   = (const float*)d_in[4];
    const float* Wv   = (const float*)d_in[5];
    const float* Wo   = (const float*)d_in[6];
    float* out = (float*)d_out;

    float *qraw, *kraw, *vraw, *qn, *y;
    uint32_t *kvp16, *qf, *kf;
    cudaGetSymbolAddress((void**)&qraw,  g_qraw);
    cudaGetSymbolAddress((void**)&kraw,  g_kraw);
    cudaGetSymbolAddress((void**)&vraw,  g_vraw);
    cudaGetSymbolAddress((void**)&qn,    g_qn);
    cudaGetSymbolAddress((void**)&kvp16, g_kvp16);
    cudaGetSymbolAddress((void**)&qf,    g_qf);
    cudaGetSymbolAddress((void**)&kf,    g_kf);
    cudaGetSymbolAddress((void**)&y,     g_y);

    const int smem_gemm = 2 * GSTAGE * 4;
    cudaFuncSetAttribute(qkv_gemm, cudaFuncAttributeMaxDynamicSharedMemorySize, smem_gemm);
    cudaFuncSetAttribute(wo_gemm,  cudaFuncAttributeMaxDynamicSharedMemorySize, smem_gemm);
    cudaFuncSetAttribute(fused_attn, cudaFuncAttributeMaxDynamicSharedMemorySize, FA_SMEM);

    qkv_gemm<<<dim3(CEMB / 64, T_SEQ / 128, 3), 256, smem_gemm>>>(
        x, Wq, Wk, Wv, qraw, kraw, vraw);

    prep_kernel<<<dim3(NH, T_SEQ / 8), 512>>>(qraw, kraw, vraw, cosp, sinp,
                                              qn, kvp16, qf, kf);

    fused_attn<<<dim3(32, NH), 512, FA_SMEM>>>(qn, qf, kf, kvp16, y);

    wo_gemm<<<dim3(CEMB / 64, T_SEQ / 128), 256, smem_gemm>>>(y, Wo, out);
}

// round 16
// speedup vs baseline: 1.7494x; 1.1518x over previous
#include <cuda_runtime.h>
#include <cuda_fp16.h>
#include <cstdint>
#include <math.h>

#define T_SEQ 2048
#define NH 16
#define HD 64
#define CEMB 1024
#define KVW 512

// ---------------- scratch (device globals) ----------------------------------
static __device__ float g_qraw[T_SEQ * CEMB];
static __device__ float g_kraw[T_SEQ * CEMB];
static __device__ float g_vraw[T_SEQ * CEMB];
static __device__ float g_qn[NH * T_SEQ * HD];
static __device__ uint32_t g_kvp16[NH * T_SEQ * KVW / 2]; // fp16x2 paired
static __device__ uint32_t g_qf[NH * T_SEQ * 32];         // q fp16x2 (permuted)
static __device__ uint32_t g_kf[NH * T_SEQ * 32];         // k fp16x2 (permuted)
static __device__ uint32_t g_xh[T_SEQ * 512];             // x fp16 hi (permuted)
static __device__ uint32_t g_xl[T_SEQ * 512];             // x fp16 lo
static __device__ uint32_t g_wh[4 * CEMB * 512];          // Wq,Wk,Wv,Wo fp16 hi
static __device__ uint32_t g_yh[T_SEQ * 512];             // y fp16 hi (permuted)
static __device__ uint32_t g_yl[T_SEQ * 512];             // y fp16 lo

// ---------------- helpers ----------------------------------------------------
static __device__ __forceinline__ uint32_t smem_u32(const void* p) {
    uint32_t a;
    asm("{ .reg .u64 t; cvta.to.shared.u64 t, %1; cvt.u32.u64 %0, t; }" : "=r"(a) : "l"(p));
    return a;
}
static __device__ __forceinline__ void mma_f16(
    float* acc, uint32_t a0, uint32_t a1, uint32_t a2, uint32_t a3,
    uint32_t b0, uint32_t b1)
{
    asm volatile(
        "mma.sync.aligned.m16n8k16.row.col.f32.f16.f16.f32 "
        "{%0,%1,%2,%3},{%4,%5,%6,%7},{%8,%9},{%0,%1,%2,%3};"
        : "+f"(acc[0]), "+f"(acc[1]), "+f"(acc[2]), "+f"(acc[3])
        : "r"(a0), "r"(a1), "r"(a2), "r"(a3), "r"(b0), "r"(b1));
}
static __device__ __forceinline__ uint32_t packf16(float lo, float hi) {
    uint32_t w;
    asm("cvt.rn.f16x2.f32 %0, %1, %2;" : "=r"(w) : "f"(hi), "f"(lo));
    return w;
}
#define CP16(dst_u32, src_ptr) \
    asm volatile("cp.async.cg.shared.global [%0], [%1], 16;" \
                 :: "r"(dst_u32), "l"(src_ptr) : "memory")
#define CP_COMMIT() asm volatile("cp.async.commit_group;" ::: "memory")
#define CP_WAIT1() asm volatile("cp.async.wait_group 1;" ::: "memory")
#define CP_WAIT0() asm volatile("cp.async.wait_group 0;" ::: "memory")

static __device__ __forceinline__ int permw(int d) {
    return (d & ~7) + ((d & 3) * 2 + ((d & 7) >> 2));
}

// ---------------- conversion kernels ------------------------------------------
// pack 16 floats -> 8 fp16x2 words in pair-permuted order {w0,w4,w1,w5,w2,w6,w3,w7}
__global__ __launch_bounds__(256) void conv_w(
    const float* __restrict__ Wq, const float* __restrict__ Wk,
    const float* __restrict__ Wv, const float* __restrict__ Wo,
    uint32_t* __restrict__ out)
{
    const float* W = blockIdx.y == 0 ? Wq : blockIdx.y == 1 ? Wk :
                     blockIdx.y == 2 ? Wv : Wo;
    uint32_t* o = out + (long)blockIdx.y * (CEMB * 512);
    long g = blockIdx.x * 256 + threadIdx.x;          // 65536 groups
    const float4* s = (const float4*)(W + g * 16);
    float4 a = s[0], b = s[1], c = s[2], d = s[3];
    uint32_t w0 = packf16(a.x, a.y), w1 = packf16(a.z, a.w);
    uint32_t w2 = packf16(b.x, b.y), w3 = packf16(b.z, b.w);
    uint32_t w4 = packf16(c.x, c.y), w5 = packf16(c.z, c.w);
    uint32_t w6 = packf16(d.x, d.y), w7 = packf16(d.z, d.w);
    uint4* dst = (uint4*)(o + g * 8);
    dst[0] = make_uint4(w0, w4, w1, w5);
    dst[1] = make_uint4(w2, w6, w3, w7);
}

__global__ __launch_bounds__(256) void conv_x(
    const float* __restrict__ x, uint32_t* __restrict__ xh, uint32_t* __restrict__ xl)
{
    long g = blockIdx.x * 256 + threadIdx.x;          // 131072 groups
    const float4* s = (const float4*)(x + g * 16);
    float f[16];
    float4 a = s[0], b = s[1], c = s[2], d = s[3];
    f[0]=a.x; f[1]=a.y; f[2]=a.z; f[3]=a.w;
    f[4]=b.x; f[5]=b.y; f[6]=b.z; f[7]=b.w;
    f[8]=c.x; f[9]=c.y; f[10]=c.z; f[11]=c.w;
    f[12]=d.x; f[13]=d.y; f[14]=d.z; f[15]=d.w;
    uint32_t hw[8], lw[8];
#pragma unroll
    for (int i = 0; i < 8; i++) {
        hw[i] = packf16(f[2*i], f[2*i+1]);
        float2 hf = __half22float2(*(__half2*)&hw[i]);
        lw[i] = packf16(f[2*i] - hf.x, f[2*i+1] - hf.y);
    }
    uint4* dh = (uint4*)(xh + g * 8);
    dh[0] = make_uint4(hw[0], hw[4], hw[1], hw[5]);
    dh[1] = make_uint4(hw[2], hw[6], hw[3], hw[7]);
    uint4* dl = (uint4*)(xl + g * 8);
    dl[0] = make_uint4(lw[0], lw[4], lw[1], lw[5]);
    dl[1] = make_uint4(lw[2], lw[6], lw[3], lw[7]);
}

// ================= fp16 2-pass GEMM (NT), cp.async 3-stage pipeline ==========
// 128x64 tiles, BK=32 floats (16 words), pre-packed permuted fp16 operands.
#define W16_AL 3072
#define W16_B  6144
#define W16_STG 7680           // words per stage (A hi 128x24 + A lo + B 64x24)
#define GEMM16_SMEM (3 * W16_STG * 4)   // 92160 B

static __device__ __forceinline__ void gemm16_body(
    const uint32_t* __restrict__ Ah, const uint32_t* __restrict__ Al,
    const uint32_t* __restrict__ Bh, float* __restrict__ C,
    int ldc, int m0, int n0)
{
    extern __shared__ uint32_t smu[];
    uint32_t sbase = smem_u32(smu);
    const int nch = 32;

    int tid = threadIdx.x, lane = tid & 31, wid = tid >> 5;
    int gid = lane >> 2, tig = lane & 3;
    int warp_m = wid & 3, warp_n = wid >> 2;

    auto issue = [&](int ch) {
        int s = (ch % 3) * W16_STG;
#pragma unroll
        for (int i = 0; i < 2; i++) {
            int u = tid + i * 256;              // 0..511
            int r = u >> 2, w4 = (u & 3) * 4;
            CP16(sbase + (s + r * 24 + w4) * 4,
                 Ah + (long)(m0 + r) * 512 + ch * 16 + w4);
            CP16(sbase + (s + W16_AL + r * 24 + w4) * 4,
                 Al + (long)(m0 + r) * 512 + ch * 16 + w4);
        }
        {
            int r = tid >> 2, w4 = (tid & 3) * 4;
            CP16(sbase + (s + W16_B + r * 24 + w4) * 4,
                 Bh + (long)(n0 + r) * 512 + ch * 16 + w4);
        }
    };

    float acc[2][4][4];
#pragma unroll
    for (int i = 0; i < 2; i++)
#pragma unroll
        for (int j = 0; j < 4; j++)
#pragma unroll
            for (int q = 0; q < 4; q++) acc[i][j][q] = 0.f;

    issue(0); CP_COMMIT();
    issue(1); CP_COMMIT();

    for (int ch = 0; ch < nch; ch++) {
        if (ch + 1 < nch) CP_WAIT1(); else CP_WAIT0();
        __syncthreads();
        if (ch + 2 < nch) { issue(ch + 2); CP_COMMIT(); }

        int sb = (ch % 3) * W16_STG;
#pragma unroll
        for (int ks = 0; ks < 2; ks++) {
            uint2 bfr[4];
#pragma unroll
            for (int nt = 0; nt < 4; nt++)
                bfr[nt] = *(const uint2*)(smu + sb + W16_B +
                    (warp_n * 32 + nt * 8 + gid) * 24 + ks * 8 + 2 * tig);
#pragma unroll
            for (int p = 0; p < 2; p++) {
                const uint32_t* Ab = smu + sb + (p ? W16_AL : 0);
                uint2 u0[2], u1[2];
#pragma unroll
                for (int mt = 0; mt < 2; mt++) {
                    int r = (warp_m * 32 + mt * 16 + gid) * 24 + ks * 8 + 2 * tig;
                    u0[mt] = *(const uint2*)(Ab + r);
                    u1[mt] = *(const uint2*)(Ab + r + 8 * 24);
                }
#pragma unroll
                for (int mt = 0; mt < 2; mt++)
#pragma unroll
                    for (int nt = 0; nt < 4; nt++)
                        mma_f16(acc[mt][nt], u0[mt].x, u1[mt].x, u0[mt].y,
                                u1[mt].y, bfr[nt].x, bfr[nt].y);
            }
        }
    }

#pragma unroll
    for (int mt = 0; mt < 2; mt++) {
        int r0 = m0 + warp_m * 32 + mt * 16 + gid;
#pragma unroll
        for (int nt = 0; nt < 4; nt++) {
            int c = n0 + warp_n * 32 + nt * 8 + tig * 2;
            *(float2*)(C + (long)r0 * ldc + c) =
                make_float2(acc[mt][nt][0], acc[mt][nt][1]);
            *(float2*)(C + (long)(r0 + 8) * ldc + c) =
                make_float2(acc[mt][nt][2], acc[mt][nt][3]);
        }
    }
}

__global__ void __launch_bounds__(256, 2) qkv_gemm(
    const uint32_t* __restrict__ xh, const uint32_t* __restrict__ xl,
    const uint32_t* __restrict__ wh,
    float* q, float* k, float* v)
{
    const uint32_t* B = wh + (long)blockIdx.z * (CEMB * 512);
    float* C = blockIdx.z == 0 ? q : blockIdx.z == 1 ? k : v;
    gemm16_body(xh, xl, B, C, CEMB, blockIdx.y * 128, blockIdx.x * 64);
}

__global__ void __launch_bounds__(256, 2) wo_gemm(
    const uint32_t* __restrict__ yh, const uint32_t* __restrict__ yl,
    const uint32_t* __restrict__ wh, float* out)
{
    gemm16_body(yh, yl, wh + 3L * (CEMB * 512), out, CEMB,
                blockIdx.y * 128, blockIdx.x * 64);
}

// ---------------- prep (unchanged from R15) ------------------------------------
__global__ __launch_bounds__(512) void prep_kernel(
    const float* __restrict__ qraw, const float* __restrict__ kraw,
    const float* __restrict__ vraw,
    const float* __restrict__ cosp, const float* __restrict__ sinp,
    float* __restrict__ qn, uint32_t* __restrict__ kvp16,
    uint32_t* __restrict__ qf, uint32_t* __restrict__ kf)
{
    int h = blockIdx.x, g = blockIdx.y;
    int tid = threadIdx.x;
    int w = tid >> 6, d = tid & 63;
    int t = g * 8 + w;

    __shared__ float r1[8][64], r2[8][64], skc[8][64], sv[8][64];
    __shared__ float sq[8][64], sk[8][64];
    __shared__ float kvstage[8][512];

    long base = (long)t * CEMB + h * HD;
    int j = d & 31;
    float c = cosp[t * 32 + j], s = sinp[t * 32 + j];

    float x1q = qraw[base + j], x2q = qraw[base + j + 32];
    float qv = (d < 32) ? (x1q * c + x2q * s) : (x2q * c - x1q * s);
    float x1k = kraw[base + j], x2k = kraw[base + j + 32];
    float kvv = (d < 32) ? (x1k * c + x2k * s) : (x2k * c - x1k * s);

    r1[w][d] = qv * qv;
    r2[w][d] = kvv * kvv;
    __syncthreads();
#pragma unroll
    for (int off = 32; off > 0; off >>= 1) {
        if (d < off) { r1[w][d] += r1[w][d + off]; r2[w][d] += r2[w][d + off]; }
        __syncthreads();
    }
    float rq = rsqrtf(r1[w][0] * (1.f / 64.f) + 1e-6f);
    float rk = rsqrtf(r2[w][0] * (1.f / 64.f) + 1e-6f);
    float qno = qv * rq, kno = kvv * rk;

    qn[((long)h * T_SEQ + t) * HD + d] = qno;
    sq[w][d] = qno;
    sk[w][d] = kno;

    float o = kno * kno;
    o += __shfl_xor_sync(0xffffffffu, o, 1);
    o += __shfl_xor_sync(0xffffffffu, o, 2);
    o += __shfl_xor_sync(0xffffffffu, o, 4);
    float ko = kno / fmaxf(sqrtf(o), 1e-12f);
    skc[w][d] = ((d & 7) == 0) ? ko : -ko;
    sv[w][d] = vraw[base + d];
    __syncthreads();

    {
        float kc = skc[w][d];
        int mb = d & ~7;
#pragma unroll
        for (int i = 0; i < 8; i++)
            kvstage[w][d * 8 + i] = kc * sv[w][mb + i];
    }
    {
        long pbase = ((long)h * T_SEQ + t) * 32;
        if (d < 32) {
            qf[pbase + permw(d)] = packf16(sq[w][2 * d], sq[w][2 * d + 1]);
        } else {
            int d2 = d - 32;
            kf[pbase + permw(d2)] = packf16(sk[w][2 * d2], sk[w][2 * d2 + 1]);
        }
    }
    __syncthreads();

    uint32_t* outb = kvp16 + ((long)(h * 128 + (g >> 1)) * 512) * 8 + (g & 1);
#pragma unroll
    for (int it = 0; it < 4; it++) {
        int idx = tid + it * 512;
        int cc = idx >> 2, pl = idx & 3;
        outb[cc * 8 + pl * 2] = packf16(kvstage[2 * pl][cc], kvstage[2 * pl + 1][cc]);
    }
}

// ---------------- octonion math ----------------------------------------------
__device__ __forceinline__ void qmul4(const float* q1, const float* q2, float* r)
{
    r[0] = q1[0]*q2[0] - q1[1]*q2[1] - q1[2]*q2[2] - q1[3]*q2[3];
    r[1] = q1[0]*q2[1] + q1[1]*q2[0] + q1[2]*q2[3] - q1[3]*q2[2];
    r[2] = q1[0]*q2[2] - q1[1]*q2[3] + q1[2]*q2[0] + q1[3]*q2[1];
    r[3] = q1[0]*q2[3] + q1[1]*q2[2] - q1[2]*q2[1] + q1[3]*q2[0];
}
__device__ __forceinline__ void omul8(const float* o1, const float* o2, float* r)
{
    const float* a = o1; const float* b = o1 + 4;
    const float* c = o2; const float* d = o2 + 4;
    float dc[4] = { d[0], -d[1], -d[2], -d[3] };
    float cc[4] = { c[0], -c[1], -c[2], -c[3] };
    float t1[4], t2[4];
    qmul4(a, c, t1); qmul4(dc, b, t2);
    r[0] = t1[0] - t2[0]; r[1] = t1[1] - t2[1];
    r[2] = t1[2] - t2[2]; r[3] = t1[3] - t2[3];
    qmul4(d, a, t1); qmul4(b, cc, t2);
    r[4] = t1[0] + t2[0]; r[5] = t1[1] + t2[1];
    r[6] = t1[2] + t2[2]; r[7] = t1[3] + t2[3];
}

// ===== fused attention (R15, unchanged except fp16 y output) =================
#define TK 32
#define OFF_KV 0
#define KV_STG 8192
#define OFF_KH 32768
#define KH_STG 1280
#define OFF_P  37888
#define P_STG  1280
#define OFF_QF 40448
#define OFF_S  43008
#define FA_SMEM ((OFF_S + 192) * 4)

__global__ void __launch_bounds__(512, 1) fused_attn(
    const float* __restrict__ qn,
    const uint32_t* __restrict__ qf, const uint32_t* __restrict__ kf,
    const uint32_t* __restrict__ kvp16,
    uint32_t* __restrict__ yh, uint32_t* __restrict__ yl)
{
    extern __shared__ __align__(16) float fsm[];
    uint32_t* usm = (uint32_t*)fsm;
    uint32_t sbase = smem_u32(fsm);

    int qt = 31 - blockIdx.x;
    int h = blockIdx.y;
    int r0 = qt * 64;
    int njt = 2 * (qt + 1);

    int tid = threadIdx.x, lane = tid & 31, wid = tid >> 5;
    int gid = lane >> 2, tig = lane & 3;
    int rg = wid & 3, kw = wid >> 2;
    int rowa = rg * 16 + gid;

    const uint32_t* kvph = kvp16 + (long)h * 128 * 4096;
    const uint32_t* kfh = kf + (long)h * T_SEQ * 32;

    auto issue_tile = [&](int t) {
        const uint32_t* src = kvph + (long)t * 8192;
        uint32_t dstw = OFF_KV + (t & 3) * KV_STG;
#pragma unroll
        for (int i = 0; i < 4; i++) {
            int idx = tid + i * 512;
            CP16(sbase + (dstw + idx * 4) * 4, src + idx * 4);
        }
        if (tid < 256) {
            int rr = tid >> 3, ch = (tid & 7) * 4;
            const uint32_t* sb2 = kfh + (long)(t * TK + rr) * 32 + ch;
            CP16(sbase + (OFF_KH + (t & 3) * KH_STG + rr * 40 + ch) * 4, sb2);
        }
    };

    float s_acc0 = 0.f, s_acc1 = 0.f;
    uint32_t qreg[4][4];

    auto do_scores = [&](int j) {
        const uint32_t* KHb = usm + OFF_KH + (j & 3) * KH_STG;
#pragma unroll
        for (int nt = 0; nt < 2; nt++) {
            float sc2[2][4];
#pragma unroll
            for (int p = 0; p < 2; p++)
#pragma unroll
                for (int q = 0; q < 4; q++) sc2[p][q] = 0.f;
            int krow = (kw * 16 + nt * 8 + gid) * 40 + 2 * tig;
#pragma unroll
            for (int ks = 0; ks < 4; ks++) {
                uint2 kb = *(const uint2*)(KHb + krow + ks * 8);
                mma_f16(sc2[ks & 1], qreg[ks][0], qreg[ks][1],
                        qreg[ks][2], qreg[ks][3], kb.x, kb.y);
            }
            float s0 = sc2[0][0] + sc2[1][0];
            float s1 = sc2[0][1] + sc2[1][1];
            float s2 = sc2[0][2] + sc2[1][2];
            float s3 = sc2[0][3] + sc2[1][3];

            int colg = j * TK + kw * 16 + nt * 8 + tig * 2;
            float p00 = __expf(s0 * 0.125f);
            float p01 = __expf(s1 * 0.125f);
            float p10 = __expf(s2 * 0.125f);
            float p11 = __expf(s3 * 0.125f);
            if (j >= njt - 2) {
                if (colg     > r0 + rowa)     p00 = 0.f;
                if (colg + 1 > r0 + rowa)     p01 = 0.f;
                if (colg     > r0 + rowa + 8) p10 = 0.f;
                if (colg + 1 > r0 + rowa + 8) p11 = 0.f;
            }
            uint32_t w0 = packf16(p00, p01);
            uint32_t w1 = packf16(p10, p11);
            uint32_t* Pr = usm + OFF_P + (j & 1) * P_STG + rowa * 20 +
                           kw * 8 + tig * 2 + nt;
            Pr[0] = w0;
            Pr[8 * 20] = w1;
            float2 f0 = __half22float2(*(__half2*)&w0);
            float2 f1 = __half22float2(*(__half2*)&w1);
            s_acc0 += f0.x + f0.y;
            s_acc1 += f1.x + f1.y;
        }
    };

    {
        const uint32_t* qhh = qf + ((long)h * T_SEQ + r0) * 32;
        {
            int rr = tid >> 3, ch = (tid & 7) * 4;
            CP16(sbase + (OFF_QF + rr * 40 + ch) * 4, qhh + (long)rr * 32 + ch);
        }
        issue_tile(0);
        CP_COMMIT();
        issue_tile(1);
        CP_COMMIT();
        CP_WAIT1();
        __syncthreads();
        if (wid < 8) {
            int arow2 = rowa * 40 + 2 * tig;
#pragma unroll
            for (int ks = 0; ks < 4; ks++) {
                uint2 a = *(const uint2*)(usm + OFF_QF + arow2 + ks * 8);
                uint2 b = *(const uint2*)(usm + OFF_QF + arow2 + ks * 8 + 8 * 40);
                qreg[ks][0] = a.x; qreg[ks][1] = b.x;
                qreg[ks][2] = a.y; qreg[ks][3] = b.y;
            }
            do_scores(0);
        }
    }

    float zacc[4][4][4];
#pragma unroll
    for (int i = 0; i < 4; i++)
#pragma unroll
        for (int j = 0; j < 4; j++)
#pragma unroll
            for (int q = 0; q < 4; q++) zacc[i][j][q] = 0.f;

    for (int jt = 0; jt < njt; jt++) {
        if (jt + 2 < njt) {
            issue_tile(jt + 2);
            CP_COMMIT();
            CP_WAIT1();
        } else {
            CP_WAIT0();
        }
        __syncthreads();

        if (wid < 8 && jt + 1 < njt) do_scores(jt + 1);

        {
            const uint32_t* KVs = usm + OFF_KV + (jt & 3) * KV_STG;
            const uint32_t* Pb = usm + OFF_P + (jt & 1) * P_STG;
#pragma unroll
            for (int ks = 0; ks < 2; ks++) {
                uint2 pa[4][2];
#pragma unroll
                for (int mt = 0; mt < 4; mt++) {
                    const uint32_t* Pr = Pb + (mt * 16 + gid) * 20 + ks * 8 + 2 * tig;
                    pa[mt][0] = *(const uint2*)Pr;
                    pa[mt][1] = *(const uint2*)(Pr + 8 * 20);
                }
#pragma unroll
                for (int nt = 0; nt < 4; nt++) {
                    int c = wid * 32 + nt * 8 + gid;
                    uint2 bb = *(const uint2*)(KVs + ks * 4096 + c * 8 + 2 * tig);
#pragma unroll
                    for (int mt = 0; mt < 4; mt++)
                        mma_f16(zacc[mt][nt], pa[mt][0].x, pa[mt][1].x,
                                pa[mt][0].y, pa[mt][1].y, bb.x, bb.y);
                }
            }
        }
    }
    __syncthreads();

    s_acc0 += __shfl_xor_sync(~0u, s_acc0, 1);
    s_acc0 += __shfl_xor_sync(~0u, s_acc0, 2);
    s_acc1 += __shfl_xor_sync(~0u, s_acc1, 1);
    s_acc1 += __shfl_xor_sync(~0u, s_acc1, 2);
    if (wid < 8 && tig == 0) {
        fsm[OFF_S + kw * 64 + rowa] = s_acc0;
        fsm[OFF_S + kw * 64 + rowa + 8] = s_acc1;
    }
#pragma unroll
    for (int mt = 0; mt < 4; mt++) {
        int row = mt * 16 + gid;
#pragma unroll
        for (int nt = 0; nt < 4; nt++) {
            float* zp = fsm + row * 520 + wid * 32 + (wid >> 1) + nt * 8 + tig * 2;
            zp[0] = zacc[mt][nt][0];
            zp[1] = zacc[mt][nt][1];
            zp[8 * 520] = zacc[mt][nt][2];
            zp[8 * 520 + 1] = zacc[mt][nt][3];
        }
    }
    __syncthreads();
    if (tid < 64)
        fsm[OFF_S + 128 + tid] = 1.f / (fsm[OFF_S + tid] + fsm[OFF_S + 64 + tid]);
    __syncthreads();

    // ---- octonion epilogue -> y fp16 hi/lo (permuted pair layout) ----
    {
        int row = tid >> 3, m = tid & 7;
        float invS = fsm[OFF_S + 128 + row];
        const float* q = qn + ((long)h * T_SEQ + r0 + row) * HD + m * 8;
        const float* z = fsm + row * 520 + m * 65;

        float q8[8];
        float4 qa = *(const float4*)q, qb = *(const float4*)(q + 4);
        q8[0]=qa.x; q8[1]=qa.y; q8[2]=qa.z; q8[3]=qa.w;
        q8[4]=qb.x; q8[5]=qb.y; q8[6]=qb.z; q8[7]=qb.w;
        float acc[8] = {0,0,0,0,0,0,0,0};
#pragma unroll
        for (int p = 0; p < 8; p++) {
            float e[8] = {0,0,0,0,0,0,0,0};
            e[p] = 1.f;
            float uo[8], z8[8], wv[8];
            omul8(q8, e, uo);
#pragma unroll
            for (int i = 0; i < 8; i++) z8[i] = z[p * 8 + i];
            omul8(uo, z8, wv);
#pragma unroll
            for (int k = 0; k < 8; k++) acc[k] += wv[k];
        }
        long ybw = (long)(r0 + row) * 512 + h * 32 + (m >> 1) * 8 + (m & 1);
#pragma unroll
        for (int j = 0; j < 4; j++) {
            float f0 = acc[2 * j] * invS, f1 = acc[2 * j + 1] * invS;
            uint32_t hw = packf16(f0, f1);
            float2 hf = __half22float2(*(__half2*)&hw);
            uint32_t lw = packf16(f0 - hf.x, f1 - hf.y);
            yh[ybw + 2 * j] = hw;
            yl[ybw + 2 * j] = lw;
        }
    }
}

// ---------------- launch -----------------------------------------------------
extern "C" void kernel_launch(void* const* d_in, const int* in_sizes, int n_in,
                              void* d_out, int out_size)
{
    const float* x    = (const float*)d_in[0];
    const float* cosp = (const float*)d_in[1];
    const float* sinp = (const float*)d_in[2];
    const float* Wq   = (const float*)d_in[3];
    const float* Wk   = (const float*)d_in[4];
    const float* Wv   = (const float*)d_in[5];
    const float* Wo   = (const float*)d_in[6];
    float* out = (float*)d_out;

    float *qraw, *kraw, *vraw, *qn;
    uint32_t *kvp16, *qf, *kf, *xh, *xl, *wh, *yh, *yl;
    cudaGetSymbolAddress((void**)&qraw,  g_qraw);
    cudaGetSymbolAddress((void**)&kraw,  g_kraw);
    cudaGetSymbolAddress((void**)&vraw,  g_vraw);
    cudaGetSymbolAddress((void**)&qn,    g_qn);
    cudaGetSymbolAddress((void**)&kvp16, g_kvp16);
    cudaGetSymbolAddress((void**)&qf,    g_qf);
    cudaGetSymbolAddress((void**)&kf,    g_kf);
    cudaGetSymbolAddress((void**)&xh,    g_xh);
    cudaGetSymbolAddress((void**)&xl,    g_xl);
    cudaGetSymbolAddress((void**)&wh,    g_wh);
    cudaGetSymbolAddress((void**)&yh,    g_yh);
    cudaGetSymbolAddress((void**)&yl,    g_yl);

    cudaFuncSetAttribute(qkv_gemm, cudaFuncAttributeMaxDynamicSharedMemorySize, GEMM16_SMEM);
    cudaFuncSetAttribute(wo_gemm,  cudaFuncAttributeMaxDynamicSharedMemorySize, GEMM16_SMEM);
    cudaFuncSetAttribute(fused_attn, cudaFuncAttributeMaxDynamicSharedMemorySize, FA_SMEM);

    // 0) pack weights (hi) and x (hi+lo) into permuted fp16 layout
    conv_w<<<dim3(256, 4), 256>>>(Wq, Wk, Wv, Wo, wh);
    conv_x<<<512, 256>>>(x, xh, xl);

    // 1) QKV projections (fp16 2-pass, cp.async pipelined)
    qkv_gemm<<<dim3(CEMB / 64, T_SEQ / 128, 3), 256, GEMM16_SMEM>>>(
        xh, xl, wh, qraw, kraw, vraw);

    // 2) rotary + rms + octet-norm + fp16 packing
    prep_kernel<<<dim3(NH, T_SEQ / 8), 512>>>(qraw, kraw, vraw, cosp, sinp,
                                              qn, kvp16, qf, kf);

    // 3) fused attention -> y (fp16 hi/lo packed)
    fused_attn<<<dim3(32, NH), 512, FA_SMEM>>>(qn, qf, kf, kvp16, yh, yl);

    // 4) out = y @ Wo^T (fp16 2-pass, cp.async pipelined)
    wo_gemm<<<dim3(CEMB / 64, T_SEQ / 128), 256, GEMM16_SMEM>>>(yh, yl, wh, out);
}

// round 17
// speedup vs baseline: 1.8040x; 1.0312x over previous
#include <cuda_runtime.h>
#include <cuda_fp16.h>
#include <cstdint>
#include <math.h>

#define T_SEQ 2048
#define NH 16
#define HD 64
#define CEMB 1024
#define KVW 512

// ---------------- scratch (device globals) ----------------------------------
static __device__ float g_qraw[T_SEQ * CEMB];
static __device__ float g_kraw[T_SEQ * CEMB];
static __device__ float g_vraw[T_SEQ * CEMB];
static __device__ float g_qn[NH * T_SEQ * HD];
static __device__ uint32_t g_kvp16[NH * T_SEQ * KVW / 2]; // fp16x2 paired
static __device__ uint32_t g_qf[NH * T_SEQ * 32];         // q fp16x2 (permuted)
static __device__ uint32_t g_kf[NH * T_SEQ * 32];         // k fp16x2 (permuted)
static __device__ uint32_t g_xh[T_SEQ * 512];             // x fp16 hi (permuted)
static __device__ uint32_t g_xl[T_SEQ * 512];             // x fp16 lo
static __device__ uint32_t g_wh[4 * CEMB * 512];          // Wq,Wk,Wv,Wo fp16 hi
static __device__ uint32_t g_yh[T_SEQ * 512];             // y fp16 hi (permuted)
static __device__ uint32_t g_yl[T_SEQ * 512];             // y fp16 lo

// ---------------- helpers ----------------------------------------------------
static __device__ __forceinline__ uint32_t smem_u32(const void* p) {
    uint32_t a;
    asm("{ .reg .u64 t; cvta.to.shared.u64 t, %1; cvt.u32.u64 %0, t; }" : "=r"(a) : "l"(p));
    return a;
}
static __device__ __forceinline__ void mma_f16(
    float* acc, uint32_t a0, uint32_t a1, uint32_t a2, uint32_t a3,
    uint32_t b0, uint32_t b1)
{
    asm volatile(
        "mma.sync.aligned.m16n8k16.row.col.f32.f16.f16.f32 "
        "{%0,%1,%2,%3},{%4,%5,%6,%7},{%8,%9},{%0,%1,%2,%3};"
        : "+f"(acc[0]), "+f"(acc[1]), "+f"(acc[2]), "+f"(acc[3])
        : "r"(a0), "r"(a1), "r"(a2), "r"(a3), "r"(b0), "r"(b1));
}
static __device__ __forceinline__ uint32_t packf16(float lo, float hi) {
    uint32_t w;
    asm("cvt.rn.f16x2.f32 %0, %1, %2;" : "=r"(w) : "f"(hi), "f"(lo));
    return w;
}
#define CP16(dst_u32, src_ptr) \
    asm volatile("cp.async.cg.shared.global [%0], [%1], 16;" \
                 :: "r"(dst_u32), "l"(src_ptr) : "memory")
#define CP_COMMIT() asm volatile("cp.async.commit_group;" ::: "memory")
#define CP_WAIT3() asm volatile("cp.async.wait_group 3;" ::: "memory")
#define CP_WAIT2() asm volatile("cp.async.wait_group 2;" ::: "memory")
#define CP_WAIT1() asm volatile("cp.async.wait_group 1;" ::: "memory")
#define CP_WAIT0() asm volatile("cp.async.wait_group 0;" ::: "memory")

static __device__ __forceinline__ int permw(int d) {
    return (d & ~7) + ((d & 3) * 2 + ((d & 7) >> 2));
}

// ---------------- conversion kernels ------------------------------------------
__global__ __launch_bounds__(256) void conv_w(
    const float* __restrict__ Wq, const float* __restrict__ Wk,
    const float* __restrict__ Wv, const float* __restrict__ Wo,
    uint32_t* __restrict__ out)
{
    const float* W = blockIdx.y == 0 ? Wq : blockIdx.y == 1 ? Wk :
                     blockIdx.y == 2 ? Wv : Wo;
    uint32_t* o = out + (long)blockIdx.y * (CEMB * 512);
    long g = blockIdx.x * 256 + threadIdx.x;
    const float4* s = (const float4*)(W + g * 16);
    float4 a = s[0], b = s[1], c = s[2], d = s[3];
    uint32_t w0 = packf16(a.x, a.y), w1 = packf16(a.z, a.w);
    uint32_t w2 = packf16(b.x, b.y), w3 = packf16(b.z, b.w);
    uint32_t w4 = packf16(c.x, c.y), w5 = packf16(c.z, c.w);
    uint32_t w6 = packf16(d.x, d.y), w7 = packf16(d.z, d.w);
    uint4* dst = (uint4*)(o + g * 8);
    dst[0] = make_uint4(w0, w4, w1, w5);
    dst[1] = make_uint4(w2, w6, w3, w7);
}

__global__ __launch_bounds__(256) void conv_x(
    const float* __restrict__ x, uint32_t* __restrict__ xh, uint32_t* __restrict__ xl)
{
    long g = blockIdx.x * 256 + threadIdx.x;
    const float4* s = (const float4*)(x + g * 16);
    float f[16];
    float4 a = s[0], b = s[1], c = s[2], d = s[3];
    f[0]=a.x; f[1]=a.y; f[2]=a.z; f[3]=a.w;
    f[4]=b.x; f[5]=b.y; f[6]=b.z; f[7]=b.w;
    f[8]=c.x; f[9]=c.y; f[10]=c.z; f[11]=c.w;
    f[12]=d.x; f[13]=d.y; f[14]=d.z; f[15]=d.w;
    uint32_t hw[8], lw[8];
#pragma unroll
    for (int i = 0; i < 8; i++) {
        hw[i] = packf16(f[2*i], f[2*i+1]);
        float2 hf = __half22float2(*(__half2*)&hw[i]);
        lw[i] = packf16(f[2*i] - hf.x, f[2*i+1] - hf.y);
    }
    uint4* dh = (uint4*)(xh + g * 8);
    dh[0] = make_uint4(hw[0], hw[4], hw[1], hw[5]);
    dh[1] = make_uint4(hw[2], hw[6], hw[3], hw[7]);
    uint4* dl = (uint4*)(xl + g * 8);
    dl[0] = make_uint4(lw[0], lw[4], lw[1], lw[5]);
    dl[1] = make_uint4(lw[2], lw[6], lw[3], lw[7]);
}

// ================= fp16 2-pass GEMM (NT), cp.async 3-stage pipeline ==========
#define W16_AL 3072
#define W16_B  6144
#define W16_STG 7680
#define GEMM16_SMEM (3 * W16_STG * 4)   // 92160 B

static __device__ __forceinline__ void gemm16_body(
    const uint32_t* __restrict__ Ah, const uint32_t* __restrict__ Al,
    const uint32_t* __restrict__ Bh, float* __restrict__ C,
    int ldc, int m0, int n0)
{
    extern __shared__ uint32_t smu[];
    uint32_t sbase = smem_u32(smu);
    const int nch = 32;

    int tid = threadIdx.x, lane = tid & 31, wid = tid >> 5;
    int gid = lane >> 2, tig = lane & 3;
    int warp_m = wid & 3, warp_n = wid >> 2;

    auto issue = [&](int ch) {
        int s = (ch % 3) * W16_STG;
#pragma unroll
        for (int i = 0; i < 2; i++) {
            int u = tid + i * 256;
            int r = u >> 2, w4 = (u & 3) * 4;
            CP16(sbase + (s + r * 24 + w4) * 4,
                 Ah + (long)(m0 + r) * 512 + ch * 16 + w4);
            CP16(sbase + (s + W16_AL + r * 24 + w4) * 4,
                 Al + (long)(m0 + r) * 512 + ch * 16 + w4);
        }
        {
            int r = tid >> 2, w4 = (tid & 3) * 4;
            CP16(sbase + (s + W16_B + r * 24 + w4) * 4,
                 Bh + (long)(n0 + r) * 512 + ch * 16 + w4);
        }
    };

    float acc[2][4][4];
#pragma unroll
    for (int i = 0; i < 2; i++)
#pragma unroll
        for (int j = 0; j < 4; j++)
#pragma unroll
            for (int q = 0; q < 4; q++) acc[i][j][q] = 0.f;

    issue(0); CP_COMMIT();
    issue(1); CP_COMMIT();

    for (int ch = 0; ch < nch; ch++) {
        if (ch + 1 < nch) CP_WAIT1(); else CP_WAIT0();
        __syncthreads();
        if (ch + 2 < nch) { issue(ch + 2); CP_COMMIT(); }

        int sb = (ch % 3) * W16_STG;
#pragma unroll
        for (int ks = 0; ks < 2; ks++) {
            uint2 bfr[4];
#pragma unroll
            for (int nt = 0; nt < 4; nt++)
                bfr[nt] = *(const uint2*)(smu + sb + W16_B +
                    (warp_n * 32 + nt * 8 + gid) * 24 + ks * 8 + 2 * tig);
#pragma unroll
            for (int p = 0; p < 2; p++) {
                const uint32_t* Ab = smu + sb + (p ? W16_AL : 0);
                uint2 u0[2], u1[2];
#pragma unroll
                for (int mt = 0; mt < 2; mt++) {
                    int r = (warp_m * 32 + mt * 16 + gid) * 24 + ks * 8 + 2 * tig;
                    u0[mt] = *(const uint2*)(Ab + r);
                    u1[mt] = *(const uint2*)(Ab + r + 8 * 24);
                }
#pragma unroll
                for (int mt = 0; mt < 2; mt++)
#pragma unroll
                    for (int nt = 0; nt < 4; nt++)
                        mma_f16(acc[mt][nt], u0[mt].x, u1[mt].x, u0[mt].y,
                                u1[mt].y, bfr[nt].x, bfr[nt].y);
            }
        }
    }

#pragma unroll
    for (int mt = 0; mt < 2; mt++) {
        int r0 = m0 + warp_m * 32 + mt * 16 + gid;
#pragma unroll
        for (int nt = 0; nt < 4; nt++) {
            int c = n0 + warp_n * 32 + nt * 8 + tig * 2;
            *(float2*)(C + (long)r0 * ldc + c) =
                make_float2(acc[mt][nt][0], acc[mt][nt][1]);
            *(float2*)(C + (long)(r0 + 8) * ldc + c) =
                make_float2(acc[mt][nt][2], acc[mt][nt][3]);
        }
    }
}

__global__ void __launch_bounds__(256, 2) qkv_gemm(
    const uint32_t* __restrict__ xh, const uint32_t* __restrict__ xl,
    const uint32_t* __restrict__ wh,
    float* q, float* k, float* v)
{
    const uint32_t* B = wh + (long)blockIdx.z * (CEMB * 512);
    float* C = blockIdx.z == 0 ? q : blockIdx.z == 1 ? k : v;
    gemm16_body(xh, xl, B, C, CEMB, blockIdx.y * 128, blockIdx.x * 64);
}

__global__ void __launch_bounds__(256, 2) wo_gemm(
    const uint32_t* __restrict__ yh, const uint32_t* __restrict__ yl,
    const uint32_t* __restrict__ wh, float* out)
{
    gemm16_body(yh, yl, wh + 3L * (CEMB * 512), out, CEMB,
                blockIdx.y * 128, blockIdx.x * 64);
}

// ---------------- prep: direct-pack KV (no smem transpose) -------------------
__global__ __launch_bounds__(512) void prep_kernel(
    const float* __restrict__ qraw, const float* __restrict__ kraw,
    const float* __restrict__ vraw,
    const float* __restrict__ cosp, const float* __restrict__ sinp,
    float* __restrict__ qn, uint32_t* __restrict__ kvp16,
    uint32_t* __restrict__ qf, uint32_t* __restrict__ kf)
{
    int h = blockIdx.x, g = blockIdx.y;
    int tid = threadIdx.x;
    int w = tid >> 6, d = tid & 63;
    int t = g * 8 + w;

    __shared__ float r1[8][64], r2[8][64];
    __shared__ float skc[8][65], sv[8][65];   // padded: conflict-free gather
    __shared__ float sq[8][64], sk[8][64];

    long base = (long)t * CEMB + h * HD;
    int j = d & 31;
    float c = cosp[t * 32 + j], s = sinp[t * 32 + j];

    float x1q = qraw[base + j], x2q = qraw[base + j + 32];
    float qv = (d < 32) ? (x1q * c + x2q * s) : (x2q * c - x1q * s);
    float x1k = kraw[base + j], x2k = kraw[base + j + 32];
    float kvv = (d < 32) ? (x1k * c + x2k * s) : (x2k * c - x1k * s);

    r1[w][d] = qv * qv;
    r2[w][d] = kvv * kvv;
    __syncthreads();
#pragma unroll
    for (int off = 32; off > 0; off >>= 1) {
        if (d < off) { r1[w][d] += r1[w][d + off]; r2[w][d] += r2[w][d + off]; }
        __syncthreads();
    }
    float rq = rsqrtf(r1[w][0] * (1.f / 64.f) + 1e-6f);
    float rk = rsqrtf(r2[w][0] * (1.f / 64.f) + 1e-6f);
    float qno = qv * rq, kno = kvv * rk;

    qn[((long)h * T_SEQ + t) * HD + d] = qno;
    sq[w][d] = qno;
    sk[w][d] = kno;

    float o = kno * kno;
    o += __shfl_xor_sync(0xffffffffu, o, 1);
    o += __shfl_xor_sync(0xffffffffu, o, 2);
    o += __shfl_xor_sync(0xffffffffu, o, 4);
    float ko = kno / fmaxf(sqrtf(o), 1e-12f);
    skc[w][d] = ((d & 7) == 0) ? ko : -ko;
    sv[w][d] = vraw[base + d];

    {
        long pbase = ((long)h * T_SEQ + t) * 32;
        if (d < 32) {
            qf[pbase + permw(d)] = packf16(sq[w][2 * d], sq[w][2 * d + 1]);
        } else {
            int d2 = d - 32;
            kf[pbase + permw(d2)] = packf16(sk[w][2 * d2], sk[w][2 * d2 + 1]);
        }
    }
    __syncthreads();

    // direct paired-fp16 output: word (cc, pl) packs keys 2pl, 2pl+1 at col cc
    uint32_t* outb = kvp16 + ((long)(h * 128 + (g >> 1)) * 512) * 8 + (g & 1);
#pragma unroll
    for (int it = 0; it < 4; it++) {
        int idx = tid + it * 512;
        int cc = idx >> 2, pl = idx & 3;
        int w0 = 2 * pl, w1 = w0 + 1;
        int dd = cc >> 3;                       // kc index
        int vi = ((cc >> 6) << 3) + (cc & 7);   // v index
        float v0 = skc[w0][dd] * sv[w0][vi];
        float v1 = skc[w1][dd] * sv[w1][vi];
        outb[cc * 8 + pl * 2] = packf16(v0, v1);
    }
}

// ---------------- octonion math ----------------------------------------------
__device__ __forceinline__ void qmul4(const float* q1, const float* q2, float* r)
{
    r[0] = q1[0]*q2[0] - q1[1]*q2[1] - q1[2]*q2[2] - q1[3]*q2[3];
    r[1] = q1[0]*q2[1] + q1[1]*q2[0] + q1[2]*q2[3] - q1[3]*q2[2];
    r[2] = q1[0]*q2[2] - q1[1]*q2[3] + q1[2]*q2[0] + q1[3]*q2[1];
    r[3] = q1[0]*q2[3] + q1[1]*q2[2] - q1[2]*q2[1] + q1[3]*q2[0];
}
__device__ __forceinline__ void omul8(const float* o1, const float* o2, float* r)
{
    const float* a = o1; const float* b = o1 + 4;
    const float* c = o2; const float* d = o2 + 4;
    float dc[4] = { d[0], -d[1], -d[2], -d[3] };
    float cc[4] = { c[0], -c[1], -c[2], -c[3] };
    float t1[4], t2[4];
    qmul4(a, c, t1); qmul4(dc, b, t2);
    r[0] = t1[0] - t2[0]; r[1] = t1[1] - t2[1];
    r[2] = t1[2] - t2[2]; r[3] = t1[3] - t2[3];
    qmul4(d, a, t1); qmul4(b, cc, t2);
    r[4] = t1[0] + t2[0]; r[5] = t1[1] + t2[1];
    r[6] = t1[2] + t2[2]; r[7] = t1[3] + t2[3];
}

// ===== fused attention: split KH/KV commit groups, deeper KV prefetch ========
#define TK 32
#define OFF_KV 0
#define KV_STG 8192
#define OFF_KH 32768
#define KH_STG 1280
#define OFF_P  37888
#define P_STG  1280
#define OFF_QF 40448
#define OFF_S  43008
#define FA_SMEM ((OFF_S + 192) * 4)

__global__ void __launch_bounds__(512, 1) fused_attn(
    const float* __restrict__ qn,
    const uint32_t* __restrict__ qf, const uint32_t* __restrict__ kf,
    const uint32_t* __restrict__ kvp16,
    uint32_t* __restrict__ yh, uint32_t* __restrict__ yl)
{
    extern __shared__ __align__(16) float fsm[];
    uint32_t* usm = (uint32_t*)fsm;
    uint32_t sbase = smem_u32(fsm);

    int qt = 31 - blockIdx.x;
    int h = blockIdx.y;
    int r0 = qt * 64;
    int njt = 2 * (qt + 1);

    int tid = threadIdx.x, lane = tid & 31, wid = tid >> 5;
    int gid = lane >> 2, tig = lane & 3;
    int rg = wid & 3, kw = wid >> 2;
    int rowa = rg * 16 + gid;

    const uint32_t* kvph = kvp16 + (long)h * 128 * 4096;
    const uint32_t* kfh = kf + (long)h * T_SEQ * 32;

    auto issue_KV = [&](int t) {
        const uint32_t* src = kvph + (long)t * 8192;
        uint32_t dstw = OFF_KV + (t & 3) * KV_STG;
#pragma unroll
        for (int i = 0; i < 4; i++) {
            int idx = tid + i * 512;
            CP16(sbase + (dstw + idx * 4) * 4, src + idx * 4);
        }
    };
    auto issue_KH = [&](int t) {
        if (tid < 256) {
            int rr = tid >> 3, ch = (tid & 7) * 4;
            const uint32_t* sb2 = kfh + (long)(t * TK + rr) * 32 + ch;
            CP16(sbase + (OFF_KH + (t & 3) * KH_STG + rr * 40 + ch) * 4, sb2);
        }
    };

    float s_acc0 = 0.f, s_acc1 = 0.f;
    uint32_t qreg[4][4];

    auto do_scores = [&](int j) {
        const uint32_t* KHb = usm + OFF_KH + (j & 3) * KH_STG;
#pragma unroll
        for (int nt = 0; nt < 2; nt++) {
            float sc2[2][4];
#pragma unroll
            for (int p = 0; p < 2; p++)
#pragma unroll
                for (int q = 0; q < 4; q++) sc2[p][q] = 0.f;
            int krow = (kw * 16 + nt * 8 + gid) * 40 + 2 * tig;
#pragma unroll
            for (int ks = 0; ks < 4; ks++) {
                uint2 kb = *(const uint2*)(KHb + krow + ks * 8);
                mma_f16(sc2[ks & 1], qreg[ks][0], qreg[ks][1],
                        qreg[ks][2], qreg[ks][3], kb.x, kb.y);
            }
            float s0 = sc2[0][0] + sc2[1][0];
            float s1 = sc2[0][1] + sc2[1][1];
            float s2 = sc2[0][2] + sc2[1][2];
            float s3 = sc2[0][3] + sc2[1][3];

            int colg = j * TK + kw * 16 + nt * 8 + tig * 2;
            float p00 = __expf(s0 * 0.125f);
            float p01 = __expf(s1 * 0.125f);
            float p10 = __expf(s2 * 0.125f);
            float p11 = __expf(s3 * 0.125f);
            if (j >= njt - 2) {
                if (colg     > r0 + rowa)     p00 = 0.f;
                if (colg + 1 > r0 + rowa)     p01 = 0.f;
                if (colg     > r0 + rowa + 8) p10 = 0.f;
                if (colg + 1 > r0 + rowa + 8) p11 = 0.f;
            }
            uint32_t w0 = packf16(p00, p01);
            uint32_t w1 = packf16(p10, p11);
            uint32_t* Pr = usm + OFF_P + (j & 1) * P_STG + rowa * 20 +
                           kw * 8 + tig * 2 + nt;
            Pr[0] = w0;
            Pr[8 * 20] = w1;
            float2 f0 = __half22float2(*(__half2*)&w0);
            float2 f1 = __half22float2(*(__half2*)&w1);
            s_acc0 += f0.x + f0.y;
            s_acc1 += f1.x + f1.y;
        }
    };

    // prologue: group0 = Q + KH0 + KV0; group1 = KH1; group2 = KV1
    {
        const uint32_t* qhh = qf + ((long)h * T_SEQ + r0) * 32;
        {
            int rr = tid >> 3, ch = (tid & 7) * 4;
            CP16(sbase + (OFF_QF + rr * 40 + ch) * 4, qhh + (long)rr * 32 + ch);
        }
        issue_KH(0);
        issue_KV(0);
        CP_COMMIT();
        issue_KH(1);
        CP_COMMIT();
        issue_KV(1);
        CP_COMMIT();
        CP_WAIT2();              // group0 done: Q, KH0, KV0
        __syncthreads();
        if (wid < 8) {
            int arow2 = rowa * 40 + 2 * tig;
#pragma unroll
            for (int ks = 0; ks < 4; ks++) {
                uint2 a = *(const uint2*)(usm + OFF_QF + arow2 + ks * 8);
                uint2 b = *(const uint2*)(usm + OFF_QF + arow2 + ks * 8 + 8 * 40);
                qreg[ks][0] = a.x; qreg[ks][1] = b.x;
                qreg[ks][2] = a.y; qreg[ks][3] = b.y;
            }
            do_scores(0);
        }
    }

    float zacc[4][4][4];
#pragma unroll
    for (int i = 0; i < 4; i++)
#pragma unroll
        for (int j = 0; j < 4; j++)
#pragma unroll
            for (int q = 0; q < 4; q++) zacc[i][j][q] = 0.f;

    for (int jt = 0; jt < njt; jt++) {
        if (jt + 2 < njt) {
            issue_KH(jt + 2);
            CP_COMMIT();
            issue_KV(jt + 2);
            CP_COMMIT();
            CP_WAIT3();          // retires KH(jt+1) and KV(jt); KV(jt+1) may fly
        } else {
            CP_WAIT0();
        }
        __syncthreads();

        if (wid < 8 && jt + 1 < njt) do_scores(jt + 1);

        // Z(jt) += P @ KV
        {
            const uint32_t* KVs = usm + OFF_KV + (jt & 3) * KV_STG;
            const uint32_t* Pb = usm + OFF_P + (jt & 1) * P_STG;
#pragma unroll
            for (int ks = 0; ks < 2; ks++) {
                uint2 pa[4][2];
#pragma unroll
                for (int mt = 0; mt < 4; mt++) {
                    const uint32_t* Pr = Pb + (mt * 16 + gid) * 20 + ks * 8 + 2 * tig;
                    pa[mt][0] = *(const uint2*)Pr;
                    pa[mt][1] = *(const uint2*)(Pr + 8 * 20);
                }
#pragma unroll
                for (int nt = 0; nt < 4; nt++) {
                    int c = wid * 32 + nt * 8 + gid;
                    uint2 bb = *(const uint2*)(KVs + ks * 4096 + c * 8 + 2 * tig);
#pragma unroll
                    for (int mt = 0; mt < 4; mt++)
                        mma_f16(zacc[mt][nt], pa[mt][0].x, pa[mt][1].x,
                                pa[mt][0].y, pa[mt][1].y, bb.x, bb.y);
                }
            }
        }
    }
    __syncthreads();

    s_acc0 += __shfl_xor_sync(~0u, s_acc0, 1);
    s_acc0 += __shfl_xor_sync(~0u, s_acc0, 2);
    s_acc1 += __shfl_xor_sync(~0u, s_acc1, 1);
    s_acc1 += __shfl_xor_sync(~0u, s_acc1, 2);
    if (wid < 8 && tig == 0) {
        fsm[OFF_S + kw * 64 + rowa] = s_acc0;
        fsm[OFF_S + kw * 64 + rowa + 8] = s_acc1;
    }
#pragma unroll
    for (int mt = 0; mt < 4; mt++) {
        int row = mt * 16 + gid;
#pragma unroll
        for (int nt = 0; nt < 4; nt++) {
            float* zp = fsm + row * 520 + wid * 32 + (wid >> 1) + nt * 8 + tig * 2;
            zp[0] = zacc[mt][nt][0];
            zp[1] = zacc[mt][nt][1];
            zp[8 * 520] = zacc[mt][nt][2];
            zp[8 * 520 + 1] = zacc[mt][nt][3];
        }
    }
    __syncthreads();
    if (tid < 64)
        fsm[OFF_S + 128 + tid] = 1.f / (fsm[OFF_S + tid] + fsm[OFF_S + 64 + tid]);
    __syncthreads();

    // ---- octonion epilogue -> y fp16 hi/lo (permuted pair layout) ----
    {
        int row = tid >> 3, m = tid & 7;
        float invS = fsm[OFF_S + 128 + row];
        const float* q = qn + ((long)h * T_SEQ + r0 + row) * HD + m * 8;
        const float* z = fsm + row * 520 + m * 65;

        float q8[8];
        float4 qa = *(const float4*)q, qb = *(const float4*)(q + 4);
        q8[0]=qa.x; q8[1]=qa.y; q8[2]=qa.z; q8[3]=qa.w;
        q8[4]=qb.x; q8[5]=qb.y; q8[6]=qb.z; q8[7]=qb.w;
        float acc[8] = {0,0,0,0,0,0,0,0};
#pragma unroll
        for (int p = 0; p < 8; p++) {
            float e[8] = {0,0,0,0,0,0,0,0};
            e[p] = 1.f;
            float uo[8], z8[8], wv[8];
            omul8(q8, e, uo);
#pragma unroll
            for (int i = 0; i < 8; i++) z8[i] = z[p * 8 + i];
            omul8(uo, z8, wv);
#pragma unroll
            for (int k = 0; k < 8; k++) acc[k] += wv[k];
        }
        long ybw = (long)(r0 + row) * 512 + h * 32 + (m >> 1) * 8 + (m & 1);
#pragma unroll
        for (int j = 0; j < 4; j++) {
            float f0 = acc[2 * j] * invS, f1 = acc[2 * j + 1] * invS;
            uint32_t hw = packf16(f0, f1);
            float2 hf = __half22float2(*(__half2*)&hw);
            uint32_t lw = packf16(f0 - hf.x, f1 - hf.y);
            yh[ybw + 2 * j] = hw;
            yl[ybw + 2 * j] = lw;
        }
    }
}

// ---------------- launch -----------------------------------------------------
extern "C" void kernel_launch(void* const* d_in, const int* in_sizes, int n_in,
                              void* d_out, int out_size)
{
    const float* x    = (const float*)d_in[0];
    const float* cosp = (const float*)d_in[1];
    const float* sinp = (const float*)d_in[2];
    const float* Wq   = (const float*)d_in[3];
    const float* Wk   = (const float*)d_in[4];
    const float* Wv   = (const float*)d_in[5];
    const float* Wo   = (const float*)d_in[6];
    float* out = (float*)d_out;

    float *qraw, *kraw, *vraw, *qn;
    uint32_t *kvp16, *qf, *kf, *xh, *xl, *wh, *yh, *yl;
    cudaGetSymbolAddress((void**)&qraw,  g_qraw);
    cudaGetSymbolAddress((void**)&kraw,  g_kraw);
    cudaGetSymbolAddress((void**)&vraw,  g_vraw);
    cudaGetSymbolAddress((void**)&qn,    g_qn);
    cudaGetSymbolAddress((void**)&kvp16, g_kvp16);
    cudaGetSymbolAddress((void**)&qf,    g_qf);
    cudaGetSymbolAddress((void**)&kf,    g_kf);
    cudaGetSymbolAddress((void**)&xh,    g_xh);
    cudaGetSymbolAddress((void**)&xl,    g_xl);
    cudaGetSymbolAddress((void**)&wh,    g_wh);
    cudaGetSymbolAddress((void**)&yh,    g_yh);
    cudaGetSymbolAddress((void**)&yl,    g_yl);

    cudaFuncSetAttribute(qkv_gemm, cudaFuncAttributeMaxDynamicSharedMemorySize, GEMM16_SMEM);
    cudaFuncSetAttribute(wo_gemm,  cudaFuncAttributeMaxDynamicSharedMemorySize, GEMM16_SMEM);
    cudaFuncSetAttribute(fused_attn, cudaFuncAttributeMaxDynamicSharedMemorySize, FA_SMEM);

    conv_w<<<dim3(256, 4), 256>>>(Wq, Wk, Wv, Wo, wh);
    conv_x<<<512, 256>>>(x, xh, xl);

    qkv_gemm<<<dim3(CEMB / 64, T_SEQ / 128, 3), 256, GEMM16_SMEM>>>(
        xh, xl, wh, qraw, kraw, vraw);

    prep_kernel<<<dim3(NH, T_SEQ / 8), 512>>>(qraw, kraw, vraw, cosp, sinp,
                                              qn, kvp16, qf, kf);

    fused_attn<<<dim3(32, NH), 512, FA_SMEM>>>(qn, qf, kf, kvp16, yh, yl);

    wo_gemm<<<dim3(CEMB / 64, T_SEQ / 128), 256, GEMM16_SMEM>>>(yh, yl, wh, out);
}